// round 1
// baseline (speedup 1.0000x reference)
#include <cuda_runtime.h>

// ---------------------------------------------------------------------------
// AdaUp: bilinear-up + concat + 1x1 conv (ReLU) + 3x3 offset conv + 1x1 proc
//        conv + 4-point deformable bilinear sampling (border clamp), averaged.
//
// Key restructuring:
//   conv1x1(concat[up(high), low]) = up(W1a@high) + W1b@low   (1x1 commutes
//   with spatial upsampling), and W1a@high shares its A matrix with Wf@high,
//   so K1 is one GEMM with N=512 producing both t and proc at 64x64.
// ---------------------------------------------------------------------------

#define NB    8
#define NC    256
#define HLO   64
#define WLO   64
#define HWLO  4096      // 64*64
#define HHI   128
#define WHI   128
#define HWHI  16384     // 128*128

// Scratch (NHWC layouts)
__device__ float g_t[(size_t)NB * HWLO * NC];         //  33.5 MB : W1a@high (no bias)
__device__ float g_proc[(size_t)NB * HWLO * NC];      //  33.5 MB : Wf@high + bf
__device__ float g_offfeat[(size_t)NB * HWHI * NC];   // 134.2 MB : relu(conv1)
__device__ float g_offsets[(size_t)NB * HWHI * 8];    //   4.2 MB : [pixel][8]

__device__ __forceinline__ float4 f4zero() { return make_float4(0.f, 0.f, 0.f, 0.f); }

// ===========================================================================
// K1: out[m][n] for m = b*4096+s (64x64 pixels), n in [0,512)
//     A[m][k] = high[b,k,s]   (NCHW, K-strided)
//     n<256 -> g_t (W1 rows, first 256 input cols),  n>=256 -> g_proc (Wf)+bf
// BM=128, BN=128, BK=8, 256 threads, 8x8 microtile
// ===========================================================================
__global__ __launch_bounds__(256, 2)
void k1_gemm(const float* __restrict__ A, const float* __restrict__ W1,
             const float* __restrict__ Wf, const float* __restrict__ bf)
{
    const int m0 = blockIdx.x * 128;      // pixel tile (never straddles batch)
    const int n0 = blockIdx.y * 128;      // out-channel tile
    const int bb = m0 >> 12;
    const int s0 = m0 & 4095;

    __shared__ float As[8][132];
    __shared__ float Bs[8][132];

    const int tid = threadIdx.x;
    const int tx = tid & 15, ty = tid >> 4;
    const int krowA = tid >> 5, mA = (tid & 31) << 2;
    const int nrowB = tid >> 1, kqB = (tid & 1) << 2;

    float acc[8][8];
#pragma unroll
    for (int i = 0; i < 8; ++i)
#pragma unroll
        for (int j = 0; j < 8; ++j) acc[i][j] = 0.f;

    for (int k0 = 0; k0 < 256; k0 += 8) {
        float4 a4 = *(const float4*)&A[((size_t)bb * 256 + k0 + krowA) * HWLO + s0 + mA];
        const int n = n0 + nrowB;
        float4 w4;
        if (n < 256) w4 = *(const float4*)&W1[(size_t)n * 512 + k0 + kqB];
        else         w4 = *(const float4*)&Wf[(size_t)(n - 256) * 256 + k0 + kqB];
        __syncthreads();
        *(float4*)&As[krowA][mA] = a4;
        Bs[kqB + 0][nrowB] = w4.x;
        Bs[kqB + 1][nrowB] = w4.y;
        Bs[kqB + 2][nrowB] = w4.z;
        Bs[kqB + 3][nrowB] = w4.w;
        __syncthreads();
#pragma unroll
        for (int kk = 0; kk < 8; ++kk) {
            float a[8], w[8];
            *(float4*)&a[0] = *(const float4*)&As[kk][ty * 8];
            *(float4*)&a[4] = *(const float4*)&As[kk][ty * 8 + 4];
            *(float4*)&w[0] = *(const float4*)&Bs[kk][tx * 8];
            *(float4*)&w[4] = *(const float4*)&Bs[kk][tx * 8 + 4];
#pragma unroll
            for (int i = 0; i < 8; ++i)
#pragma unroll
                for (int j = 0; j < 8; ++j)
                    acc[i][j] = fmaf(a[i], w[j], acc[i][j]);
        }
    }

    if (n0 < 256) {
#pragma unroll
        for (int i = 0; i < 8; ++i) {
            size_t row = (size_t)(m0 + ty * 8 + i) * 256 + n0 + tx * 8;
            *(float4*)&g_t[row]     = make_float4(acc[i][0], acc[i][1], acc[i][2], acc[i][3]);
            *(float4*)&g_t[row + 4] = make_float4(acc[i][4], acc[i][5], acc[i][6], acc[i][7]);
        }
    } else {
        const int nc = n0 - 256 + tx * 8;
        float4 bf0 = *(const float4*)&bf[nc];
        float4 bf1 = *(const float4*)&bf[nc + 4];
#pragma unroll
        for (int i = 0; i < 8; ++i) {
            size_t row = (size_t)(m0 + ty * 8 + i) * 256 + nc;
            *(float4*)&g_proc[row] = make_float4(acc[i][0] + bf0.x, acc[i][1] + bf0.y,
                                                 acc[i][2] + bf0.z, acc[i][3] + bf0.w);
            *(float4*)&g_proc[row + 4] = make_float4(acc[i][4] + bf1.x, acc[i][5] + bf1.y,
                                                     acc[i][6] + bf1.z, acc[i][7] + bf1.w);
        }
    }
}

// ===========================================================================
// K2: off_feat[m][n] = relu( W1b@low + upsample2x(t) + b1 ),  m over 128x128
//     A[m][k] = low[b,k,s], W1b = W1[:, 256:512]
// Upsample (align_corners=False, scale 2): out[2t]=.25 in[t-1]+.75 in[t],
//                                          out[2t+1]=.75 in[t]+.25 in[t+1], clamped.
// ===========================================================================
__global__ __launch_bounds__(256, 2)
void k2_gemm(const float* __restrict__ A, const float* __restrict__ W1,
             const float* __restrict__ b1)
{
    const int m0 = blockIdx.x * 128;
    const int n0 = blockIdx.y * 128;
    const int bb = m0 >> 14;
    const int s0 = m0 & 16383;

    __shared__ float As[8][132];
    __shared__ float Bs[8][132];

    const int tid = threadIdx.x;
    const int tx = tid & 15, ty = tid >> 4;
    const int krowA = tid >> 5, mA = (tid & 31) << 2;
    const int nrowB = tid >> 1, kqB = (tid & 1) << 2;

    float acc[8][8];
#pragma unroll
    for (int i = 0; i < 8; ++i)
#pragma unroll
        for (int j = 0; j < 8; ++j) acc[i][j] = 0.f;

    for (int k0 = 0; k0 < 256; k0 += 8) {
        float4 a4 = *(const float4*)&A[((size_t)bb * 256 + k0 + krowA) * HWHI + s0 + mA];
        float4 w4 = *(const float4*)&W1[(size_t)(n0 + nrowB) * 512 + 256 + k0 + kqB];
        __syncthreads();
        *(float4*)&As[krowA][mA] = a4;
        Bs[kqB + 0][nrowB] = w4.x;
        Bs[kqB + 1][nrowB] = w4.y;
        Bs[kqB + 2][nrowB] = w4.z;
        Bs[kqB + 3][nrowB] = w4.w;
        __syncthreads();
#pragma unroll
        for (int kk = 0; kk < 8; ++kk) {
            float a[8], w[8];
            *(float4*)&a[0] = *(const float4*)&As[kk][ty * 8];
            *(float4*)&a[4] = *(const float4*)&As[kk][ty * 8 + 4];
            *(float4*)&w[0] = *(const float4*)&Bs[kk][tx * 8];
            *(float4*)&w[4] = *(const float4*)&Bs[kk][tx * 8 + 4];
#pragma unroll
            for (int i = 0; i < 8; ++i)
#pragma unroll
                for (int j = 0; j < 8; ++j)
                    acc[i][j] = fmaf(a[i], w[j], acc[i][j]);
        }
    }

    const int nc = n0 + tx * 8;
    float4 b10 = *(const float4*)&b1[nc];
    float4 b11 = *(const float4*)&b1[nc + 4];
    const float* tb = g_t + (size_t)bb * HWLO * 256;

#pragma unroll
    for (int i = 0; i < 8; ++i) {
        const int s = s0 + ty * 8 + i;
        const int yy = s >> 7, xx = s & 127;
        int th = yy >> 1, twv = xx >> 1;
        int jy0, jy1, jx0, jx1;
        float wy0, wy1, wx0, wx1;
        if (yy & 1) { jy0 = th; jy1 = (th + 1 > 63) ? 63 : th + 1; wy0 = 0.75f; wy1 = 0.25f; }
        else        { jy0 = (th - 1 < 0) ? 0 : th - 1; jy1 = th;   wy0 = 0.25f; wy1 = 0.75f; }
        if (xx & 1) { jx0 = twv; jx1 = (twv + 1 > 63) ? 63 : twv + 1; wx0 = 0.75f; wx1 = 0.25f; }
        else        { jx0 = (twv - 1 < 0) ? 0 : twv - 1; jx1 = twv;   wx0 = 0.25f; wx1 = 0.75f; }

        const float wa = wy0 * wx0, wb = wy0 * wx1, wc = wy1 * wx0, wd = wy1 * wx1;
        const float* p00 = tb + (size_t)(jy0 * 64 + jx0) * 256 + nc;
        const float* p01 = tb + (size_t)(jy0 * 64 + jx1) * 256 + nc;
        const float* p10 = tb + (size_t)(jy1 * 64 + jx0) * 256 + nc;
        const float* p11 = tb + (size_t)(jy1 * 64 + jx1) * 256 + nc;

        float4 u00 = *(const float4*)p00,       u01 = *(const float4*)p01;
        float4 u10 = *(const float4*)p10,       u11 = *(const float4*)p11;
        float4 v00 = *(const float4*)(p00 + 4), v01 = *(const float4*)(p01 + 4);
        float4 v10 = *(const float4*)(p10 + 4), v11 = *(const float4*)(p11 + 4);

        float4 r0, r1;
        r0.x = fmaxf(acc[i][0] + b10.x + wa*u00.x + wb*u01.x + wc*u10.x + wd*u11.x, 0.f);
        r0.y = fmaxf(acc[i][1] + b10.y + wa*u00.y + wb*u01.y + wc*u10.y + wd*u11.y, 0.f);
        r0.z = fmaxf(acc[i][2] + b10.z + wa*u00.z + wb*u01.z + wc*u10.z + wd*u11.z, 0.f);
        r0.w = fmaxf(acc[i][3] + b10.w + wa*u00.w + wb*u01.w + wc*u10.w + wd*u11.w, 0.f);
        r1.x = fmaxf(acc[i][4] + b11.x + wa*v00.x + wb*v01.x + wc*v10.x + wd*v11.x, 0.f);
        r1.y = fmaxf(acc[i][5] + b11.y + wa*v00.y + wb*v01.y + wc*v10.y + wd*v11.y, 0.f);
        r1.z = fmaxf(acc[i][6] + b11.z + wa*v00.z + wb*v01.z + wc*v10.z + wd*v11.z, 0.f);
        r1.w = fmaxf(acc[i][7] + b11.w + wa*v00.w + wb*v01.w + wc*v10.w + wd*v11.w, 0.f);

        size_t row = (size_t)(m0 + ty * 8 + i) * 256 + nc;
        *(float4*)&g_offfeat[row]     = r0;
        *(float4*)&g_offfeat[row + 4] = r1;
    }
}

// ===========================================================================
// K3: offsets[pix][o] = sum_{tap,c} W2[o][c][tap] * off_feat[pix+tap][c] + b2[o]
// Block = 32 pixels (one row segment), warp = 4 pixels, lane = 4 channels.
// Weights staged in smem as [tap][o][c_local] per 128-channel half.
// Zero padding on spatial borders.
// ===========================================================================
__global__ __launch_bounds__(256)
void k3_conv3(const float* __restrict__ W2, const float* __restrict__ b2)
{
    __shared__ float wsh[9 * 8 * 128];   // 36 KB

    const int tid  = threadIdx.x;
    const int lane = tid & 31, wrp = tid >> 5;
    const int pix0 = blockIdx.x * 32;
    const int bb = pix0 >> 14;
    const int s0 = pix0 & 16383;
    const int y  = s0 >> 7;
    const int xw = (s0 & 127) + wrp * 4;

    float acc[4][8];
#pragma unroll
    for (int r = 0; r < 4; ++r)
#pragma unroll
        for (int o = 0; o < 8; ++o) acc[r][o] = 0.f;

    const float* fb = g_offfeat + (size_t)bb * HWHI * 256;

    for (int ch = 0; ch < 2; ++ch) {
        __syncthreads();
        for (int i = tid; i < 9216; i += 256) {
            const int tap = i >> 10;
            const int o   = (i >> 7) & 7;
            const int cl  = i & 127;
            wsh[i] = W2[(size_t)o * 2304 + (ch * 128 + cl) * 9 + tap];
        }
        __syncthreads();
        const int co = ch * 128 + 4 * lane;
#pragma unroll
        for (int tap = 0; tap < 9; ++tap) {
            const int ky = tap / 3 - 1, kx = tap % 3 - 1;
            const int yy = y + ky;
            float4 v[4];
#pragma unroll
            for (int r = 0; r < 4; ++r) {
                const int xx = xw + r + kx;
                if (yy >= 0 && yy < 128 && xx >= 0 && xx < 128)
                    v[r] = *(const float4*)&fb[(size_t)(yy * 128 + xx) * 256 + co];
                else
                    v[r] = f4zero();
            }
#pragma unroll
            for (int o = 0; o < 8; ++o) {
                const float4 wv = *(const float4*)&wsh[(tap * 8 + o) * 128 + 4 * lane];
#pragma unroll
                for (int r = 0; r < 4; ++r)
                    acc[r][o] += v[r].x * wv.x + v[r].y * wv.y + v[r].z * wv.z + v[r].w * wv.w;
            }
        }
    }

    // reduce over lanes (channel dim)
#pragma unroll
    for (int r = 0; r < 4; ++r)
#pragma unroll
        for (int o = 0; o < 8; ++o) {
            float s = acc[r][o];
#pragma unroll
            for (int d = 16; d > 0; d >>= 1) s += __shfl_xor_sync(0xffffffffu, s, d);
            acc[r][o] = s;
        }

    if (lane < 4) {
        const size_t pi = (size_t)(pix0 + wrp * 4 + lane) * 8;
        *(float4*)&g_offsets[pi] =
            make_float4(acc[lane][0] + b2[0], acc[lane][1] + b2[1],
                        acc[lane][2] + b2[2], acc[lane][3] + b2[3]);
        *(float4*)&g_offsets[pi + 4] =
            make_float4(acc[lane][4] + b2[4], acc[lane][5] + b2[5],
                        acc[lane][6] + b2[6], acc[lane][7] + b2[7]);
    }
}

// ===========================================================================
// K4: out[b,c,y,x] = (1/4) sum_p bilinear_border(proc, base(y,x)+off_p(y,x))
// CTA = (b, y, 32 x-pixels, 128-channel half). Phase A computes the 16
// (index,weight) taps per pixel; Phase B gathers NHWC proc with LDG.128;
// smem transpose gives coalesced NCHW writes.
// ===========================================================================
__global__ __launch_bounds__(256)
void k4_sample(float* __restrict__ out)
{
    __shared__ int   sh_idx[32][16];
    __shared__ float sh_w[32][16];
    __shared__ float sh_t[32][132];

    const int tid = threadIdx.x;
    const int bx = blockIdx.x;     // 0..7 : xtile(0..3)*2 + chalf
    const int xt = bx >> 1;
    const int ch = bx & 1;
    const int y  = blockIdx.y;
    const int bb = blockIdx.z;
    const int x0 = xt * 32;

    if (tid < 128) {
        const int px = tid >> 2, p = tid & 3;
        const int x = x0 + px;
        const size_t pi = ((size_t)bb * HWHI + y * 128 + x) * 8;
        const float ox = g_offsets[pi + 2 * p]     * (1.0f / 64.0f);
        const float oy = g_offsets[pi + 2 * p + 1] * (1.0f / 64.0f);
        const float gx = fmaf((float)x, 2.0f / 127.0f, -1.0f) + ox;
        const float gy = fmaf((float)y, 2.0f / 127.0f, -1.0f) + oy;
        const float gxp = fminf(fmaxf(fmaf(gx, 32.0f, 31.5f), 0.0f), 63.0f);
        const float gyp = fminf(fmaxf(fmaf(gy, 32.0f, 31.5f), 0.0f), 63.0f);
        const float fx0 = floorf(gxp), fy0 = floorf(gyp);
        const int ix0 = (int)fx0, iy0 = (int)fy0;
        const float fx = gxp - fx0, fy = gyp - fy0;
        const int ix1 = (ix0 + 1 > 63) ? 63 : ix0 + 1;
        const int iy1 = (iy0 + 1 > 63) ? 63 : iy0 + 1;
        const int q = p * 4;
        sh_idx[px][q + 0] = (iy0 * 64 + ix0) * 256;
        sh_idx[px][q + 1] = (iy0 * 64 + ix1) * 256;
        sh_idx[px][q + 2] = (iy1 * 64 + ix0) * 256;
        sh_idx[px][q + 3] = (iy1 * 64 + ix1) * 256;
        sh_w[px][q + 0] = (1.f - fx) * (1.f - fy) * 0.25f;
        sh_w[px][q + 1] = fx * (1.f - fy) * 0.25f;
        sh_w[px][q + 2] = (1.f - fx) * fy * 0.25f;
        sh_w[px][q + 3] = fx * fy * 0.25f;
    }
    __syncthreads();

    const int lane = tid & 31, wrp = tid >> 5;
    const float* pb = g_proc + (size_t)bb * HWLO * 256 + ch * 128 + 4 * lane;

#pragma unroll
    for (int r = 0; r < 4; ++r) {
        const int px = wrp * 4 + r;
        float4 acc = f4zero();
#pragma unroll
        for (int t = 0; t < 16; ++t) {
            const float wt = sh_w[px][t];
            const float4 v = *(const float4*)(pb + sh_idx[px][t]);
            acc.x = fmaf(wt, v.x, acc.x);
            acc.y = fmaf(wt, v.y, acc.y);
            acc.z = fmaf(wt, v.z, acc.z);
            acc.w = fmaf(wt, v.w, acc.w);
        }
        *(float4*)&sh_t[px][4 * lane] = acc;
    }
    __syncthreads();

    const int xl = tid & 31;
    const int c0 = tid >> 5;    // 0..7
#pragma unroll
    for (int i = 0; i < 16; ++i) {
        const int c = c0 * 16 + i;   // 0..127
        out[((size_t)bb * 256 + ch * 128 + c) * HWHI + y * 128 + x0 + xl] = sh_t[xl][c];
    }
}

// ===========================================================================
extern "C" void kernel_launch(void* const* d_in, const int* in_sizes, int n_in,
                              void* d_out, int out_size)
{
    const float* high = (const float*)d_in[0];
    const float* low  = (const float*)d_in[1];
    const float* W1   = (const float*)d_in[2];
    const float* b1   = (const float*)d_in[3];
    const float* W2   = (const float*)d_in[4];
    const float* b2   = (const float*)d_in[5];
    const float* Wf   = (const float*)d_in[6];
    const float* bf   = (const float*)d_in[7];
    float* out = (float*)d_out;

    // K1: t + proc (shared A GEMM, M=32768, N=512, K=256)
    k1_gemm<<<dim3(256, 4), 256>>>(high, W1, Wf, bf);
    // K2: off_feat (M=131072, N=256, K=256) + upsampled-t + bias + ReLU
    k2_gemm<<<dim3(1024, 2), 256>>>(low, W1, b1);
    // K3: 3x3 offset conv (N=8)
    k3_conv3<<<4096, 256>>>(W2, b2);
    // K4: 4-point deformable bilinear sampling, averaged
    k4_sample<<<dim3(8, 128, 8), 256>>>(out);
}

// round 3
// speedup vs baseline: 1.6146x; 1.6146x over previous
#include <cuda_runtime.h>

// ---------------------------------------------------------------------------
// AdaUp via warp-level tf32 mma.sync (HMMA path; tcgen05 unavailable because
// the harness lowers through compute_103 without the 'a' feature target).
//   K1m: t = W1a@high ; proc = Wf@high + bf      (tf32 mma, NHWC out)
//   K2m: off_feat = relu(W1b@low + up2x(t) + b1) (tf32 mma + staged epilogue)
//   K5m: q[p][tap*8+o] = W2[:,:,tap]@off_feat(p) (tf32 mma, N=72 pad 80)
//   K6 : offsets(p) = b2 + sum_tap q[p+delta(tap)]
//   K4 : 4-point deformable bilinear sampling of proc, averaged
// ---------------------------------------------------------------------------

#define NB    8
#define HWLO  4096      // 64*64
#define HWHI  16384     // 128*128

__device__ float g_t[(size_t)NB * HWLO * 256];
__device__ float g_proc[(size_t)NB * HWLO * 256];
__device__ float g_offfeat[(size_t)NB * HWHI * 256];
__device__ float g_q[(size_t)NB * HWHI * 72];
__device__ float g_offsets[(size_t)NB * HWHI * 8];

__device__ __forceinline__ unsigned f2tf32(float f) {
    unsigned u; asm("cvt.rna.tf32.f32 %0, %1;" : "=r"(u) : "f"(f)); return u;
}

// D(16x8) += A(16x8,row) @ B(8x8,col) ; tf32 inputs as uint bits
#define MMA_TF32(d, a, b) \
    asm volatile("mma.sync.aligned.m16n8k8.row.col.f32.tf32.tf32.f32 " \
                 "{%0,%1,%2,%3}, {%4,%5,%6,%7}, {%8,%9}, {%0,%1,%2,%3};" \
                 : "+f"((d)[0]), "+f"((d)[1]), "+f"((d)[2]), "+f"((d)[3]) \
                 : "r"((a)[0]), "r"((a)[1]), "r"((a)[2]), "r"((a)[3]), \
                   "r"((b)[0]), "r"((b)[1]))

// ===========================================================================
// K1m: D[128m x 128n] tiles of  [t | proc] = [W1a | Wf] @ high
//   A[k][m] = high[b, k, s0+m]  (m contiguous in gmem)
//   grid.x = 256 m-tiles, grid.y = 4 : (ny = which B) * 2 + nhalf
// ===========================================================================
__global__ __launch_bounds__(256)
void k1m(const float* __restrict__ high, const float* __restrict__ W1,
         const float* __restrict__ Wf, const float* __restrict__ bf)
{
    __shared__ unsigned As[16][136];
    __shared__ unsigned Bs[16][136];

    const int tid = threadIdx.x, lane = tid & 31, warp = tid >> 5;
    const int wm = warp & 1, wn = warp >> 1;
    const int m0 = blockIdx.x * 128;
    const int ny = blockIdx.y >> 1, nhalf = blockIdx.y & 1;
    const int bb = m0 >> 12, s0 = m0 & 4095;

    const float* Ab = high + (size_t)bb * 256 * HWLO + s0;
    const float* Bb = ny ? Wf : W1;
    const int brs = ny ? 256 : 512;

    float d[4][4][4];
#pragma unroll
    for (int i = 0; i < 4; ++i)
#pragma unroll
        for (int j = 0; j < 4; ++j)
#pragma unroll
            for (int e = 0; e < 4; ++e) d[i][j][e] = 0.f;

    const int krA = tid >> 4, mcA = (tid & 15) * 4;
    const int nB = nhalf * 128 + (tid >> 1), kqB = (tid & 1) * 8;

    for (int k0 = 0; k0 < 256; k0 += 16) {
        const float* ap = Ab + (size_t)(k0 + krA) * HWLO + mcA;
        float4 va0 = *(const float4*)ap;
        float4 va1 = *(const float4*)(ap + 64);
        const float* bp = Bb + (size_t)nB * brs + k0 + kqB;
        float4 wb0 = *(const float4*)bp;
        float4 wb1 = *(const float4*)(bp + 4);
        __syncthreads();
        *(uint4*)&As[krA][mcA] = make_uint4(f2tf32(va0.x), f2tf32(va0.y), f2tf32(va0.z), f2tf32(va0.w));
        *(uint4*)&As[krA][mcA + 64] = make_uint4(f2tf32(va1.x), f2tf32(va1.y), f2tf32(va1.z), f2tf32(va1.w));
        {
            const int nl = tid >> 1;
            Bs[kqB + 0][nl] = f2tf32(wb0.x); Bs[kqB + 1][nl] = f2tf32(wb0.y);
            Bs[kqB + 2][nl] = f2tf32(wb0.z); Bs[kqB + 3][nl] = f2tf32(wb0.w);
            Bs[kqB + 4][nl] = f2tf32(wb1.x); Bs[kqB + 5][nl] = f2tf32(wb1.y);
            Bs[kqB + 6][nl] = f2tf32(wb1.z); Bs[kqB + 7][nl] = f2tf32(wb1.w);
        }
        __syncthreads();
#pragma unroll
        for (int ks = 0; ks < 16; ks += 8) {
            const int kr = ks + (lane & 3);
            const int mb = wm * 64 + (lane >> 2);
            const int nb = wn * 32 + (lane >> 2);
            unsigned a[4][4], b[4][2];
#pragma unroll
            for (int mt = 0; mt < 4; ++mt) {
                a[mt][0] = As[kr][mb + mt * 16];
                a[mt][1] = As[kr][mb + mt * 16 + 8];
                a[mt][2] = As[kr + 4][mb + mt * 16];
                a[mt][3] = As[kr + 4][mb + mt * 16 + 8];
            }
#pragma unroll
            for (int nt = 0; nt < 4; ++nt) {
                b[nt][0] = Bs[kr][nb + nt * 8];
                b[nt][1] = Bs[kr + 4][nb + nt * 8];
            }
#pragma unroll
            for (int mt = 0; mt < 4; ++mt)
#pragma unroll
                for (int nt = 0; nt < 4; ++nt)
                    MMA_TF32(d[mt][nt], a[mt], b[nt]);
        }
    }

    float* ob = ny ? g_proc : g_t;
#pragma unroll
    for (int mt = 0; mt < 4; ++mt) {
        const int row = m0 + wm * 64 + mt * 16 + (lane >> 2);
#pragma unroll
        for (int nt = 0; nt < 4; ++nt) {
            const int col = nhalf * 128 + wn * 32 + nt * 8 + (lane & 3) * 2;
            float b0 = 0.f, b1 = 0.f;
            if (ny) { b0 = bf[col]; b1 = bf[col + 1]; }
            *(float2*)&ob[(size_t)row * 256 + col] =
                make_float2(d[mt][nt][0] + b0, d[mt][nt][1] + b1);
            *(float2*)&ob[(size_t)(row + 8) * 256 + col] =
                make_float2(d[mt][nt][2] + b0, d[mt][nt][3] + b1);
        }
    }
}

// ===========================================================================
// K2m: off_feat = relu(W1b@low + up2x(t) + b1)
//   grid.x = 1024 m-tiles (each = one image row y, x 0..127), grid.y = 2 (n)
//   Accums staged to smem, then R1-style per-pixel epilogue.
// ===========================================================================
__global__ __launch_bounds__(256)
void k2m(const float* __restrict__ low, const float* __restrict__ W1,
         const float* __restrict__ b1)
{
    extern __shared__ char dsm[];
    unsigned (*As)[136] = (unsigned(*)[136])dsm;
    unsigned (*Bs)[136] = (unsigned(*)[136])(dsm + 8704);
    float    (*stage)[132] = (float(*)[132])(dsm + 17408);

    const int tid = threadIdx.x, lane = tid & 31, warp = tid >> 5;
    const int wm = warp & 1, wn = warp >> 1;
    const int m0 = blockIdx.x * 128;
    const int n0 = blockIdx.y * 128;
    const int bb = m0 >> 14, s0 = m0 & 16383;

    const float* Ab = low + (size_t)bb * 256 * HWHI + s0;

    float d[4][4][4];
#pragma unroll
    for (int i = 0; i < 4; ++i)
#pragma unroll
        for (int j = 0; j < 4; ++j)
#pragma unroll
            for (int e = 0; e < 4; ++e) d[i][j][e] = 0.f;

    const int krA = tid >> 4, mcA = (tid & 15) * 4;
    const int nB = n0 + (tid >> 1), kqB = (tid & 1) * 8;

    for (int k0 = 0; k0 < 256; k0 += 16) {
        const float* ap = Ab + (size_t)(k0 + krA) * HWHI + mcA;
        float4 va0 = *(const float4*)ap;
        float4 va1 = *(const float4*)(ap + 64);
        const float* bp = W1 + (size_t)nB * 512 + 256 + k0 + kqB;
        float4 wb0 = *(const float4*)bp;
        float4 wb1 = *(const float4*)(bp + 4);
        __syncthreads();
        *(uint4*)&As[krA][mcA] = make_uint4(f2tf32(va0.x), f2tf32(va0.y), f2tf32(va0.z), f2tf32(va0.w));
        *(uint4*)&As[krA][mcA + 64] = make_uint4(f2tf32(va1.x), f2tf32(va1.y), f2tf32(va1.z), f2tf32(va1.w));
        {
            const int nl = tid >> 1;
            Bs[kqB + 0][nl] = f2tf32(wb0.x); Bs[kqB + 1][nl] = f2tf32(wb0.y);
            Bs[kqB + 2][nl] = f2tf32(wb0.z); Bs[kqB + 3][nl] = f2tf32(wb0.w);
            Bs[kqB + 4][nl] = f2tf32(wb1.x); Bs[kqB + 5][nl] = f2tf32(wb1.y);
            Bs[kqB + 6][nl] = f2tf32(wb1.z); Bs[kqB + 7][nl] = f2tf32(wb1.w);
        }
        __syncthreads();
#pragma unroll
        for (int ks = 0; ks < 16; ks += 8) {
            const int kr = ks + (lane & 3);
            const int mb = wm * 64 + (lane >> 2);
            const int nb = wn * 32 + (lane >> 2);
            unsigned a[4][4], b[4][2];
#pragma unroll
            for (int mt = 0; mt < 4; ++mt) {
                a[mt][0] = As[kr][mb + mt * 16];
                a[mt][1] = As[kr][mb + mt * 16 + 8];
                a[mt][2] = As[kr + 4][mb + mt * 16];
                a[mt][3] = As[kr + 4][mb + mt * 16 + 8];
            }
#pragma unroll
            for (int nt = 0; nt < 4; ++nt) {
                b[nt][0] = Bs[kr][nb + nt * 8];
                b[nt][1] = Bs[kr + 4][nb + nt * 8];
            }
#pragma unroll
            for (int mt = 0; mt < 4; ++mt)
#pragma unroll
                for (int nt = 0; nt < 4; ++nt)
                    MMA_TF32(d[mt][nt], a[mt], b[nt]);
        }
    }

    // stage accumulators: stage[pixel_local][col_local]
    __syncthreads();
#pragma unroll
    for (int mt = 0; mt < 4; ++mt) {
        const int sr = wm * 64 + mt * 16 + (lane >> 2);
#pragma unroll
        for (int nt = 0; nt < 4; ++nt) {
            const int sc = wn * 32 + nt * 8 + (lane & 3) * 2;
            *(float2*)&stage[sr][sc]     = make_float2(d[mt][nt][0], d[mt][nt][1]);
            *(float2*)&stage[sr + 8][sc] = make_float2(d[mt][nt][2], d[mt][nt][3]);
        }
    }
    __syncthreads();

    // per-pixel epilogue: thread owns (pixel p, 64-col half)
    const int p = tid >> 1, chh = tid & 1;
    const int m = m0 + p;
    const int s = m & 16383, yy = s >> 7, xx = s & 127;
    const int th = yy >> 1, tw = xx >> 1;
    int jy0, jy1, jx0, jx1;
    float wy0, wy1, wx0, wx1;
    if (yy & 1) { jy0 = th; jy1 = (th + 1 > 63) ? 63 : th + 1; wy0 = 0.75f; wy1 = 0.25f; }
    else        { jy0 = (th - 1 < 0) ? 0 : th - 1; jy1 = th;   wy0 = 0.25f; wy1 = 0.75f; }
    if (xx & 1) { jx0 = tw; jx1 = (tw + 1 > 63) ? 63 : tw + 1; wx0 = 0.75f; wx1 = 0.25f; }
    else        { jx0 = (tw - 1 < 0) ? 0 : tw - 1; jx1 = tw;   wx0 = 0.25f; wx1 = 0.75f; }
    const float wa = wy0 * wx0, wb_ = wy0 * wx1, wc = wy1 * wx0, wd = wy1 * wx1;
    const float* tb = g_t + (size_t)bb * HWLO * 256;
    const float* p00 = tb + (size_t)(jy0 * 64 + jx0) * 256 + n0;
    const float* p01 = tb + (size_t)(jy0 * 64 + jx1) * 256 + n0;
    const float* p10 = tb + (size_t)(jy1 * 64 + jx0) * 256 + n0;
    const float* p11 = tb + (size_t)(jy1 * 64 + jx1) * 256 + n0;
    float* ob = g_offfeat + (size_t)m * 256 + n0;

#pragma unroll
    for (int g = 0; g < 16; ++g) {
        const int c = chh * 64 + g * 4;
        float4 av  = *(const float4*)&stage[p][c];
        float4 bv  = *(const float4*)&b1[n0 + c];
        float4 u00 = *(const float4*)&p00[c];
        float4 u01 = *(const float4*)&p01[c];
        float4 u10 = *(const float4*)&p10[c];
        float4 u11 = *(const float4*)&p11[c];
        float4 o;
        o.x = fmaxf(av.x + bv.x + wa*u00.x + wb_*u01.x + wc*u10.x + wd*u11.x, 0.f);
        o.y = fmaxf(av.y + bv.y + wa*u00.y + wb_*u01.y + wc*u10.y + wd*u11.y, 0.f);
        o.z = fmaxf(av.z + bv.z + wa*u00.z + wb_*u01.z + wc*u10.z + wd*u11.z, 0.f);
        o.w = fmaxf(av.w + bv.w + wa*u00.w + wb_*u01.w + wc*u10.w + wd*u11.w, 0.f);
        *(float4*)&ob[c] = o;
    }
}

// ===========================================================================
// K5m: q[m][tap*8+o] = off_feat[m][:] @ W2[o][:][tap]   (N = 72, padded 80)
//   warps: 4 m-warps x 2 n-warps; warp tile 32m x 40n
// ===========================================================================
__global__ __launch_bounds__(256)
void k5m(const float* __restrict__ W2)
{
    __shared__ unsigned As2[128][20];
    __shared__ unsigned Bs2[16][88];

    const int tid = threadIdx.x, lane = tid & 31, warp = tid >> 5;
    const int wm = warp >> 1, wn = warp & 1;
    const int m0 = blockIdx.x * 128;

    // zero pad columns (n >= 72) once
    for (int i = tid; i < 16 * 88; i += 256) ((unsigned*)Bs2)[i] = 0u;

    float d[2][5][4];
#pragma unroll
    for (int i = 0; i < 2; ++i)
#pragma unroll
        for (int j = 0; j < 5; ++j)
#pragma unroll
            for (int e = 0; e < 4; ++e) d[i][j][e] = 0.f;

    const int mA = tid >> 1, khA = (tid & 1) * 8;
    const int nB = tid >> 1, kqB = (tid & 1) * 8;       // nB valid < 72
    const int oB = nB & 7, tapB = nB >> 3;

    for (int k0 = 0; k0 < 256; k0 += 16) {
        const float* ap = g_offfeat + (size_t)(m0 + mA) * 256 + k0 + khA;
        float4 va0 = *(const float4*)ap;
        float4 va1 = *(const float4*)(ap + 4);
        float wv[8];
        if (nB < 72) {
            const float* bp = W2 + (size_t)oB * 2304 + tapB;
#pragma unroll
            for (int i = 0; i < 8; ++i) wv[i] = bp[(size_t)(k0 + kqB + i) * 9];
        }
        __syncthreads();
        *(uint4*)&As2[mA][khA]     = make_uint4(f2tf32(va0.x), f2tf32(va0.y), f2tf32(va0.z), f2tf32(va0.w));
        *(uint4*)&As2[mA][khA + 4] = make_uint4(f2tf32(va1.x), f2tf32(va1.y), f2tf32(va1.z), f2tf32(va1.w));
        if (nB < 72) {
#pragma unroll
            for (int i = 0; i < 8; ++i) Bs2[kqB + i][nB] = f2tf32(wv[i]);
        }
        __syncthreads();
#pragma unroll
        for (int ks = 0; ks < 16; ks += 8) {
            const int kr = ks + (lane & 3);
            const int mb = wm * 32 + (lane >> 2);
            const int nb = wn * 40 + (lane >> 2);
            unsigned a[2][4], b[5][2];
#pragma unroll
            for (int mt = 0; mt < 2; ++mt) {
                a[mt][0] = As2[mb + mt * 16][kr];
                a[mt][1] = As2[mb + mt * 16 + 8][kr];
                a[mt][2] = As2[mb + mt * 16][kr + 4];
                a[mt][3] = As2[mb + mt * 16 + 8][kr + 4];
            }
#pragma unroll
            for (int nt = 0; nt < 5; ++nt) {
                b[nt][0] = Bs2[kr][nb + nt * 8];
                b[nt][1] = Bs2[kr + 4][nb + nt * 8];
            }
#pragma unroll
            for (int mt = 0; mt < 2; ++mt)
#pragma unroll
                for (int nt = 0; nt < 5; ++nt)
                    MMA_TF32(d[mt][nt], a[mt], b[nt]);
        }
    }

#pragma unroll
    for (int mt = 0; mt < 2; ++mt) {
        const int row = m0 + wm * 32 + mt * 16 + (lane >> 2);
#pragma unroll
        for (int nt = 0; nt < 5; ++nt) {
            const int col = wn * 40 + nt * 8 + (lane & 3) * 2;
            if (col < 72) {
                *(float2*)&g_q[(size_t)row * 72 + col] = make_float2(d[mt][nt][0], d[mt][nt][1]);
                *(float2*)&g_q[(size_t)(row + 8) * 72 + col] = make_float2(d[mt][nt][2], d[mt][nt][3]);
            }
        }
    }
}

// ===========================================================================
// K6: offsets[p][o] = b2[o] + sum_{dy,dx} q[p + (dy-1,dx-1)][(dy*3+dx)*8+o]
// ===========================================================================
__global__ __launch_bounds__(256)
void k6_stencil(const float* __restrict__ b2)
{
    const int p = blockIdx.x * 256 + threadIdx.x;
    const int bb = p >> 14, s = p & 16383, y = s >> 7, x = s & 127;
    float4 a0 = *(const float4*)&b2[0];
    float4 a1 = *(const float4*)&b2[4];
    const float* qb = g_q + (size_t)bb * HWHI * 72;
#pragma unroll
    for (int dy = 0; dy < 3; ++dy) {
        const int yy = y + dy - 1;
        if (yy < 0 || yy > 127) continue;
#pragma unroll
        for (int dx = 0; dx < 3; ++dx) {
            const int xx = x + dx - 1;
            if (xx < 0 || xx > 127) continue;
            const float* qq = qb + (size_t)(yy * 128 + xx) * 72 + (dy * 3 + dx) * 8;
            float4 v0 = *(const float4*)qq;
            float4 v1 = *(const float4*)(qq + 4);
            a0.x += v0.x; a0.y += v0.y; a0.z += v0.z; a0.w += v0.w;
            a1.x += v1.x; a1.y += v1.y; a1.z += v1.z; a1.w += v1.w;
        }
    }
    *(float4*)&g_offsets[(size_t)p * 8] = a0;
    *(float4*)&g_offsets[(size_t)p * 8 + 4] = a1;
}

// ===========================================================================
// K4: deformable 4-point bilinear sample + average (proven in R1)
// ===========================================================================
__global__ __launch_bounds__(256)
void k4_sample(float* __restrict__ out)
{
    __shared__ int   sh_idx[32][16];
    __shared__ float sh_w[32][16];
    __shared__ float sh_t[32][132];

    const int tid = threadIdx.x;
    const int bx = blockIdx.x;
    const int xt = bx >> 1;
    const int ch = bx & 1;
    const int y  = blockIdx.y;
    const int bb = blockIdx.z;
    const int x0 = xt * 32;

    if (tid < 128) {
        const int px = tid >> 2, p = tid & 3;
        const int x = x0 + px;
        const size_t pi = ((size_t)bb * HWHI + y * 128 + x) * 8;
        const float ox = g_offsets[pi + 2 * p]     * (1.0f / 64.0f);
        const float oy = g_offsets[pi + 2 * p + 1] * (1.0f / 64.0f);
        const float gx = fmaf((float)x, 2.0f / 127.0f, -1.0f) + ox;
        const float gy = fmaf((float)y, 2.0f / 127.0f, -1.0f) + oy;
        const float gxp = fminf(fmaxf(fmaf(gx, 32.0f, 31.5f), 0.0f), 63.0f);
        const float gyp = fminf(fmaxf(fmaf(gy, 32.0f, 31.5f), 0.0f), 63.0f);
        const float fx0 = floorf(gxp), fy0 = floorf(gyp);
        const int ix0 = (int)fx0, iy0 = (int)fy0;
        const float fx = gxp - fx0, fy = gyp - fy0;
        const int ix1 = (ix0 + 1 > 63) ? 63 : ix0 + 1;
        const int iy1 = (iy0 + 1 > 63) ? 63 : iy0 + 1;
        const int q = p * 4;
        sh_idx[px][q + 0] = (iy0 * 64 + ix0) * 256;
        sh_idx[px][q + 1] = (iy0 * 64 + ix1) * 256;
        sh_idx[px][q + 2] = (iy1 * 64 + ix0) * 256;
        sh_idx[px][q + 3] = (iy1 * 64 + ix1) * 256;
        sh_w[px][q + 0] = (1.f - fx) * (1.f - fy) * 0.25f;
        sh_w[px][q + 1] = fx * (1.f - fy) * 0.25f;
        sh_w[px][q + 2] = (1.f - fx) * fy * 0.25f;
        sh_w[px][q + 3] = fx * fy * 0.25f;
    }
    __syncthreads();

    const int lane = tid & 31, wrp = tid >> 5;
    const float* pb = g_proc + (size_t)bb * HWLO * 256 + ch * 128 + 4 * lane;

#pragma unroll
    for (int r = 0; r < 4; ++r) {
        const int px = wrp * 4 + r;
        float4 acc = make_float4(0.f, 0.f, 0.f, 0.f);
#pragma unroll
        for (int t = 0; t < 16; ++t) {
            const float wt = sh_w[px][t];
            const float4 v = *(const float4*)(pb + sh_idx[px][t]);
            acc.x = fmaf(wt, v.x, acc.x);
            acc.y = fmaf(wt, v.y, acc.y);
            acc.z = fmaf(wt, v.z, acc.z);
            acc.w = fmaf(wt, v.w, acc.w);
        }
        *(float4*)&sh_t[px][4 * lane] = acc;
    }
    __syncthreads();

    const int xl = tid & 31;
    const int c0 = tid >> 5;
#pragma unroll
    for (int i = 0; i < 16; ++i) {
        const int c = c0 * 16 + i;
        out[((size_t)bb * 256 + ch * 128 + c) * HWHI + y * 128 + x0 + xl] = sh_t[xl][c];
    }
}

// ===========================================================================
extern "C" void kernel_launch(void* const* d_in, const int* in_sizes, int n_in,
                              void* d_out, int out_size)
{
    const float* high = (const float*)d_in[0];
    const float* low  = (const float*)d_in[1];
    const float* W1   = (const float*)d_in[2];
    const float* b1   = (const float*)d_in[3];
    const float* W2   = (const float*)d_in[4];
    const float* b2   = (const float*)d_in[5];
    const float* Wf   = (const float*)d_in[6];
    const float* bf   = (const float*)d_in[7];
    float* out = (float*)d_out;

    const int SMEM_K2 = 17408 + 128 * 132 * 4;   // As+Bs + stage = 84992
    static int inited = 0;
    if (!inited) {
        cudaFuncSetAttribute(k2m, cudaFuncAttributeMaxDynamicSharedMemorySize, SMEM_K2);
        inited = 1;
    }

    k1m<<<dim3(256, 4), 256>>>(high, W1, Wf, bf);
    k2m<<<dim3(1024, 2), 256, SMEM_K2>>>(low, W1, b1);
    k5m<<<1024, 256>>>(W2);
    k6_stencil<<<512, 256>>>(b2);
    k4_sample<<<dim3(8, 128, 8), 256>>>(out);
}

// round 4
// speedup vs baseline: 1.7571x; 1.0883x over previous
#include <cuda_runtime.h>
#include <cuda_fp16.h>

// ---------------------------------------------------------------------------
// AdaUp via fp16 mma.sync m16n8k16 (f32 accum), ldmatrix fragment loads from
// SW128-swizzled k-major smem, double-buffered mainloops.
//   K1h: t = W1a@high ; proc = Wf@high + bf
//   K2h: off_feat = relu(W1b@low + up2x(t) + b1)
//   K5h: q[p][tap*8+o] = W2[:,:,tap]@off_feat(p)  (N=72 pad 80)
//   K6 : offsets(p) = b2 + sum_tap q[p+delta(tap)]
//   K4 : 4-point deformable bilinear sampling of proc, averaged
// ---------------------------------------------------------------------------

#define NB    8
#define HWLO  4096
#define HWHI  16384

__device__ float g_t[(size_t)NB * HWLO * 256];
__device__ float g_proc[(size_t)NB * HWLO * 256];
__device__ float g_offfeat[(size_t)NB * HWHI * 256];
__device__ float g_q[(size_t)NB * HWHI * 72];
__device__ float g_offsets[(size_t)NB * HWHI * 8];

__device__ __forceinline__ unsigned smem_u32(const void* p) {
    unsigned a;
    asm("{ .reg .u64 t; cvta.to.shared.u64 t, %1; cvt.u32.u64 %0, t; }" : "=r"(a) : "l"(p));
    return a;
}
__device__ __forceinline__ unsigned sw128(unsigned o) { return o ^ ((o >> 3) & 0x70); }
__device__ __forceinline__ unsigned pack_h2(float lo, float hi) {
    unsigned u;
    asm("cvt.rn.f16x2.f32 %0, %1, %2;" : "=r"(u) : "f"(hi), "f"(lo));
    return u;
}
__device__ __forceinline__ void sts128(unsigned a, unsigned x, unsigned y, unsigned z, unsigned w) {
    asm volatile("st.shared.v4.b32 [%0], {%1,%2,%3,%4};" :: "r"(a), "r"(x), "r"(y), "r"(z), "r"(w));
}

#define LDSM_X4(r0, r1, r2, r3, addr) \
    asm volatile("ldmatrix.sync.aligned.m8n8.x4.shared.b16 {%0,%1,%2,%3}, [%4];" \
                 : "=r"(r0), "=r"(r1), "=r"(r2), "=r"(r3) : "r"(addr))
#define LDSM_X2(r0, r1, addr) \
    asm volatile("ldmatrix.sync.aligned.m8n8.x2.shared.b16 {%0,%1}, [%2];" \
                 : "=r"(r0), "=r"(r1) : "r"(addr))

// D(16x8,f32) += A(16x16 f16, row) @ B(16x8 f16, col)
#define MMA_F16(d, a, b) \
    asm volatile("mma.sync.aligned.m16n8k16.row.col.f32.f16.f16.f32 " \
                 "{%0,%1,%2,%3}, {%4,%5,%6,%7}, {%8,%9}, {%0,%1,%2,%3};" \
                 : "+f"((d)[0]), "+f"((d)[1]), "+f"((d)[2]), "+f"((d)[3]) \
                 : "r"((a)[0]), "r"((a)[1]), "r"((a)[2]), "r"((a)[3]), \
                   "r"((b)[0]), "r"((b)[1]))

// Smem tile: rows = m (or n), 128 bytes = 64 fp16 k-values per row, SW128.
// Buffer offsets (dynamic smem): A0=0, A1=16K, B0=32K, B1=B0+Bsz.

// ===========================================================================
// K1h: [t | proc](m, n) ;  A[k][m] strided gmem (m contiguous)
// grid (256, 4): y = ny*2 + nhalf
// ===========================================================================
__global__ __launch_bounds__(256)
void k1h(const float* __restrict__ high, const float* __restrict__ W1,
         const float* __restrict__ Wf, const float* __restrict__ bf)
{
    extern __shared__ char dsm[];
    const unsigned sb = smem_u32(dsm);
    const int tid = threadIdx.x, lane = tid & 31, warp = tid >> 5;
    const int wm = warp & 1, wn = warp >> 1;
    const int m0 = blockIdx.x * 128;
    const int ny = blockIdx.y >> 1, nhalf = blockIdx.y & 1;
    const int bb = m0 >> 12, s0 = m0 & 4095;

    const float* Ab = high + (size_t)bb * 256 * HWLO + s0;
    const float* Bb = ny ? Wf : W1;
    const int brs = ny ? 256 : 512;

    const int lm = tid & 127;            // A: m-row / B: n-row (local)
    const int lkq = (tid >> 7) * 32;     // k sub-range (halves)

    // fragment lane offsets (bytes within tile)
    unsigned aoff[4], boff[2];
#pragma unroll
    for (int mt = 0; mt < 4; ++mt)
        aoff[mt] = ((unsigned)(wm * 64 + mt * 16 + (lane & 15)) << 7) + (lane >> 4) * 16;
#pragma unroll
    for (int p = 0; p < 2; ++p)
        boff[p] = ((unsigned)(wn * 32 + p * 16 + (lane & 7) + ((lane >> 4) & 1) * 8) << 7)
                  + ((lane >> 3) & 1) * 16;

    float d[4][4][4];
#pragma unroll
    for (int i = 0; i < 4; ++i)
#pragma unroll
        for (int j = 0; j < 4; ++j)
#pragma unroll
            for (int e = 0; e < 4; ++e) d[i][j][e] = 0.f;

    unsigned hA[16];

    // ---- prefetch A chunk 0 ----
#pragma unroll
    for (int g = 0; g < 4; ++g) {
        const float* p = Ab + (size_t)(lkq + g * 8) * HWLO + lm;
#pragma unroll
        for (int j = 0; j < 4; ++j)
            hA[g * 4 + j] = pack_h2(p[(size_t)(2 * j) * HWLO], p[(size_t)(2 * j + 1) * HWLO]);
    }
    // store A0 + B0
#pragma unroll
    for (int g = 0; g < 4; ++g)
        sts128(sb + sw128(lm * 128 + (lkq + g * 8) * 2),
               hA[g * 4], hA[g * 4 + 1], hA[g * 4 + 2], hA[g * 4 + 3]);
    {
        const int nn = nhalf * 128 + lm;
#pragma unroll
        for (int g = 0; g < 4; ++g) {
            const float* p = Bb + (size_t)nn * brs + lkq + g * 8;
            float4 v0 = *(const float4*)p, v1 = *(const float4*)(p + 4);
            sts128(sb + 32768 + sw128(lm * 128 + (lkq + g * 8) * 2),
                   pack_h2(v0.x, v0.y), pack_h2(v0.z, v0.w),
                   pack_h2(v1.x, v1.y), pack_h2(v1.z, v1.w));
        }
    }
    __syncthreads();

    for (int kt = 0; kt < 4; ++kt) {
        if (kt < 3) {
            const int k0 = (kt + 1) * 64;
#pragma unroll
            for (int g = 0; g < 4; ++g) {
                const float* p = Ab + (size_t)(k0 + lkq + g * 8) * HWLO + lm;
#pragma unroll
                for (int j = 0; j < 4; ++j)
                    hA[g * 4 + j] = pack_h2(p[(size_t)(2 * j) * HWLO], p[(size_t)(2 * j + 1) * HWLO]);
            }
        }
        const unsigned bufA = sb + (kt & 1) * 16384;
        const unsigned bufB = sb + 32768 + (kt & 1) * 16384;
#pragma unroll
        for (int ks = 0; ks < 4; ++ks) {
            const unsigned ksb = ks * 32;
            unsigned a[4][4], b[4][2];
#pragma unroll
            for (int mt = 0; mt < 4; ++mt)
                LDSM_X4(a[mt][0], a[mt][1], a[mt][2], a[mt][3], bufA + sw128(aoff[mt] + ksb));
            LDSM_X4(b[0][0], b[0][1], b[1][0], b[1][1], bufB + sw128(boff[0] + ksb));
            LDSM_X4(b[2][0], b[2][1], b[3][0], b[3][1], bufB + sw128(boff[1] + ksb));
#pragma unroll
            for (int mt = 0; mt < 4; ++mt)
#pragma unroll
                for (int nt = 0; nt < 4; ++nt)
                    MMA_F16(d[mt][nt], a[mt], b[nt]);
        }
        if (kt < 3) {
            __syncthreads();
            const unsigned nbufA = sb + ((kt + 1) & 1) * 16384;
            const unsigned nbufB = sb + 32768 + ((kt + 1) & 1) * 16384;
#pragma unroll
            for (int g = 0; g < 4; ++g)
                sts128(nbufA + sw128(lm * 128 + (lkq + g * 8) * 2),
                       hA[g * 4], hA[g * 4 + 1], hA[g * 4 + 2], hA[g * 4 + 3]);
            const int nn = nhalf * 128 + lm;
            const int k0 = (kt + 1) * 64;
#pragma unroll
            for (int g = 0; g < 4; ++g) {
                const float* p = Bb + (size_t)nn * brs + k0 + lkq + g * 8;
                float4 v0 = *(const float4*)p, v1 = *(const float4*)(p + 4);
                sts128(nbufB + sw128(lm * 128 + (lkq + g * 8) * 2),
                       pack_h2(v0.x, v0.y), pack_h2(v0.z, v0.w),
                       pack_h2(v1.x, v1.y), pack_h2(v1.z, v1.w));
            }
            __syncthreads();
        }
    }

    float* ob = ny ? g_proc : g_t;
#pragma unroll
    for (int mt = 0; mt < 4; ++mt) {
        const int row = m0 + wm * 64 + mt * 16 + (lane >> 2);
#pragma unroll
        for (int nt = 0; nt < 4; ++nt) {
            const int col = nhalf * 128 + wn * 32 + nt * 8 + (lane & 3) * 2;
            float b0 = 0.f, b1 = 0.f;
            if (ny) { b0 = bf[col]; b1 = bf[col + 1]; }
            *(float2*)&ob[(size_t)row * 256 + col] =
                make_float2(d[mt][nt][0] + b0, d[mt][nt][1] + b1);
            *(float2*)&ob[(size_t)(row + 8) * 256 + col] =
                make_float2(d[mt][nt][2] + b0, d[mt][nt][3] + b1);
        }
    }
}

// ===========================================================================
// K2h: off_feat = relu(W1b@low + up2x(t) + b1) ; grid (1024, 2)
// ===========================================================================
__global__ __launch_bounds__(256)
void k2h(const float* __restrict__ low, const float* __restrict__ W1,
         const float* __restrict__ b1)
{
    extern __shared__ char dsm[];
    const unsigned sb = smem_u32(dsm);
    float (*stage)[132] = (float(*)[132])dsm;     // aliases buffers (used after)

    const int tid = threadIdx.x, lane = tid & 31, warp = tid >> 5;
    const int wm = warp & 1, wn = warp >> 1;
    const int m0 = blockIdx.x * 128;
    const int n0 = blockIdx.y * 128;
    const int bb = m0 >> 14, s0 = m0 & 16383;

    const float* Ab = low + (size_t)bb * 256 * HWHI + s0;

    const int lm = tid & 127;
    const int lkq = (tid >> 7) * 32;

    unsigned aoff[4], boff[2];
#pragma unroll
    for (int mt = 0; mt < 4; ++mt)
        aoff[mt] = ((unsigned)(wm * 64 + mt * 16 + (lane & 15)) << 7) + (lane >> 4) * 16;
#pragma unroll
    for (int p = 0; p < 2; ++p)
        boff[p] = ((unsigned)(wn * 32 + p * 16 + (lane & 7) + ((lane >> 4) & 1) * 8) << 7)
                  + ((lane >> 3) & 1) * 16;

    float d[4][4][4];
#pragma unroll
    for (int i = 0; i < 4; ++i)
#pragma unroll
        for (int j = 0; j < 4; ++j)
#pragma unroll
            for (int e = 0; e < 4; ++e) d[i][j][e] = 0.f;

    unsigned hA[16];
#pragma unroll
    for (int g = 0; g < 4; ++g) {
        const float* p = Ab + (size_t)(lkq + g * 8) * HWHI + lm;
#pragma unroll
        for (int j = 0; j < 4; ++j)
            hA[g * 4 + j] = pack_h2(p[(size_t)(2 * j) * HWHI], p[(size_t)(2 * j + 1) * HWHI]);
    }
#pragma unroll
    for (int g = 0; g < 4; ++g)
        sts128(sb + sw128(lm * 128 + (lkq + g * 8) * 2),
               hA[g * 4], hA[g * 4 + 1], hA[g * 4 + 2], hA[g * 4 + 3]);
    {
        const int nn = n0 + lm;
#pragma unroll
        for (int g = 0; g < 4; ++g) {
            const float* p = W1 + (size_t)nn * 512 + 256 + lkq + g * 8;
            float4 v0 = *(const float4*)p, v1 = *(const float4*)(p + 4);
            sts128(sb + 32768 + sw128(lm * 128 + (lkq + g * 8) * 2),
                   pack_h2(v0.x, v0.y), pack_h2(v0.z, v0.w),
                   pack_h2(v1.x, v1.y), pack_h2(v1.z, v1.w));
        }
    }
    __syncthreads();

    for (int kt = 0; kt < 4; ++kt) {
        if (kt < 3) {
            const int k0 = (kt + 1) * 64;
#pragma unroll
            for (int g = 0; g < 4; ++g) {
                const float* p = Ab + (size_t)(k0 + lkq + g * 8) * HWHI + lm;
#pragma unroll
                for (int j = 0; j < 4; ++j)
                    hA[g * 4 + j] = pack_h2(p[(size_t)(2 * j) * HWHI], p[(size_t)(2 * j + 1) * HWHI]);
            }
        }
        const unsigned bufA = sb + (kt & 1) * 16384;
        const unsigned bufB = sb + 32768 + (kt & 1) * 16384;
#pragma unroll
        for (int ks = 0; ks < 4; ++ks) {
            const unsigned ksb = ks * 32;
            unsigned a[4][4], b[4][2];
#pragma unroll
            for (int mt = 0; mt < 4; ++mt)
                LDSM_X4(a[mt][0], a[mt][1], a[mt][2], a[mt][3], bufA + sw128(aoff[mt] + ksb));
            LDSM_X4(b[0][0], b[0][1], b[1][0], b[1][1], bufB + sw128(boff[0] + ksb));
            LDSM_X4(b[2][0], b[2][1], b[3][0], b[3][1], bufB + sw128(boff[1] + ksb));
#pragma unroll
            for (int mt = 0; mt < 4; ++mt)
#pragma unroll
                for (int nt = 0; nt < 4; ++nt)
                    MMA_F16(d[mt][nt], a[mt], b[nt]);
        }
        if (kt < 3) {
            __syncthreads();
            const unsigned nbufA = sb + ((kt + 1) & 1) * 16384;
            const unsigned nbufB = sb + 32768 + ((kt + 1) & 1) * 16384;
#pragma unroll
            for (int g = 0; g < 4; ++g)
                sts128(nbufA + sw128(lm * 128 + (lkq + g * 8) * 2),
                       hA[g * 4], hA[g * 4 + 1], hA[g * 4 + 2], hA[g * 4 + 3]);
            const int nn = n0 + lm;
            const int k0 = (kt + 1) * 64;
#pragma unroll
            for (int g = 0; g < 4; ++g) {
                const float* p = W1 + (size_t)nn * 512 + 256 + k0 + lkq + g * 8;
                float4 v0 = *(const float4*)p, v1 = *(const float4*)(p + 4);
                sts128(nbufB + sw128(lm * 128 + (lkq + g * 8) * 2),
                       pack_h2(v0.x, v0.y), pack_h2(v0.z, v0.w),
                       pack_h2(v1.x, v1.y), pack_h2(v1.z, v1.w));
            }
            __syncthreads();
        }
    }

    // stage accumulators then per-pixel epilogue
    __syncthreads();
#pragma unroll
    for (int mt = 0; mt < 4; ++mt) {
        const int sr = wm * 64 + mt * 16 + (lane >> 2);
#pragma unroll
        for (int nt = 0; nt < 4; ++nt) {
            const int sc = wn * 32 + nt * 8 + (lane & 3) * 2;
            *(float2*)&stage[sr][sc]     = make_float2(d[mt][nt][0], d[mt][nt][1]);
            *(float2*)&stage[sr + 8][sc] = make_float2(d[mt][nt][2], d[mt][nt][3]);
        }
    }
    __syncthreads();

    const int p = tid >> 1, chh = tid & 1;
    const int m = m0 + p;
    const int s = m & 16383, yy = s >> 7, xx = s & 127;
    const int th = yy >> 1, tw = xx >> 1;
    int jy0, jy1, jx0, jx1;
    float wy0, wy1, wx0, wx1;
    if (yy & 1) { jy0 = th; jy1 = (th + 1 > 63) ? 63 : th + 1; wy0 = 0.75f; wy1 = 0.25f; }
    else        { jy0 = (th - 1 < 0) ? 0 : th - 1; jy1 = th;   wy0 = 0.25f; wy1 = 0.75f; }
    if (xx & 1) { jx0 = tw; jx1 = (tw + 1 > 63) ? 63 : tw + 1; wx0 = 0.75f; wx1 = 0.25f; }
    else        { jx0 = (tw - 1 < 0) ? 0 : tw - 1; jx1 = tw;   wx0 = 0.25f; wx1 = 0.75f; }
    const float wa = wy0 * wx0, wb_ = wy0 * wx1, wc = wy1 * wx0, wd = wy1 * wx1;
    const float* tb = g_t + (size_t)bb * HWLO * 256;
    const float* p00 = tb + (size_t)(jy0 * 64 + jx0) * 256 + n0;
    const float* p01 = tb + (size_t)(jy0 * 64 + jx1) * 256 + n0;
    const float* p10 = tb + (size_t)(jy1 * 64 + jx0) * 256 + n0;
    const float* p11 = tb + (size_t)(jy1 * 64 + jx1) * 256 + n0;
    float* ob = g_offfeat + (size_t)m * 256 + n0;

#pragma unroll
    for (int g = 0; g < 16; ++g) {
        const int c = chh * 64 + g * 4;
        float4 av  = *(const float4*)&stage[p][c];
        float4 bv  = *(const float4*)&b1[n0 + c];
        float4 u00 = *(const float4*)&p00[c];
        float4 u01 = *(const float4*)&p01[c];
        float4 u10 = *(const float4*)&p10[c];
        float4 u11 = *(const float4*)&p11[c];
        float4 o;
        o.x = fmaxf(av.x + bv.x + wa*u00.x + wb_*u01.x + wc*u10.x + wd*u11.x, 0.f);
        o.y = fmaxf(av.y + bv.y + wa*u00.y + wb_*u01.y + wc*u10.y + wd*u11.y, 0.f);
        o.z = fmaxf(av.z + bv.z + wa*u00.z + wb_*u01.z + wc*u10.z + wd*u11.z, 0.f);
        o.w = fmaxf(av.w + bv.w + wa*u00.w + wb_*u01.w + wc*u10.w + wd*u11.w, 0.f);
        *(float4*)&ob[c] = o;
    }
}

// ===========================================================================
// K5h: q = off_feat @ W2-per-tap  (N=72 pad 80). A is k-contiguous in gmem.
// warps: wm = warp>>1 (32m), wn = warp&1 (40n)
// ===========================================================================
__global__ __launch_bounds__(256)
void k5h(const float* __restrict__ W2)
{
    extern __shared__ char dsm[];
    const unsigned sb = smem_u32(dsm);
    const int tid = threadIdx.x, lane = tid & 31, warp = tid >> 5;
    const int wm = warp >> 1, wn = warp & 1;
    const int m0 = blockIdx.x * 128;

    const int lm = tid & 127;
    const int lkq = (tid >> 7) * 32;

    // B loader role: threads 0-79 -> (n=tid, kq=0); 128-207 -> (n=tid-128, kq=32)
    const int bn = (tid < 128) ? tid : tid - 128;
    const int bkq = (tid < 128) ? 0 : 32;
    const bool bact = (bn < 80);
    const int btap = bn >> 3, bo = bn & 7;

    unsigned aoff[2], boffp[2], boffs;
#pragma unroll
    for (int mt = 0; mt < 2; ++mt)
        aoff[mt] = ((unsigned)(wm * 32 + mt * 16 + (lane & 15)) << 7) + (lane >> 4) * 16;
#pragma unroll
    for (int p = 0; p < 2; ++p)
        boffp[p] = ((unsigned)(wn * 40 + p * 16 + (lane & 7) + ((lane >> 4) & 1) * 8) << 7)
                   + ((lane >> 3) & 1) * 16;
    boffs = ((unsigned)(wn * 40 + 32 + (lane & 7)) << 7) + ((lane >> 3) & 1) * 16;

    float d[2][5][4];
#pragma unroll
    for (int i = 0; i < 2; ++i)
#pragma unroll
        for (int j = 0; j < 5; ++j)
#pragma unroll
            for (int e = 0; e < 4; ++e) d[i][j][e] = 0.f;

    const float* Ab = g_offfeat + ((size_t)m0 + lm) * 256;

    unsigned hA[16];
#pragma unroll
    for (int g = 0; g < 4; ++g) {
        float4 v0 = *(const float4*)&Ab[lkq + g * 8];
        float4 v1 = *(const float4*)&Ab[lkq + g * 8 + 4];
        hA[g * 4 + 0] = pack_h2(v0.x, v0.y); hA[g * 4 + 1] = pack_h2(v0.z, v0.w);
        hA[g * 4 + 2] = pack_h2(v1.x, v1.y); hA[g * 4 + 3] = pack_h2(v1.z, v1.w);
    }
#pragma unroll
    for (int g = 0; g < 4; ++g)
        sts128(sb + sw128(lm * 128 + (lkq + g * 8) * 2),
               hA[g * 4], hA[g * 4 + 1], hA[g * 4 + 2], hA[g * 4 + 3]);
    if (bact) {
#pragma unroll
        for (int g = 0; g < 4; ++g) {
            unsigned h[4] = {0u, 0u, 0u, 0u};
            if (bn < 72) {
                const float* p = W2 + (size_t)bo * 2304 + btap;
#pragma unroll
                for (int j = 0; j < 4; ++j)
                    h[j] = pack_h2(p[(size_t)(bkq + g * 8 + 2 * j) * 9],
                                   p[(size_t)(bkq + g * 8 + 2 * j + 1) * 9]);
            }
            sts128(sb + 32768 + sw128(bn * 128 + (bkq + g * 8) * 2), h[0], h[1], h[2], h[3]);
        }
    }
    __syncthreads();

    for (int kt = 0; kt < 4; ++kt) {
        if (kt < 3) {
            const int k0 = (kt + 1) * 64;
#pragma unroll
            for (int g = 0; g < 4; ++g) {
                float4 v0 = *(const float4*)&Ab[k0 + lkq + g * 8];
                float4 v1 = *(const float4*)&Ab[k0 + lkq + g * 8 + 4];
                hA[g * 4 + 0] = pack_h2(v0.x, v0.y); hA[g * 4 + 1] = pack_h2(v0.z, v0.w);
                hA[g * 4 + 2] = pack_h2(v1.x, v1.y); hA[g * 4 + 3] = pack_h2(v1.z, v1.w);
            }
        }
        const unsigned bufA = sb + (kt & 1) * 16384;
        const unsigned bufB = sb + 32768 + (kt & 1) * 10240;
#pragma unroll
        for (int ks = 0; ks < 4; ++ks) {
            const unsigned ksb = ks * 32;
            unsigned a[2][4], b[5][2];
#pragma unroll
            for (int mt = 0; mt < 2; ++mt)
                LDSM_X4(a[mt][0], a[mt][1], a[mt][2], a[mt][3], bufA + sw128(aoff[mt] + ksb));
            LDSM_X4(b[0][0], b[0][1], b[1][0], b[1][1], bufB + sw128(boffp[0] + ksb));
            LDSM_X4(b[2][0], b[2][1], b[3][0], b[3][1], bufB + sw128(boffp[1] + ksb));
            LDSM_X2(b[4][0], b[4][1], bufB + sw128(boffs + ksb));
#pragma unroll
            for (int mt = 0; mt < 2; ++mt)
#pragma unroll
                for (int nt = 0; nt < 5; ++nt)
                    MMA_F16(d[mt][nt], a[mt], b[nt]);
        }
        if (kt < 3) {
            __syncthreads();
            const unsigned nbufA = sb + ((kt + 1) & 1) * 16384;
            const unsigned nbufB = sb + 32768 + ((kt + 1) & 1) * 10240;
#pragma unroll
            for (int g = 0; g < 4; ++g)
                sts128(nbufA + sw128(lm * 128 + (lkq + g * 8) * 2),
                       hA[g * 4], hA[g * 4 + 1], hA[g * 4 + 2], hA[g * 4 + 3]);
            if (bact) {
                const int k0 = (kt + 1) * 64;
#pragma unroll
                for (int g = 0; g < 4; ++g) {
                    unsigned h[4] = {0u, 0u, 0u, 0u};
                    if (bn < 72) {
                        const float* p = W2 + (size_t)bo * 2304 + btap;
#pragma unroll
                        for (int j = 0; j < 4; ++j)
                            h[j] = pack_h2(p[(size_t)(k0 + bkq + g * 8 + 2 * j) * 9],
                                           p[(size_t)(k0 + bkq + g * 8 + 2 * j + 1) * 9]);
                    }
                    sts128(nbufB + sw128(bn * 128 + (bkq + g * 8) * 2), h[0], h[1], h[2], h[3]);
                }
            }
            __syncthreads();
        }
    }

#pragma unroll
    for (int mt = 0; mt < 2; ++mt) {
        const int row = m0 + wm * 32 + mt * 16 + (lane >> 2);
#pragma unroll
        for (int nt = 0; nt < 5; ++nt) {
            const int col = wn * 40 + nt * 8 + (lane & 3) * 2;
            if (col < 72) {
                *(float2*)&g_q[(size_t)row * 72 + col] = make_float2(d[mt][nt][0], d[mt][nt][1]);
                *(float2*)&g_q[(size_t)(row + 8) * 72 + col] = make_float2(d[mt][nt][2], d[mt][nt][3]);
            }
        }
    }
}

// ===========================================================================
// K6: offsets[p][o] = b2[o] + sum_{dy,dx} q[p + (dy-1,dx-1)][(dy*3+dx)*8+o]
// ===========================================================================
__global__ __launch_bounds__(256)
void k6_stencil(const float* __restrict__ b2)
{
    const int p = blockIdx.x * 256 + threadIdx.x;
    const int bb = p >> 14, s = p & 16383, y = s >> 7, x = s & 127;
    float4 a0 = *(const float4*)&b2[0];
    float4 a1 = *(const float4*)&b2[4];
    const float* qb = g_q + (size_t)bb * HWHI * 72;
#pragma unroll
    for (int dy = 0; dy < 3; ++dy) {
        const int yy = y + dy - 1;
        if (yy < 0 || yy > 127) continue;
#pragma unroll
        for (int dx = 0; dx < 3; ++dx) {
            const int xx = x + dx - 1;
            if (xx < 0 || xx > 127) continue;
            const float* qq = qb + (size_t)(yy * 128 + xx) * 72 + (dy * 3 + dx) * 8;
            float4 v0 = *(const float4*)qq;
            float4 v1 = *(const float4*)(qq + 4);
            a0.x += v0.x; a0.y += v0.y; a0.z += v0.z; a0.w += v0.w;
            a1.x += v1.x; a1.y += v1.y; a1.z += v1.z; a1.w += v1.w;
        }
    }
    *(float4*)&g_offsets[(size_t)p * 8] = a0;
    *(float4*)&g_offsets[(size_t)p * 8 + 4] = a1;
}

// ===========================================================================
// K4: deformable 4-point bilinear sample + average
// ===========================================================================
__global__ __launch_bounds__(256)
void k4_sample(float* __restrict__ out)
{
    __shared__ int   sh_idx[32][16];
    __shared__ float sh_w[32][16];
    __shared__ float sh_t[32][132];

    const int tid = threadIdx.x;
    const int bx = blockIdx.x;
    const int xt = bx >> 1;
    const int ch = bx & 1;
    const int y  = blockIdx.y;
    const int bb = blockIdx.z;
    const int x0 = xt * 32;

    if (tid < 128) {
        const int px = tid >> 2, p = tid & 3;
        const int x = x0 + px;
        const size_t pi = ((size_t)bb * HWHI + y * 128 + x) * 8;
        const float ox = g_offsets[pi + 2 * p]     * (1.0f / 64.0f);
        const float oy = g_offsets[pi + 2 * p + 1] * (1.0f / 64.0f);
        const float gx = fmaf((float)x, 2.0f / 127.0f, -1.0f) + ox;
        const float gy = fmaf((float)y, 2.0f / 127.0f, -1.0f) + oy;
        const float gxp = fminf(fmaxf(fmaf(gx, 32.0f, 31.5f), 0.0f), 63.0f);
        const float gyp = fminf(fmaxf(fmaf(gy, 32.0f, 31.5f), 0.0f), 63.0f);
        const float fx0 = floorf(gxp), fy0 = floorf(gyp);
        const int ix0 = (int)fx0, iy0 = (int)fy0;
        const float fx = gxp - fx0, fy = gyp - fy0;
        const int ix1 = (ix0 + 1 > 63) ? 63 : ix0 + 1;
        const int iy1 = (iy0 + 1 > 63) ? 63 : iy0 + 1;
        const int q = p * 4;
        sh_idx[px][q + 0] = (iy0 * 64 + ix0) * 256;
        sh_idx[px][q + 1] = (iy0 * 64 + ix1) * 256;
        sh_idx[px][q + 2] = (iy1 * 64 + ix0) * 256;
        sh_idx[px][q + 3] = (iy1 * 64 + ix1) * 256;
        sh_w[px][q + 0] = (1.f - fx) * (1.f - fy) * 0.25f;
        sh_w[px][q + 1] = fx * (1.f - fy) * 0.25f;
        sh_w[px][q + 2] = (1.f - fx) * fy * 0.25f;
        sh_w[px][q + 3] = fx * fy * 0.25f;
    }
    __syncthreads();

    const int lane = tid & 31, wrp = tid >> 5;
    const float* pb = g_proc + (size_t)bb * HWLO * 256 + ch * 128 + 4 * lane;

#pragma unroll
    for (int r = 0; r < 4; ++r) {
        const int px = wrp * 4 + r;
        float4 acc = make_float4(0.f, 0.f, 0.f, 0.f);
#pragma unroll
        for (int t = 0; t < 16; ++t) {
            const float wt = sh_w[px][t];
            const float4 v = *(const float4*)(pb + sh_idx[px][t]);
            acc.x = fmaf(wt, v.x, acc.x);
            acc.y = fmaf(wt, v.y, acc.y);
            acc.z = fmaf(wt, v.z, acc.z);
            acc.w = fmaf(wt, v.w, acc.w);
        }
        *(float4*)&sh_t[px][4 * lane] = acc;
    }
    __syncthreads();

    const int xl = tid & 31;
    const int c0 = tid >> 5;
#pragma unroll
    for (int i = 0; i < 16; ++i) {
        const int c = c0 * 16 + i;
        out[((size_t)bb * 256 + ch * 128 + c) * HWHI + y * 128 + x0 + xl] = sh_t[xl][c];
    }
}

// ===========================================================================
extern "C" void kernel_launch(void* const* d_in, const int* in_sizes, int n_in,
                              void* d_out, int out_size)
{
    const float* high = (const float*)d_in[0];
    const float* low  = (const float*)d_in[1];
    const float* W1   = (const float*)d_in[2];
    const float* b1   = (const float*)d_in[3];
    const float* W2   = (const float*)d_in[4];
    const float* b2   = (const float*)d_in[5];
    const float* Wf   = (const float*)d_in[6];
    const float* bf   = (const float*)d_in[7];
    float* out = (float*)d_out;

    const int SM_K1 = 65536;                 // A0,A1,B0,B1 (16K each)
    const int SM_K2 = 68352;                 // max(buffers 64K, stage 128*132*4)
    const int SM_K5 = 32768 + 2 * 10240;     // 53248
    static int inited = 0;
    if (!inited) {
        cudaFuncSetAttribute(k1h, cudaFuncAttributeMaxDynamicSharedMemorySize, SM_K1);
        cudaFuncSetAttribute(k2h, cudaFuncAttributeMaxDynamicSharedMemorySize, SM_K2);
        cudaFuncSetAttribute(k5h, cudaFuncAttributeMaxDynamicSharedMemorySize, SM_K5);
        inited = 1;
    }

    k1h<<<dim3(256, 4), 256, SM_K1>>>(high, W1, Wf, bf);
    k2h<<<dim3(1024, 2), 256, SM_K2>>>(low, W1, b1);
    k5h<<<1024, 256, SM_K5>>>(W2);
    k6_stencil<<<512, 256>>>(b2);
    k4_sample<<<dim3(8, 128, 8), 256>>>(out);
}

// round 6
// speedup vs baseline: 2.3514x; 1.3382x over previous
#include <cuda_runtime.h>
#include <cuda_fp16.h>

// ---------------------------------------------------------------------------
// AdaUp, fp16 mma.sync + cp.async pipelines.
//   K0t: f32 NCHW -> fp16 NHWC transpose (high, low)   [dst chosen in-device]
//   K0w: weights -> packed fp16 [n][k] table (W1a | Wf | W1b | W2taps | pad)
//   K1f: t = W1a@high (f32 out) ; proc = Wf@high + bf (fp16 out)
//   K2f: off_feat = relu(W1b@low + up2x(t) + b1)  (fp16 out)
//   K5f: q[p][tap*8+o] = W2tap @ off_feat(p)      (f32 out, N=72 pad 80)
//   K6 : offsets = b2 + 9-tap shift-sum of q
//   K4 : 4-point deformable bilinear sampling of fp16 proc, averaged
// ---------------------------------------------------------------------------

#define NB    8
#define HWLO  4096
#define HWHI  16384

__device__ __half g_h16[(size_t)NB * HWLO * 256];    // high, NHWC fp16
__device__ __half g_l16[(size_t)NB * HWHI * 256];    // low, NHWC fp16
__device__ __half g_wh[1024 * 256];                  // packed weights fp16
__device__ float  g_t[(size_t)NB * HWLO * 256];      // W1a@high (f32)
__device__ __half g_proc16[(size_t)NB * HWLO * 256]; // Wf@high + bf (fp16)
__device__ __half g_off16[(size_t)NB * HWHI * 256];  // relu(...) (fp16)
__device__ float  g_q[(size_t)NB * HWHI * 72];
__device__ float  g_offsets[(size_t)NB * HWHI * 8];

__device__ __forceinline__ unsigned smem_u32(const void* p) {
    unsigned a;
    asm("{ .reg .u64 t; cvta.to.shared.u64 t, %1; cvt.u32.u64 %0, t; }" : "=r"(a) : "l"(p));
    return a;
}
__device__ __forceinline__ unsigned sw128(unsigned o) { return o ^ ((o >> 3) & 0x70); }
__device__ __forceinline__ unsigned pack_h2(float lo, float hi) {
    unsigned u;
    asm("cvt.rn.f16x2.f32 %0, %1, %2;" : "=r"(u) : "f"(hi), "f"(lo));
    return u;
}
__device__ __forceinline__ void cpa16(unsigned dst, const void* src) {
    asm volatile("cp.async.cg.shared.global [%0], [%1], 16;" :: "r"(dst), "l"(src));
}
#define CP_COMMIT() asm volatile("cp.async.commit_group;" ::: "memory")
template <int N> __device__ __forceinline__ void cp_wait() {
    asm volatile("cp.async.wait_group %0;" :: "n"(N) : "memory");
}

#define LDSM_X4(r0, r1, r2, r3, addr) \
    asm volatile("ldmatrix.sync.aligned.m8n8.x4.shared.b16 {%0,%1,%2,%3}, [%4];" \
                 : "=r"(r0), "=r"(r1), "=r"(r2), "=r"(r3) : "r"(addr))
#define LDSM_X2(r0, r1, addr) \
    asm volatile("ldmatrix.sync.aligned.m8n8.x2.shared.b16 {%0,%1}, [%2];" \
                 : "=r"(r0), "=r"(r1) : "r"(addr))
#define MMA_F16(d, a, b) \
    asm volatile("mma.sync.aligned.m16n8k16.row.col.f32.f16.f16.f32 " \
                 "{%0,%1,%2,%3}, {%4,%5,%6,%7}, {%8,%9}, {%0,%1,%2,%3};" \
                 : "+f"((d)[0]), "+f"((d)[1]), "+f"((d)[2]), "+f"((d)[3]) \
                 : "r"((a)[0]), "r"((a)[1]), "r"((a)[2]), "r"((a)[3]), \
                   "r"((b)[0]), "r"((b)[1]))

// ===========================================================================
// K0t: [b][k][s] f32 -> [b][s][k] fp16 ; tile 64s x 64k, K=256
// which: 0 -> g_h16 (S=4096), 1 -> g_l16 (S=16384). Dst resolved in device
// code (device globals must NOT be passed as kernel args from host).
// ===========================================================================
__global__ __launch_bounds__(256)
void k0t(const float* __restrict__ src, int which, int S)
{
    __shared__ float ts[64][65];
    __half* dst = which ? g_l16 : g_h16;
    const int tid = threadIdx.x;
    const int s0 = blockIdx.x * 64, k0 = blockIdx.y * 64, b = blockIdx.z;
    const float* in = src + (size_t)b * 256 * S + (size_t)k0 * S + s0;
#pragma unroll
    for (int i = 0; i < 16; ++i) {
        const int idx = i * 256 + tid;
        const int kk = idx >> 6, ss = idx & 63;
        ts[ss][kk] = in[(size_t)kk * S + ss];
    }
    __syncthreads();
    unsigned* ob = (unsigned*)(dst + ((size_t)b * S + s0) * 256 + k0);
#pragma unroll
    for (int i = 0; i < 8; ++i) {
        const int idx = i * 256 + tid;
        const int ss = idx >> 5, kp = (idx & 31) * 2;
        ob[(size_t)ss * 128 + (kp >> 1)] = pack_h2(ts[ss][kp], ts[ss][kp + 1]);
    }
}

// ===========================================================================
// K0w: pack weights fp16 [row][256]
// rows: 0-255 W1a | 256-511 Wf | 512-767 W1b | 768-839 W2(tap*8+o) | 840-847 0
// ===========================================================================
__global__ __launch_bounds__(256)
void k0w(const float* __restrict__ W1, const float* __restrict__ Wf,
         const float* __restrict__ W2)
{
    const int row = blockIdx.x, c = threadIdx.x;
    float v = 0.f;
    if (row < 256)      v = W1[(size_t)row * 512 + c];
    else if (row < 512) v = Wf[(size_t)(row - 256) * 256 + c];
    else if (row < 768) v = W1[(size_t)(row - 512) * 512 + 256 + c];
    else if (row < 840) {
        const int t = (row - 768) >> 3, o = (row - 768) & 7;
        v = W2[(size_t)o * 2304 + c * 9 + t];
    }
    g_wh[(size_t)row * 256 + c] = __float2half(v);
}

// ===========================================================================
// shared GEMM helper: cp.async one 64-k A chunk (128 rows x 128 bytes)
// ===========================================================================
__device__ __forceinline__ void load_A_chunk(unsigned bufA, const __half* A16,
                                             int kt, int tid)
{
    const int row = tid >> 1, c4 = (tid & 1) * 4;
#pragma unroll
    for (int j = 0; j < 4; ++j) {
        const int c = c4 + j;
        cpa16(bufA + sw128(row * 128 + c * 16), A16 + (size_t)row * 256 + kt * 64 + c * 8);
    }
}

// ===========================================================================
// K1f: [t | proc] = [W1a | Wf] @ high ; grid (256, 4): y = ny*2 + nhalf
// smem: A0 @0, A1 @16384, B (4 chunks of 16K) @32768
// ===========================================================================
__global__ __launch_bounds__(256, 2)
void k1f(const float* __restrict__ bf)
{
    extern __shared__ char dsm[];
    const unsigned sb = smem_u32(dsm), sbB = sb + 32768;
    const int tid = threadIdx.x, lane = tid & 31, warp = tid >> 5;
    const int wm = warp & 1, wn = warp >> 1;
    const int m0 = blockIdx.x * 128;
    const int ny = blockIdx.y >> 1, nhalf = blockIdx.y & 1;
    const int bb = m0 >> 12, s0 = m0 & 4095;
    const int brow0 = ny * 256 + nhalf * 128;

    const __half* A16 = g_h16 + ((size_t)bb * HWLO + s0) * 256;

    unsigned aoff[4], boff[2];
#pragma unroll
    for (int mt = 0; mt < 4; ++mt)
        aoff[mt] = ((unsigned)(wm * 64 + mt * 16 + (lane & 15)) << 7) + (lane >> 4) * 16;
#pragma unroll
    for (int p = 0; p < 2; ++p)
        boff[p] = ((unsigned)(wn * 32 + p * 16 + (lane & 7) + ((lane >> 4) & 1) * 8) << 7)
                  + ((lane >> 3) & 1) * 16;

    float d[4][4][4];
#pragma unroll
    for (int i = 0; i < 4; ++i)
#pragma unroll
        for (int j = 0; j < 4; ++j)
#pragma unroll
            for (int e = 0; e < 4; ++e) d[i][j][e] = 0.f;

    // group 1: B full-K + A chunk 0 ; group 2: A chunk 1
#pragma unroll
    for (int i = 0; i < 16; ++i) {
        const int idx = i * 256 + tid;
        const int n = idx >> 5, c = idx & 31;
        cpa16(sbB + (c >> 3) * 16384 + sw128(n * 128 + (c & 7) * 16),
              g_wh + (size_t)(brow0 + n) * 256 + c * 8);
    }
    load_A_chunk(sb, A16, 0, tid);
    CP_COMMIT();
    load_A_chunk(sb + 16384, A16, 1, tid);
    CP_COMMIT();

    for (int kt = 0; kt < 4; ++kt) {
        if (kt < 3) cp_wait<1>(); else cp_wait<0>();
        __syncthreads();
        const unsigned bufA = sb + (kt & 1) * 16384;
        const unsigned bufB = sbB + kt * 16384;
#pragma unroll
        for (int ks = 0; ks < 4; ++ks) {
            const unsigned ksb = ks * 32;
            unsigned a[4][4], b[4][2];
#pragma unroll
            for (int mt = 0; mt < 4; ++mt)
                LDSM_X4(a[mt][0], a[mt][1], a[mt][2], a[mt][3], bufA + sw128(aoff[mt] + ksb));
            LDSM_X4(b[0][0], b[0][1], b[1][0], b[1][1], bufB + sw128(boff[0] + ksb));
            LDSM_X4(b[2][0], b[2][1], b[3][0], b[3][1], bufB + sw128(boff[1] + ksb));
#pragma unroll
            for (int mt = 0; mt < 4; ++mt)
#pragma unroll
                for (int nt = 0; nt < 4; ++nt)
                    MMA_F16(d[mt][nt], a[mt], b[nt]);
        }
        __syncthreads();
        if (kt < 2) { load_A_chunk(sb + (kt & 1) * 16384, A16, kt + 2, tid); CP_COMMIT(); }
    }

#pragma unroll
    for (int mt = 0; mt < 4; ++mt) {
        const int row = m0 + wm * 64 + mt * 16 + (lane >> 2);
#pragma unroll
        for (int nt = 0; nt < 4; ++nt) {
            const int col = nhalf * 128 + wn * 32 + nt * 8 + (lane & 3) * 2;
            if (ny == 0) {
                *(float2*)&g_t[(size_t)row * 256 + col] = make_float2(d[mt][nt][0], d[mt][nt][1]);
                *(float2*)&g_t[(size_t)(row + 8) * 256 + col] = make_float2(d[mt][nt][2], d[mt][nt][3]);
            } else {
                const float b0 = bf[col], b1 = bf[col + 1];
                *(unsigned*)&g_proc16[(size_t)row * 256 + col] =
                    pack_h2(d[mt][nt][0] + b0, d[mt][nt][1] + b1);
                *(unsigned*)&g_proc16[(size_t)(row + 8) * 256 + col] =
                    pack_h2(d[mt][nt][2] + b0, d[mt][nt][3] + b1);
            }
        }
    }
}

// ===========================================================================
// K2f: off_feat = relu(W1b@low + up2x(t) + b1) -> fp16 ; grid (1024, 2)
// ===========================================================================
__global__ __launch_bounds__(256, 2)
void k2f(const float* __restrict__ b1)
{
    extern __shared__ char dsm[];
    const unsigned sb = smem_u32(dsm), sbB = sb + 32768;
    float (*stage)[132] = (float(*)[132])dsm;

    const int tid = threadIdx.x, lane = tid & 31, warp = tid >> 5;
    const int wm = warp & 1, wn = warp >> 1;
    const int m0 = blockIdx.x * 128;
    const int n0 = blockIdx.y * 128;
    const int bb = m0 >> 14, s0 = m0 & 16383;
    const int brow0 = 512 + n0;

    const __half* A16 = g_l16 + ((size_t)bb * HWHI + s0) * 256;

    unsigned aoff[4], boff[2];
#pragma unroll
    for (int mt = 0; mt < 4; ++mt)
        aoff[mt] = ((unsigned)(wm * 64 + mt * 16 + (lane & 15)) << 7) + (lane >> 4) * 16;
#pragma unroll
    for (int p = 0; p < 2; ++p)
        boff[p] = ((unsigned)(wn * 32 + p * 16 + (lane & 7) + ((lane >> 4) & 1) * 8) << 7)
                  + ((lane >> 3) & 1) * 16;

    float d[4][4][4];
#pragma unroll
    for (int i = 0; i < 4; ++i)
#pragma unroll
        for (int j = 0; j < 4; ++j)
#pragma unroll
            for (int e = 0; e < 4; ++e) d[i][j][e] = 0.f;

#pragma unroll
    for (int i = 0; i < 16; ++i) {
        const int idx = i * 256 + tid;
        const int n = idx >> 5, c = idx & 31;
        cpa16(sbB + (c >> 3) * 16384 + sw128(n * 128 + (c & 7) * 16),
              g_wh + (size_t)(brow0 + n) * 256 + c * 8);
    }
    load_A_chunk(sb, A16, 0, tid);
    CP_COMMIT();
    load_A_chunk(sb + 16384, A16, 1, tid);
    CP_COMMIT();

    for (int kt = 0; kt < 4; ++kt) {
        if (kt < 3) cp_wait<1>(); else cp_wait<0>();
        __syncthreads();
        const unsigned bufA = sb + (kt & 1) * 16384;
        const unsigned bufB = sbB + kt * 16384;
#pragma unroll
        for (int ks = 0; ks < 4; ++ks) {
            const unsigned ksb = ks * 32;
            unsigned a[4][4], b[4][2];
#pragma unroll
            for (int mt = 0; mt < 4; ++mt)
                LDSM_X4(a[mt][0], a[mt][1], a[mt][2], a[mt][3], bufA + sw128(aoff[mt] + ksb));
            LDSM_X4(b[0][0], b[0][1], b[1][0], b[1][1], bufB + sw128(boff[0] + ksb));
            LDSM_X4(b[2][0], b[2][1], b[3][0], b[3][1], bufB + sw128(boff[1] + ksb));
#pragma unroll
            for (int mt = 0; mt < 4; ++mt)
#pragma unroll
                for (int nt = 0; nt < 4; ++nt)
                    MMA_F16(d[mt][nt], a[mt], b[nt]);
        }
        __syncthreads();
        if (kt < 2) { load_A_chunk(sb + (kt & 1) * 16384, A16, kt + 2, tid); CP_COMMIT(); }
    }

    // stage aliases the A buffers -> MUST sync before overwriting
    __syncthreads();
#pragma unroll
    for (int mt = 0; mt < 4; ++mt) {
        const int sr = wm * 64 + mt * 16 + (lane >> 2);
#pragma unroll
        for (int nt = 0; nt < 4; ++nt) {
            const int sc = wn * 32 + nt * 8 + (lane & 3) * 2;
            *(float2*)&stage[sr][sc]     = make_float2(d[mt][nt][0], d[mt][nt][1]);
            *(float2*)&stage[sr + 8][sc] = make_float2(d[mt][nt][2], d[mt][nt][3]);
        }
    }
    __syncthreads();

    const int p = tid >> 1, chh = tid & 1;
    const int m = m0 + p;
    const int s = m & 16383, yy = s >> 7, xx = s & 127;
    const int th = yy >> 1, tw = xx >> 1;
    int jy0, jy1, jx0, jx1;
    float wy0, wy1, wx0, wx1;
    if (yy & 1) { jy0 = th; jy1 = (th + 1 > 63) ? 63 : th + 1; wy0 = 0.75f; wy1 = 0.25f; }
    else        { jy0 = (th - 1 < 0) ? 0 : th - 1; jy1 = th;   wy0 = 0.25f; wy1 = 0.75f; }
    if (xx & 1) { jx0 = tw; jx1 = (tw + 1 > 63) ? 63 : tw + 1; wx0 = 0.75f; wx1 = 0.25f; }
    else        { jx0 = (tw - 1 < 0) ? 0 : tw - 1; jx1 = tw;   wx0 = 0.25f; wx1 = 0.75f; }
    const float wa = wy0 * wx0, wb_ = wy0 * wx1, wc = wy1 * wx0, wd = wy1 * wx1;
    const float* tb = g_t + (size_t)bb * HWLO * 256;
    const float* p00 = tb + (size_t)(jy0 * 64 + jx0) * 256 + n0;
    const float* p01 = tb + (size_t)(jy0 * 64 + jx1) * 256 + n0;
    const float* p10 = tb + (size_t)(jy1 * 64 + jx0) * 256 + n0;
    const float* p11 = tb + (size_t)(jy1 * 64 + jx1) * 256 + n0;
    __half* ob = g_off16 + (size_t)m * 256 + n0;

#pragma unroll
    for (int g = 0; g < 16; ++g) {
        const int c = chh * 64 + g * 4;
        float4 av  = *(const float4*)&stage[p][c];
        float4 bv  = *(const float4*)&b1[n0 + c];
        float4 u00 = *(const float4*)&p00[c];
        float4 u01 = *(const float4*)&p01[c];
        float4 u10 = *(const float4*)&p10[c];
        float4 u11 = *(const float4*)&p11[c];
        float o0 = fmaxf(av.x + bv.x + wa*u00.x + wb_*u01.x + wc*u10.x + wd*u11.x, 0.f);
        float o1 = fmaxf(av.y + bv.y + wa*u00.y + wb_*u01.y + wc*u10.y + wd*u11.y, 0.f);
        float o2 = fmaxf(av.z + bv.z + wa*u00.z + wb_*u01.z + wc*u10.z + wd*u11.z, 0.f);
        float o3 = fmaxf(av.w + bv.w + wa*u00.w + wb_*u01.w + wc*u10.w + wd*u11.w, 0.f);
        *(uint2*)&ob[c] = make_uint2(pack_h2(o0, o1), pack_h2(o2, o3));
    }
}

// ===========================================================================
// K5f: q = off_feat @ W2taps (N=72 pad 80) ; B rows 768..847 of g_wh
// smem: A0 @0, A1 @16384, B (4 x 10240) @32768
// ===========================================================================
__global__ __launch_bounds__(256, 2)
void k5f()
{
    extern __shared__ char dsm[];
    const unsigned sb = smem_u32(dsm), sbB = sb + 32768;
    const int tid = threadIdx.x, lane = tid & 31, warp = tid >> 5;
    const int wm = warp >> 1, wn = warp & 1;
    const int m0 = blockIdx.x * 128;

    const __half* A16 = g_off16 + (size_t)m0 * 256;

    unsigned aoff[2], boffp[2], boffs;
#pragma unroll
    for (int mt = 0; mt < 2; ++mt)
        aoff[mt] = ((unsigned)(wm * 32 + mt * 16 + (lane & 15)) << 7) + (lane >> 4) * 16;
#pragma unroll
    for (int p = 0; p < 2; ++p)
        boffp[p] = ((unsigned)(wn * 40 + p * 16 + (lane & 7) + ((lane >> 4) & 1) * 8) << 7)
                   + ((lane >> 3) & 1) * 16;
    boffs = ((unsigned)(wn * 40 + 32 + (lane & 7)) << 7) + ((lane >> 3) & 1) * 16;

    float d[2][5][4];
#pragma unroll
    for (int i = 0; i < 2; ++i)
#pragma unroll
        for (int j = 0; j < 5; ++j)
#pragma unroll
            for (int e = 0; e < 4; ++e) d[i][j][e] = 0.f;

#pragma unroll
    for (int i = 0; i < 10; ++i) {
        const int idx = i * 256 + tid;
        const int n = idx >> 5, c = idx & 31;
        cpa16(sbB + (c >> 3) * 10240 + sw128(n * 128 + (c & 7) * 16),
              g_wh + (size_t)(768 + n) * 256 + c * 8);
    }
    load_A_chunk(sb, A16, 0, tid);
    CP_COMMIT();
    load_A_chunk(sb + 16384, A16, 1, tid);
    CP_COMMIT();

    for (int kt = 0; kt < 4; ++kt) {
        if (kt < 3) cp_wait<1>(); else cp_wait<0>();
        __syncthreads();
        const unsigned bufA = sb + (kt & 1) * 16384;
        const unsigned bufB = sbB + kt * 10240;
#pragma unroll
        for (int ks = 0; ks < 4; ++ks) {
            const unsigned ksb = ks * 32;
            unsigned a[2][4], b[5][2];
#pragma unroll
            for (int mt = 0; mt < 2; ++mt)
                LDSM_X4(a[mt][0], a[mt][1], a[mt][2], a[mt][3], bufA + sw128(aoff[mt] + ksb));
            LDSM_X4(b[0][0], b[0][1], b[1][0], b[1][1], bufB + sw128(boffp[0] + ksb));
            LDSM_X4(b[2][0], b[2][1], b[3][0], b[3][1], bufB + sw128(boffp[1] + ksb));
            LDSM_X2(b[4][0], b[4][1], bufB + sw128(boffs + ksb));
#pragma unroll
            for (int mt = 0; mt < 2; ++mt)
#pragma unroll
                for (int nt = 0; nt < 5; ++nt)
                    MMA_F16(d[mt][nt], a[mt], b[nt]);
        }
        __syncthreads();
        if (kt < 2) { load_A_chunk(sb + (kt & 1) * 16384, A16, kt + 2, tid); CP_COMMIT(); }
    }

#pragma unroll
    for (int mt = 0; mt < 2; ++mt) {
        const int row = m0 + wm * 32 + mt * 16 + (lane >> 2);
#pragma unroll
        for (int nt = 0; nt < 5; ++nt) {
            const int col = wn * 40 + nt * 8 + (lane & 3) * 2;
            if (col < 72) {
                *(float2*)&g_q[(size_t)row * 72 + col] = make_float2(d[mt][nt][0], d[mt][nt][1]);
                *(float2*)&g_q[(size_t)(row + 8) * 72 + col] = make_float2(d[mt][nt][2], d[mt][nt][3]);
            }
        }
    }
}

// ===========================================================================
// K6: offsets[p][o] = b2[o] + sum 9-tap shift of q
// ===========================================================================
__global__ __launch_bounds__(256)
void k6_stencil(const float* __restrict__ b2)
{
    const int p = blockIdx.x * 256 + threadIdx.x;
    const int bb = p >> 14, s = p & 16383, y = s >> 7, x = s & 127;
    float4 a0 = *(const float4*)&b2[0];
    float4 a1 = *(const float4*)&b2[4];
    const float* qb = g_q + (size_t)bb * HWHI * 72;
#pragma unroll
    for (int dy = 0; dy < 3; ++dy) {
        const int yy = y + dy - 1;
        if (yy < 0 || yy > 127) continue;
#pragma unroll
        for (int dx = 0; dx < 3; ++dx) {
            const int xx = x + dx - 1;
            if (xx < 0 || xx > 127) continue;
            const float* qq = qb + (size_t)(yy * 128 + xx) * 72 + (dy * 3 + dx) * 8;
            float4 v0 = *(const float4*)qq;
            float4 v1 = *(const float4*)(qq + 4);
            a0.x += v0.x; a0.y += v0.y; a0.z += v0.z; a0.w += v0.w;
            a1.x += v1.x; a1.y += v1.y; a1.z += v1.z; a1.w += v1.w;
        }
    }
    *(float4*)&g_offsets[(size_t)p * 8] = a0;
    *(float4*)&g_offsets[(size_t)p * 8 + 4] = a1;
}

// ===========================================================================
// K4: deformable 4-point bilinear sample of fp16 proc + average
// ===========================================================================
__global__ __launch_bounds__(256)
void k4_sample(float* __restrict__ out)
{
    __shared__ int   sh_idx[32][16];
    __shared__ float sh_w[32][16];
    __shared__ float sh_t[32][132];

    const int tid = threadIdx.x;
    const int bx = blockIdx.x;
    const int xt = bx >> 1;
    const int ch = bx & 1;
    const int y  = blockIdx.y;
    const int bb = blockIdx.z;
    const int x0 = xt * 32;

    if (tid < 128) {
        const int px = tid >> 2, p = tid & 3;
        const int x = x0 + px;
        const size_t pi = ((size_t)bb * HWHI + y * 128 + x) * 8;
        const float ox = g_offsets[pi + 2 * p]     * (1.0f / 64.0f);
        const float oy = g_offsets[pi + 2 * p + 1] * (1.0f / 64.0f);
        const float gx = fmaf((float)x, 2.0f / 127.0f, -1.0f) + ox;
        const float gy = fmaf((float)y, 2.0f / 127.0f, -1.0f) + oy;
        const float gxp = fminf(fmaxf(fmaf(gx, 32.0f, 31.5f), 0.0f), 63.0f);
        const float gyp = fminf(fmaxf(fmaf(gy, 32.0f, 31.5f), 0.0f), 63.0f);
        const float fx0 = floorf(gxp), fy0 = floorf(gyp);
        const int ix0 = (int)fx0, iy0 = (int)fy0;
        const float fx = gxp - fx0, fy = gyp - fy0;
        const int ix1 = (ix0 + 1 > 63) ? 63 : ix0 + 1;
        const int iy1 = (iy0 + 1 > 63) ? 63 : iy0 + 1;
        const int q = p * 4;
        // offsets in half2 units (pixel stride = 128 half2)
        sh_idx[px][q + 0] = (iy0 * 64 + ix0) * 128;
        sh_idx[px][q + 1] = (iy0 * 64 + ix1) * 128;
        sh_idx[px][q + 2] = (iy1 * 64 + ix0) * 128;
        sh_idx[px][q + 3] = (iy1 * 64 + ix1) * 128;
        sh_w[px][q + 0] = (1.f - fx) * (1.f - fy) * 0.25f;
        sh_w[px][q + 1] = fx * (1.f - fy) * 0.25f;
        sh_w[px][q + 2] = (1.f - fx) * fy * 0.25f;
        sh_w[px][q + 3] = fx * fy * 0.25f;
    }
    __syncthreads();

    const int lane = tid & 31, wrp = tid >> 5;
    const __half2* pb = (const __half2*)(g_proc16 + (size_t)bb * HWLO * 256 + ch * 128 + 4 * lane);

#pragma unroll
    for (int r = 0; r < 4; ++r) {
        const int px = wrp * 4 + r;
        float4 acc = make_float4(0.f, 0.f, 0.f, 0.f);
#pragma unroll
        for (int t = 0; t < 16; ++t) {
            const float wt = sh_w[px][t];
            const __half2* vp = pb + sh_idx[px][t];
            float2 f0 = __half22float2(vp[0]);
            float2 f1 = __half22float2(vp[1]);
            acc.x = fmaf(wt, f0.x, acc.x);
            acc.y = fmaf(wt, f0.y, acc.y);
            acc.z = fmaf(wt, f1.x, acc.z);
            acc.w = fmaf(wt, f1.y, acc.w);
        }
        *(float4*)&sh_t[px][4 * lane] = acc;
    }
    __syncthreads();

    const int xl = tid & 31;
    const int c0 = tid >> 5;
#pragma unroll
    for (int i = 0; i < 16; ++i) {
        const int c = c0 * 16 + i;
        out[((size_t)bb * 256 + ch * 128 + c) * HWHI + y * 128 + x0 + xl] = sh_t[xl][c];
    }
}

// ===========================================================================
extern "C" void kernel_launch(void* const* d_in, const int* in_sizes, int n_in,
                              void* d_out, int out_size)
{
    const float* high = (const float*)d_in[0];
    const float* low  = (const float*)d_in[1];
    const float* W1   = (const float*)d_in[2];
    const float* b1   = (const float*)d_in[3];
    const float* W2   = (const float*)d_in[4];
    const float* b2   = (const float*)d_in[5];
    const float* Wf   = (const float*)d_in[6];
    const float* bf   = (const float*)d_in[7];
    float* out = (float*)d_out;

    const int SM_G  = 98304;   // 2x16K A + 64K B (k1f/k2f)
    const int SM_K5 = 73728;   // 2x16K A + 4x10240 B
    static int inited = 0;
    if (!inited) {
        cudaFuncSetAttribute(k1f, cudaFuncAttributeMaxDynamicSharedMemorySize, SM_G);
        cudaFuncSetAttribute(k2f, cudaFuncAttributeMaxDynamicSharedMemorySize, SM_G);
        cudaFuncSetAttribute(k5f, cudaFuncAttributeMaxDynamicSharedMemorySize, SM_K5);
        inited = 1;
    }

    k0t<<<dim3(64, 4, 8), 256>>>(high, 0, HWLO);
    k0t<<<dim3(256, 4, 8), 256>>>(low, 1, HWHI);
    k0w<<<848, 256>>>(W1, Wf, W2);
    k1f<<<dim3(256, 4), 256, SM_G>>>(bf);
    k2f<<<dim3(1024, 2), 256, SM_G>>>(b1);
    k5f<<<1024, 256, SM_K5>>>();
    k6_stencil<<<512, 256>>>(b2);
    k4_sample<<<dim3(8, 128, 8), 256>>>(out);
}

// round 7
// speedup vs baseline: 2.5429x; 1.0814x over previous
#include <cuda_runtime.h>
#include <cuda_fp16.h>

// ---------------------------------------------------------------------------
// AdaUp, fp16 mma.sync + cp.async pipelines.
//   K0t: f32 NCHW -> fp16 NHWC transpose (high, low)   [dst chosen in-device]
//   K0w: weights -> packed fp16 [n][k] table (W1a | Wf | W1b | W2taps | pad)
//   K1f: t = W1a@high (fp16 out) ; proc = Wf@high + bf (fp16 out)
//   K2f: off_feat = relu(W1b@low + up2x(t) + b1)  (fp16 out)
//   K5f: q[p][tap*8+o] = W2tap @ off_feat(p)      (f32 out, N=72 pad 80)
//   K6 : offsets = b2 + 9-tap shift-sum of q
//   K4 : 4-point deformable bilinear sampling of fp16 proc, averaged
// ---------------------------------------------------------------------------

#define NB    8
#define HWLO  4096
#define HWHI  16384

__device__ __half g_h16[(size_t)NB * HWLO * 256];    // high, NHWC fp16
__device__ __half g_l16[(size_t)NB * HWHI * 256];    // low, NHWC fp16
__device__ __half g_wh[1024 * 256];                  // packed weights fp16
__device__ __half g_t16[(size_t)NB * HWLO * 256];    // W1a@high (fp16)
__device__ __half g_proc16[(size_t)NB * HWLO * 256]; // Wf@high + bf (fp16)
__device__ __half g_off16[(size_t)NB * HWHI * 256];  // relu(...) (fp16)
__device__ float  g_q[(size_t)NB * HWHI * 72];
__device__ float  g_offsets[(size_t)NB * HWHI * 8];

__device__ __forceinline__ unsigned smem_u32(const void* p) {
    unsigned a;
    asm("{ .reg .u64 t; cvta.to.shared.u64 t, %1; cvt.u32.u64 %0, t; }" : "=r"(a) : "l"(p));
    return a;
}
__device__ __forceinline__ unsigned sw128(unsigned o) { return o ^ ((o >> 3) & 0x70); }
__device__ __forceinline__ unsigned pack_h2(float lo, float hi) {
    unsigned u;
    asm("cvt.rn.f16x2.f32 %0, %1, %2;" : "=r"(u) : "f"(hi), "f"(lo));
    return u;
}
__device__ __forceinline__ void cpa16(unsigned dst, const void* src) {
    asm volatile("cp.async.cg.shared.global [%0], [%1], 16;" :: "r"(dst), "l"(src));
}
#define CP_COMMIT() asm volatile("cp.async.commit_group;" ::: "memory")
template <int N> __device__ __forceinline__ void cp_wait() {
    asm volatile("cp.async.wait_group %0;" :: "n"(N) : "memory");
}

#define LDSM_X4(r0, r1, r2, r3, addr) \
    asm volatile("ldmatrix.sync.aligned.m8n8.x4.shared.b16 {%0,%1,%2,%3}, [%4];" \
                 : "=r"(r0), "=r"(r1), "=r"(r2), "=r"(r3) : "r"(addr))
#define LDSM_X2(r0, r1, addr) \
    asm volatile("ldmatrix.sync.aligned.m8n8.x2.shared.b16 {%0,%1}, [%2];" \
                 : "=r"(r0), "=r"(r1) : "r"(addr))
#define MMA_F16(d, a, b) \
    asm volatile("mma.sync.aligned.m16n8k16.row.col.f32.f16.f16.f32 " \
                 "{%0,%1,%2,%3}, {%4,%5,%6,%7}, {%8,%9}, {%0,%1,%2,%3};" \
                 : "+f"((d)[0]), "+f"((d)[1]), "+f"((d)[2]), "+f"((d)[3]) \
                 : "r"((a)[0]), "r"((a)[1]), "r"((a)[2]), "r"((a)[3]), \
                   "r"((b)[0]), "r"((b)[1]))

__device__ __forceinline__ float2 h2f(unsigned u) {
    return __half22float2(*(const __half2*)&u);
}

// ===========================================================================
// K0t: [b][k][s] f32 -> [b][s][k] fp16 ; tile 64s x 64k, K=256
// which: 0 -> g_h16 (S=4096), 1 -> g_l16 (S=16384)
// ===========================================================================
__global__ __launch_bounds__(256)
void k0t(const float* __restrict__ src, int which, int S)
{
    __shared__ float ts[64][65];
    __half* dst = which ? g_l16 : g_h16;
    const int tid = threadIdx.x;
    const int s0 = blockIdx.x * 64, k0 = blockIdx.y * 64, b = blockIdx.z;
    const float* in = src + (size_t)b * 256 * S + (size_t)k0 * S + s0;
#pragma unroll
    for (int i = 0; i < 16; ++i) {
        const int idx = i * 256 + tid;
        const int kk = idx >> 6, ss = idx & 63;
        ts[ss][kk] = in[(size_t)kk * S + ss];
    }
    __syncthreads();
    unsigned* ob = (unsigned*)(dst + ((size_t)b * S + s0) * 256 + k0);
#pragma unroll
    for (int i = 0; i < 8; ++i) {
        const int idx = i * 256 + tid;
        const int ss = idx >> 5, kp = (idx & 31) * 2;
        ob[(size_t)ss * 128 + (kp >> 1)] = pack_h2(ts[ss][kp], ts[ss][kp + 1]);
    }
}

// ===========================================================================
// K0w: pack weights fp16 [row][256]
// rows: 0-255 W1a | 256-511 Wf | 512-767 W1b | 768-839 W2(tap*8+o) | 840-847 0
// ===========================================================================
__global__ __launch_bounds__(256)
void k0w(const float* __restrict__ W1, const float* __restrict__ Wf,
         const float* __restrict__ W2)
{
    const int row = blockIdx.x, c = threadIdx.x;
    float v = 0.f;
    if (row < 256)      v = W1[(size_t)row * 512 + c];
    else if (row < 512) v = Wf[(size_t)(row - 256) * 256 + c];
    else if (row < 768) v = W1[(size_t)(row - 512) * 512 + 256 + c];
    else if (row < 840) {
        const int t = (row - 768) >> 3, o = (row - 768) & 7;
        v = W2[(size_t)o * 2304 + c * 9 + t];
    }
    g_wh[(size_t)row * 256 + c] = __float2half(v);
}

// ===========================================================================
// cp.async one 64-k A chunk (128 rows x 128 bytes)
// ===========================================================================
__device__ __forceinline__ void load_A_chunk(unsigned bufA, const __half* A16,
                                             int kt, int tid)
{
    const int row = tid >> 1, c4 = (tid & 1) * 4;
#pragma unroll
    for (int j = 0; j < 4; ++j) {
        const int c = c4 + j;
        cpa16(bufA + sw128(row * 128 + c * 16), A16 + (size_t)row * 256 + kt * 64 + c * 8);
    }
}

// ===========================================================================
// K1f: [t | proc] = [W1a | Wf] @ high ; grid (256, 4): y = ny*2 + nhalf
// smem: A0 @0, A1 @16384, B (4 chunks of 16K) @32768
// ===========================================================================
__global__ __launch_bounds__(256, 2)
void k1f(const float* __restrict__ bf)
{
    extern __shared__ char dsm[];
    const unsigned sb = smem_u32(dsm), sbB = sb + 32768;
    const int tid = threadIdx.x, lane = tid & 31, warp = tid >> 5;
    const int wm = warp & 1, wn = warp >> 1;
    const int m0 = blockIdx.x * 128;
    const int ny = blockIdx.y >> 1, nhalf = blockIdx.y & 1;
    const int bb = m0 >> 12, s0 = m0 & 4095;
    const int brow0 = ny * 256 + nhalf * 128;

    const __half* A16 = g_h16 + ((size_t)bb * HWLO + s0) * 256;

    unsigned aoff[4], boff[2];
#pragma unroll
    for (int mt = 0; mt < 4; ++mt)
        aoff[mt] = ((unsigned)(wm * 64 + mt * 16 + (lane & 15)) << 7) + (lane >> 4) * 16;
#pragma unroll
    for (int p = 0; p < 2; ++p)
        boff[p] = ((unsigned)(wn * 32 + p * 16 + (lane & 7) + ((lane >> 4) & 1) * 8) << 7)
                  + ((lane >> 3) & 1) * 16;

    float d[4][4][4];
#pragma unroll
    for (int i = 0; i < 4; ++i)
#pragma unroll
        for (int j = 0; j < 4; ++j)
#pragma unroll
            for (int e = 0; e < 4; ++e) d[i][j][e] = 0.f;

#pragma unroll
    for (int i = 0; i < 16; ++i) {
        const int idx = i * 256 + tid;
        const int n = idx >> 5, c = idx & 31;
        cpa16(sbB + (c >> 3) * 16384 + sw128(n * 128 + (c & 7) * 16),
              g_wh + (size_t)(brow0 + n) * 256 + c * 8);
    }
    load_A_chunk(sb, A16, 0, tid);
    CP_COMMIT();
    load_A_chunk(sb + 16384, A16, 1, tid);
    CP_COMMIT();

    for (int kt = 0; kt < 4; ++kt) {
        if (kt < 3) cp_wait<1>(); else cp_wait<0>();
        __syncthreads();
        const unsigned bufA = sb + (kt & 1) * 16384;
        const unsigned bufB = sbB + kt * 16384;
#pragma unroll
        for (int ks = 0; ks < 4; ++ks) {
            const unsigned ksb = ks * 32;
            unsigned a[4][4], b[4][2];
#pragma unroll
            for (int mt = 0; mt < 4; ++mt)
                LDSM_X4(a[mt][0], a[mt][1], a[mt][2], a[mt][3], bufA + sw128(aoff[mt] + ksb));
            LDSM_X4(b[0][0], b[0][1], b[1][0], b[1][1], bufB + sw128(boff[0] + ksb));
            LDSM_X4(b[2][0], b[2][1], b[3][0], b[3][1], bufB + sw128(boff[1] + ksb));
#pragma unroll
            for (int mt = 0; mt < 4; ++mt)
#pragma unroll
                for (int nt = 0; nt < 4; ++nt)
                    MMA_F16(d[mt][nt], a[mt], b[nt]);
        }
        __syncthreads();
        if (kt < 2) { load_A_chunk(sb + (kt & 1) * 16384, A16, kt + 2, tid); CP_COMMIT(); }
    }

#pragma unroll
    for (int mt = 0; mt < 4; ++mt) {
        const int row = m0 + wm * 64 + mt * 16 + (lane >> 2);
#pragma unroll
        for (int nt = 0; nt < 4; ++nt) {
            const int col = nhalf * 128 + wn * 32 + nt * 8 + (lane & 3) * 2;
            if (ny == 0) {
                *(unsigned*)&g_t16[(size_t)row * 256 + col] =
                    pack_h2(d[mt][nt][0], d[mt][nt][1]);
                *(unsigned*)&g_t16[(size_t)(row + 8) * 256 + col] =
                    pack_h2(d[mt][nt][2], d[mt][nt][3]);
            } else {
                const float b0 = bf[col], b1 = bf[col + 1];
                *(unsigned*)&g_proc16[(size_t)row * 256 + col] =
                    pack_h2(d[mt][nt][0] + b0, d[mt][nt][1] + b1);
                *(unsigned*)&g_proc16[(size_t)(row + 8) * 256 + col] =
                    pack_h2(d[mt][nt][2] + b0, d[mt][nt][3] + b1);
            }
        }
    }
}

// ===========================================================================
// K2f: off_feat = relu(W1b@low + up2x(t) + b1) -> fp16 ; grid (1024, 2)
// ===========================================================================
__global__ __launch_bounds__(256, 2)
void k2f(const float* __restrict__ b1)
{
    extern __shared__ char dsm[];
    const unsigned sb = smem_u32(dsm), sbB = sb + 32768;
    float (*stage)[132] = (float(*)[132])dsm;

    const int tid = threadIdx.x, lane = tid & 31, warp = tid >> 5;
    const int wm = warp & 1, wn = warp >> 1;
    const int m0 = blockIdx.x * 128;
    const int n0 = blockIdx.y * 128;
    const int bb = m0 >> 14, s0 = m0 & 16383;
    const int brow0 = 512 + n0;

    const __half* A16 = g_l16 + ((size_t)bb * HWHI + s0) * 256;

    unsigned aoff[4], boff[2];
#pragma unroll
    for (int mt = 0; mt < 4; ++mt)
        aoff[mt] = ((unsigned)(wm * 64 + mt * 16 + (lane & 15)) << 7) + (lane >> 4) * 16;
#pragma unroll
    for (int p = 0; p < 2; ++p)
        boff[p] = ((unsigned)(wn * 32 + p * 16 + (lane & 7) + ((lane >> 4) & 1) * 8) << 7)
                  + ((lane >> 3) & 1) * 16;

    float d[4][4][4];
#pragma unroll
    for (int i = 0; i < 4; ++i)
#pragma unroll
        for (int j = 0; j < 4; ++j)
#pragma unroll
            for (int e = 0; e < 4; ++e) d[i][j][e] = 0.f;

#pragma unroll
    for (int i = 0; i < 16; ++i) {
        const int idx = i * 256 + tid;
        const int n = idx >> 5, c = idx & 31;
        cpa16(sbB + (c >> 3) * 16384 + sw128(n * 128 + (c & 7) * 16),
              g_wh + (size_t)(brow0 + n) * 256 + c * 8);
    }
    load_A_chunk(sb, A16, 0, tid);
    CP_COMMIT();
    load_A_chunk(sb + 16384, A16, 1, tid);
    CP_COMMIT();

    for (int kt = 0; kt < 4; ++kt) {
        if (kt < 3) cp_wait<1>(); else cp_wait<0>();
        __syncthreads();
        const unsigned bufA = sb + (kt & 1) * 16384;
        const unsigned bufB = sbB + kt * 16384;
#pragma unroll
        for (int ks = 0; ks < 4; ++ks) {
            const unsigned ksb = ks * 32;
            unsigned a[4][4], b[4][2];
#pragma unroll
            for (int mt = 0; mt < 4; ++mt)
                LDSM_X4(a[mt][0], a[mt][1], a[mt][2], a[mt][3], bufA + sw128(aoff[mt] + ksb));
            LDSM_X4(b[0][0], b[0][1], b[1][0], b[1][1], bufB + sw128(boff[0] + ksb));
            LDSM_X4(b[2][0], b[2][1], b[3][0], b[3][1], bufB + sw128(boff[1] + ksb));
#pragma unroll
            for (int mt = 0; mt < 4; ++mt)
#pragma unroll
                for (int nt = 0; nt < 4; ++nt)
                    MMA_F16(d[mt][nt], a[mt], b[nt]);
        }
        __syncthreads();
        if (kt < 2) { load_A_chunk(sb + (kt & 1) * 16384, A16, kt + 2, tid); CP_COMMIT(); }
    }

    // stage aliases the A buffers -> MUST sync before overwriting
    __syncthreads();
#pragma unroll
    for (int mt = 0; mt < 4; ++mt) {
        const int sr = wm * 64 + mt * 16 + (lane >> 2);
#pragma unroll
        for (int nt = 0; nt < 4; ++nt) {
            const int sc = wn * 32 + nt * 8 + (lane & 3) * 2;
            *(float2*)&stage[sr][sc]     = make_float2(d[mt][nt][0], d[mt][nt][1]);
            *(float2*)&stage[sr + 8][sc] = make_float2(d[mt][nt][2], d[mt][nt][3]);
        }
    }
    __syncthreads();

    const int p = tid >> 1, chh = tid & 1;
    const int m = m0 + p;
    const int s = m & 16383, yy = s >> 7, xx = s & 127;
    const int th = yy >> 1, tw = xx >> 1;
    int jy0, jy1, jx0, jx1;
    float wy0, wy1, wx0, wx1;
    if (yy & 1) { jy0 = th; jy1 = (th + 1 > 63) ? 63 : th + 1; wy0 = 0.75f; wy1 = 0.25f; }
    else        { jy0 = (th - 1 < 0) ? 0 : th - 1; jy1 = th;   wy0 = 0.25f; wy1 = 0.75f; }
    if (xx & 1) { jx0 = tw; jx1 = (tw + 1 > 63) ? 63 : tw + 1; wx0 = 0.75f; wx1 = 0.25f; }
    else        { jx0 = (tw - 1 < 0) ? 0 : tw - 1; jx1 = tw;   wx0 = 0.25f; wx1 = 0.75f; }
    const float wa = wy0 * wx0, wb_ = wy0 * wx1, wc = wy1 * wx0, wd = wy1 * wx1;
    const __half* tb = g_t16 + (size_t)bb * HWLO * 256;
    const __half* p00 = tb + (size_t)(jy0 * 64 + jx0) * 256 + n0;
    const __half* p01 = tb + (size_t)(jy0 * 64 + jx1) * 256 + n0;
    const __half* p10 = tb + (size_t)(jy1 * 64 + jx0) * 256 + n0;
    const __half* p11 = tb + (size_t)(jy1 * 64 + jx1) * 256 + n0;
    __half* ob = g_off16 + (size_t)m * 256 + n0;

#pragma unroll
    for (int g = 0; g < 16; ++g) {
        const int c = chh * 64 + g * 4;
        float4 av  = *(const float4*)&stage[p][c];
        float4 bv  = *(const float4*)&b1[n0 + c];
        uint2 q00 = *(const uint2*)&p00[c];
        uint2 q01 = *(const uint2*)&p01[c];
        uint2 q10 = *(const uint2*)&p10[c];
        uint2 q11 = *(const uint2*)&p11[c];
        float2 a00 = h2f(q00.x), b00 = h2f(q00.y);
        float2 a01 = h2f(q01.x), b01 = h2f(q01.y);
        float2 a10 = h2f(q10.x), b10v = h2f(q10.y);
        float2 a11 = h2f(q11.x), b11v = h2f(q11.y);
        float o0 = fmaxf(av.x + bv.x + wa*a00.x + wb_*a01.x + wc*a10.x + wd*a11.x, 0.f);
        float o1 = fmaxf(av.y + bv.y + wa*a00.y + wb_*a01.y + wc*a10.y + wd*a11.y, 0.f);
        float o2 = fmaxf(av.z + bv.z + wa*b00.x + wb_*b01.x + wc*b10v.x + wd*b11v.x, 0.f);
        float o3 = fmaxf(av.w + bv.w + wa*b00.y + wb_*b01.y + wc*b10v.y + wd*b11v.y, 0.f);
        *(uint2*)&ob[c] = make_uint2(pack_h2(o0, o1), pack_h2(o2, o3));
    }
}

// ===========================================================================
// K5f: q = off_feat @ W2taps (N=72 pad 80) ; B rows 768..847 of g_wh
// smem: A0 @0, A1 @16384, B (4 x 10240) @32768
// ===========================================================================
__global__ __launch_bounds__(256, 2)
void k5f()
{
    extern __shared__ char dsm[];
    const unsigned sb = smem_u32(dsm), sbB = sb + 32768;
    const int tid = threadIdx.x, lane = tid & 31, warp = tid >> 5;
    const int wm = warp >> 1, wn = warp & 1;
    const int m0 = blockIdx.x * 128;

    const __half* A16 = g_off16 + (size_t)m0 * 256;

    unsigned aoff[2], boffp[2], boffs;
#pragma unroll
    for (int mt = 0; mt < 2; ++mt)
        aoff[mt] = ((unsigned)(wm * 32 + mt * 16 + (lane & 15)) << 7) + (lane >> 4) * 16;
#pragma unroll
    for (int p = 0; p < 2; ++p)
        boffp[p] = ((unsigned)(wn * 40 + p * 16 + (lane & 7) + ((lane >> 4) & 1) * 8) << 7)
                   + ((lane >> 3) & 1) * 16;
    boffs = ((unsigned)(wn * 40 + 32 + (lane & 7)) << 7) + ((lane >> 3) & 1) * 16;

    float d[2][5][4];
#pragma unroll
    for (int i = 0; i < 2; ++i)
#pragma unroll
        for (int j = 0; j < 5; ++j)
#pragma unroll
            for (int e = 0; e < 4; ++e) d[i][j][e] = 0.f;

#pragma unroll
    for (int i = 0; i < 10; ++i) {
        const int idx = i * 256 + tid;
        const int n = idx >> 5, c = idx & 31;
        cpa16(sbB + (c >> 3) * 10240 + sw128(n * 128 + (c & 7) * 16),
              g_wh + (size_t)(768 + n) * 256 + c * 8);
    }
    load_A_chunk(sb, A16, 0, tid);
    CP_COMMIT();
    load_A_chunk(sb + 16384, A16, 1, tid);
    CP_COMMIT();

    for (int kt = 0; kt < 4; ++kt) {
        if (kt < 3) cp_wait<1>(); else cp_wait<0>();
        __syncthreads();
        const unsigned bufA = sb + (kt & 1) * 16384;
        const unsigned bufB = sbB + kt * 10240;
#pragma unroll
        for (int ks = 0; ks < 4; ++ks) {
            const unsigned ksb = ks * 32;
            unsigned a[2][4], b[5][2];
#pragma unroll
            for (int mt = 0; mt < 2; ++mt)
                LDSM_X4(a[mt][0], a[mt][1], a[mt][2], a[mt][3], bufA + sw128(aoff[mt] + ksb));
            LDSM_X4(b[0][0], b[0][1], b[1][0], b[1][1], bufB + sw128(boffp[0] + ksb));
            LDSM_X4(b[2][0], b[2][1], b[3][0], b[3][1], bufB + sw128(boffp[1] + ksb));
            LDSM_X2(b[4][0], b[4][1], bufB + sw128(boffs + ksb));
#pragma unroll
            for (int mt = 0; mt < 2; ++mt)
#pragma unroll
                for (int nt = 0; nt < 5; ++nt)
                    MMA_F16(d[mt][nt], a[mt], b[nt]);
        }
        __syncthreads();
        if (kt < 2) { load_A_chunk(sb + (kt & 1) * 16384, A16, kt + 2, tid); CP_COMMIT(); }
    }

#pragma unroll
    for (int mt = 0; mt < 2; ++mt) {
        const int row = m0 + wm * 32 + mt * 16 + (lane >> 2);
#pragma unroll
        for (int nt = 0; nt < 5; ++nt) {
            const int col = wn * 40 + nt * 8 + (lane & 3) * 2;
            if (col < 72) {
                *(float2*)&g_q[(size_t)row * 72 + col] = make_float2(d[mt][nt][0], d[mt][nt][1]);
                *(float2*)&g_q[(size_t)(row + 8) * 72 + col] = make_float2(d[mt][nt][2], d[mt][nt][3]);
            }
        }
    }
}

// ===========================================================================
// K6: offsets[p][o] = b2[o] + sum 9-tap shift of q
// ===========================================================================
__global__ __launch_bounds__(256)
void k6_stencil(const float* __restrict__ b2)
{
    const int p = blockIdx.x * 256 + threadIdx.x;
    const int bb = p >> 14, s = p & 16383, y = s >> 7, x = s & 127;
    float4 a0 = *(const float4*)&b2[0];
    float4 a1 = *(const float4*)&b2[4];
    const float* qb = g_q + (size_t)bb * HWHI * 72;
#pragma unroll
    for (int dy = 0; dy < 3; ++dy) {
        const int yy = y + dy - 1;
        if (yy < 0 || yy > 127) continue;
#pragma unroll
        for (int dx = 0; dx < 3; ++dx) {
            const int xx = x + dx - 1;
            if (xx < 0 || xx > 127) continue;
            const float* qq = qb + (size_t)(yy * 128 + xx) * 72 + (dy * 3 + dx) * 8;
            float4 v0 = *(const float4*)qq;
            float4 v1 = *(const float4*)(qq + 4);
            a0.x += v0.x; a0.y += v0.y; a0.z += v0.z; a0.w += v0.w;
            a1.x += v1.x; a1.y += v1.y; a1.z += v1.z; a1.w += v1.w;
        }
    }
    *(float4*)&g_offsets[(size_t)p * 8] = a0;
    *(float4*)&g_offsets[(size_t)p * 8 + 4] = a1;
}

// ===========================================================================
// K4: deformable 4-point bilinear sample of fp16 proc + average
// ===========================================================================
__global__ __launch_bounds__(256)
void k4_sample(float* __restrict__ out)
{
    __shared__ int   sh_idx[32][16];
    __shared__ float sh_w[32][16];
    __shared__ float sh_t[32][132];

    const int tid = threadIdx.x;
    const int bx = blockIdx.x;
    const int xt = bx >> 1;
    const int ch = bx & 1;
    const int y  = blockIdx.y;
    const int bb = blockIdx.z;
    const int x0 = xt * 32;

    if (tid < 128) {
        const int px = tid >> 2, p = tid & 3;
        const int x = x0 + px;
        const size_t pi = ((size_t)bb * HWHI + y * 128 + x) * 8;
        const float ox = g_offsets[pi + 2 * p]     * (1.0f / 64.0f);
        const float oy = g_offsets[pi + 2 * p + 1] * (1.0f / 64.0f);
        const float gx = fmaf((float)x, 2.0f / 127.0f, -1.0f) + ox;
        const float gy = fmaf((float)y, 2.0f / 127.0f, -1.0f) + oy;
        const float gxp = fminf(fmaxf(fmaf(gx, 32.0f, 31.5f), 0.0f), 63.0f);
        const float gyp = fminf(fmaxf(fmaf(gy, 32.0f, 31.5f), 0.0f), 63.0f);
        const float fx0 = floorf(gxp), fy0 = floorf(gyp);
        const int ix0 = (int)fx0, iy0 = (int)fy0;
        const float fx = gxp - fx0, fy = gyp - fy0;
        const int ix1 = (ix0 + 1 > 63) ? 63 : ix0 + 1;
        const int iy1 = (iy0 + 1 > 63) ? 63 : iy0 + 1;
        const int q = p * 4;
        // offsets in half2 units (pixel stride = 128 half2)
        sh_idx[px][q + 0] = (iy0 * 64 + ix0) * 128;
        sh_idx[px][q + 1] = (iy0 * 64 + ix1) * 128;
        sh_idx[px][q + 2] = (iy1 * 64 + ix0) * 128;
        sh_idx[px][q + 3] = (iy1 * 64 + ix1) * 128;
        sh_w[px][q + 0] = (1.f - fx) * (1.f - fy) * 0.25f;
        sh_w[px][q + 1] = fx * (1.f - fy) * 0.25f;
        sh_w[px][q + 2] = (1.f - fx) * fy * 0.25f;
        sh_w[px][q + 3] = fx * fy * 0.25f;
    }
    __syncthreads();

    const int lane = tid & 31, wrp = tid >> 5;
    const __half2* pb = (const __half2*)(g_proc16 + (size_t)bb * HWLO * 256 + ch * 128 + 4 * lane);

#pragma unroll
    for (int r = 0; r < 4; ++r) {
        const int px = wrp * 4 + r;
        float4 acc = make_float4(0.f, 0.f, 0.f, 0.f);
#pragma unroll
        for (int t = 0; t < 16; ++t) {
            const float wt = sh_w[px][t];
            const uint2 u = *(const uint2*)(pb + sh_idx[px][t]);
            float2 f0 = h2f(u.x);
            float2 f1 = h2f(u.y);
            acc.x = fmaf(wt, f0.x, acc.x);
            acc.y = fmaf(wt, f0.y, acc.y);
            acc.z = fmaf(wt, f1.x, acc.z);
            acc.w = fmaf(wt, f1.y, acc.w);
        }
        *(float4*)&sh_t[px][4 * lane] = acc;
    }
    __syncthreads();

    const int xl = tid & 31;
    const int c0 = tid >> 5;
#pragma unroll
    for (int i = 0; i < 16; ++i) {
        const int c = c0 * 16 + i;
        out[((size_t)bb * 256 + ch * 128 + c) * HWHI + y * 128 + x0 + xl] = sh_t[xl][c];
    }
}

// ===========================================================================
extern "C" void kernel_launch(void* const* d_in, const int* in_sizes, int n_in,
                              void* d_out, int out_size)
{
    const float* high = (const float*)d_in[0];
    const float* low  = (const float*)d_in[1];
    const float* W1   = (const float*)d_in[2];
    const float* b1   = (const float*)d_in[3];
    const float* W2   = (const float*)d_in[4];
    const float* b2   = (const float*)d_in[5];
    const float* Wf   = (const float*)d_in[6];
    const float* bf   = (const float*)d_in[7];
    float* out = (float*)d_out;

    const int SM_G  = 98304;   // 2x16K A + 64K B (k1f/k2f)
    const int SM_K5 = 73728;   // 2x16K A + 4x10240 B
    static int inited = 0;
    if (!inited) {
        cudaFuncSetAttribute(k1f, cudaFuncAttributeMaxDynamicSharedMemorySize, SM_G);
        cudaFuncSetAttribute(k2f, cudaFuncAttributeMaxDynamicSharedMemorySize, SM_G);
        cudaFuncSetAttribute(k5f, cudaFuncAttributeMaxDynamicSharedMemorySize, SM_K5);
        inited = 1;
    }

    k0t<<<dim3(64, 4, 8), 256>>>(high, 0, HWLO);
    k0t<<<dim3(256, 4, 8), 256>>>(low, 1, HWHI);
    k0w<<<848, 256>>>(W1, Wf, W2);
    k1f<<<dim3(256, 4), 256, SM_G>>>(bf);
    k2f<<<dim3(1024, 2), 256, SM_G>>>(b1);
    k5f<<<1024, 256, SM_K5>>>();
    k6_stencil<<<512, 256>>>(b2);
    k4_sample<<<dim3(8, 128, 8), 256>>>(out);
}

// round 10
// speedup vs baseline: 2.7399x; 1.0775x over previous
#include <cuda_runtime.h>
#include <cuda_fp16.h>

// ---------------------------------------------------------------------------
// AdaUp, fp16 mma.sync + cp.async pipelines.
//   K0t: f32 NCHW -> fp16 NHWC transpose (high, low)
//   K0w: weights -> packed fp16 [n][k] table
//   K1f: t = W1a@high (fp16) ; proc = Wf@high + bf (fp16)
//   K2f: off_feat = relu(W1b@low + up2x(t) + b1) (fp16) [t rows staged in smem]
//   K5f: q[p][tap*8+o] = W2tap @ off_feat(p)  (f32, N=72 pad 80)
//   K6 : offsets = b2 + 9-tap shift-sum of q
//   K4 : 4-point deformable sampling of fp16 proc (warp = 256ch, LDG.128)
// ---------------------------------------------------------------------------

#define NB    8
#define HWLO  4096
#define HWHI  16384

__device__ __half g_h16[(size_t)NB * HWLO * 256];
__device__ __half g_l16[(size_t)NB * HWHI * 256];
__device__ __half g_wh[1024 * 256];
__device__ __half g_t16[(size_t)NB * HWLO * 256];
__device__ __half g_proc16[(size_t)NB * HWLO * 256];
__device__ __half g_off16[(size_t)NB * HWHI * 256];
__device__ float  g_q[(size_t)NB * HWHI * 72];
__device__ float  g_offsets[(size_t)NB * HWHI * 8];

__device__ __forceinline__ unsigned smem_u32(const void* p) {
    unsigned a;
    asm("{ .reg .u64 t; cvta.to.shared.u64 t, %1; cvt.u32.u64 %0, t; }" : "=r"(a) : "l"(p));
    return a;
}
__device__ __forceinline__ unsigned sw128(unsigned o) { return o ^ ((o >> 3) & 0x70); }
__device__ __forceinline__ unsigned pack_h2(float lo, float hi) {
    unsigned u;
    asm("cvt.rn.f16x2.f32 %0, %1, %2;" : "=r"(u) : "f"(hi), "f"(lo));
    return u;
}
__device__ __forceinline__ void cpa16(unsigned dst, const void* src) {
    asm volatile("cp.async.cg.shared.global [%0], [%1], 16;" :: "r"(dst), "l"(src));
}
#define CP_COMMIT() asm volatile("cp.async.commit_group;" ::: "memory")
template <int N> __device__ __forceinline__ void cp_wait() {
    asm volatile("cp.async.wait_group %0;" :: "n"(N) : "memory");
}

#define LDSM_X4(r0, r1, r2, r3, addr) \
    asm volatile("ldmatrix.sync.aligned.m8n8.x4.shared.b16 {%0,%1,%2,%3}, [%4];" \
                 : "=r"(r0), "=r"(r1), "=r"(r2), "=r"(r3) : "r"(addr))
#define LDSM_X2(r0, r1, addr) \
    asm volatile("ldmatrix.sync.aligned.m8n8.x2.shared.b16 {%0,%1}, [%2];" \
                 : "=r"(r0), "=r"(r1) : "r"(addr))
#define MMA_F16(d, a, b) \
    asm volatile("mma.sync.aligned.m16n8k16.row.col.f32.f16.f16.f32 " \
                 "{%0,%1,%2,%3}, {%4,%5,%6,%7}, {%8,%9}, {%0,%1,%2,%3};" \
                 : "+f"((d)[0]), "+f"((d)[1]), "+f"((d)[2]), "+f"((d)[3]) \
                 : "r"((a)[0]), "r"((a)[1]), "r"((a)[2]), "r"((a)[3]), \
                   "r"((b)[0]), "r"((b)[1]))

__device__ __forceinline__ float2 h2f(unsigned u) {
    return __half22float2(*(const __half2*)&u);
}

// ===========================================================================
// K0t: [b][k][s] f32 -> [b][s][k] fp16
// ===========================================================================
__global__ __launch_bounds__(256)
void k0t(const float* __restrict__ src, int which, int S)
{
    __shared__ float ts[64][65];
    __half* dst = which ? g_l16 : g_h16;
    const int tid = threadIdx.x;
    const int s0 = blockIdx.x * 64, k0 = blockIdx.y * 64, b = blockIdx.z;
    const float* in = src + (size_t)b * 256 * S + (size_t)k0 * S + s0;
#pragma unroll
    for (int i = 0; i < 16; ++i) {
        const int idx = i * 256 + tid;
        const int kk = idx >> 6, ss = idx & 63;
        ts[ss][kk] = in[(size_t)kk * S + ss];
    }
    __syncthreads();
    unsigned* ob = (unsigned*)(dst + ((size_t)b * S + s0) * 256 + k0);
#pragma unroll
    for (int i = 0; i < 8; ++i) {
        const int idx = i * 256 + tid;
        const int ss = idx >> 5, kp = (idx & 31) * 2;
        ob[(size_t)ss * 128 + (kp >> 1)] = pack_h2(ts[ss][kp], ts[ss][kp + 1]);
    }
}

// ===========================================================================
// K0w: pack weights fp16 [row][256]
// ===========================================================================
__global__ __launch_bounds__(256)
void k0w(const float* __restrict__ W1, const float* __restrict__ Wf,
         const float* __restrict__ W2)
{
    const int row = blockIdx.x, c = threadIdx.x;
    float v = 0.f;
    if (row < 256)      v = W1[(size_t)row * 512 + c];
    else if (row < 512) v = Wf[(size_t)(row - 256) * 256 + c];
    else if (row < 768) v = W1[(size_t)(row - 512) * 512 + 256 + c];
    else if (row < 840) {
        const int t = (row - 768) >> 3, o = (row - 768) & 7;
        v = W2[(size_t)o * 2304 + c * 9 + t];
    }
    g_wh[(size_t)row * 256 + c] = __float2half(v);
}

// ===========================================================================
// cp.async one 64-k A chunk (128 rows x 128 bytes)
// ===========================================================================
__device__ __forceinline__ void load_A_chunk(unsigned bufA, const __half* A16,
                                             int kt, int tid)
{
    const int row = tid >> 1, c4 = (tid & 1) * 4;
#pragma unroll
    for (int j = 0; j < 4; ++j) {
        const int c = c4 + j;
        cpa16(bufA + sw128(row * 128 + c * 16), A16 + (size_t)row * 256 + kt * 64 + c * 8);
    }
}

// ===========================================================================
// K1f: [t | proc] = [W1a | Wf] @ high ; grid (256, 4)
// ===========================================================================
__global__ __launch_bounds__(256, 2)
void k1f(const float* __restrict__ bf)
{
    extern __shared__ char dsm[];
    const unsigned sb = smem_u32(dsm), sbB = sb + 32768;
    const int tid = threadIdx.x, lane = tid & 31, warp = tid >> 5;
    const int wm = warp & 1, wn = warp >> 1;
    const int m0 = blockIdx.x * 128;
    const int ny = blockIdx.y >> 1, nhalf = blockIdx.y & 1;
    const int bb = m0 >> 12, s0 = m0 & 4095;
    const int brow0 = ny * 256 + nhalf * 128;

    const __half* A16 = g_h16 + ((size_t)bb * HWLO + s0) * 256;

    unsigned aoff[4], boff[2];
#pragma unroll
    for (int mt = 0; mt < 4; ++mt)
        aoff[mt] = ((unsigned)(wm * 64 + mt * 16 + (lane & 15)) << 7) + (lane >> 4) * 16;
#pragma unroll
    for (int p = 0; p < 2; ++p)
        boff[p] = ((unsigned)(wn * 32 + p * 16 + (lane & 7) + ((lane >> 4) & 1) * 8) << 7)
                  + ((lane >> 3) & 1) * 16;

    float d[4][4][4];
#pragma unroll
    for (int i = 0; i < 4; ++i)
#pragma unroll
        for (int j = 0; j < 4; ++j)
#pragma unroll
            for (int e = 0; e < 4; ++e) d[i][j][e] = 0.f;

#pragma unroll
    for (int i = 0; i < 16; ++i) {
        const int idx = i * 256 + tid;
        const int n = idx >> 5, c = idx & 31;
        cpa16(sbB + (c >> 3) * 16384 + sw128(n * 128 + (c & 7) * 16),
              g_wh + (size_t)(brow0 + n) * 256 + c * 8);
    }
    load_A_chunk(sb, A16, 0, tid);
    CP_COMMIT();
    load_A_chunk(sb + 16384, A16, 1, tid);
    CP_COMMIT();

    for (int kt = 0; kt < 4; ++kt) {
        if (kt < 3) cp_wait<1>(); else cp_wait<0>();
        __syncthreads();
        const unsigned bufA = sb + (kt & 1) * 16384;
        const unsigned bufB = sbB + kt * 16384;
#pragma unroll
        for (int ks = 0; ks < 4; ++ks) {
            const unsigned ksb = ks * 32;
            unsigned a[4][4], b[4][2];
#pragma unroll
            for (int mt = 0; mt < 4; ++mt)
                LDSM_X4(a[mt][0], a[mt][1], a[mt][2], a[mt][3], bufA + sw128(aoff[mt] + ksb));
            LDSM_X4(b[0][0], b[0][1], b[1][0], b[1][1], bufB + sw128(boff[0] + ksb));
            LDSM_X4(b[2][0], b[2][1], b[3][0], b[3][1], bufB + sw128(boff[1] + ksb));
#pragma unroll
            for (int mt = 0; mt < 4; ++mt)
#pragma unroll
                for (int nt = 0; nt < 4; ++nt)
                    MMA_F16(d[mt][nt], a[mt], b[nt]);
        }
        __syncthreads();
        if (kt < 2) { load_A_chunk(sb + (kt & 1) * 16384, A16, kt + 2, tid); CP_COMMIT(); }
    }

#pragma unroll
    for (int mt = 0; mt < 4; ++mt) {
        const int row = m0 + wm * 64 + mt * 16 + (lane >> 2);
#pragma unroll
        for (int nt = 0; nt < 4; ++nt) {
            const int col = nhalf * 128 + wn * 32 + nt * 8 + (lane & 3) * 2;
            if (ny == 0) {
                *(unsigned*)&g_t16[(size_t)row * 256 + col] =
                    pack_h2(d[mt][nt][0], d[mt][nt][1]);
                *(unsigned*)&g_t16[(size_t)(row + 8) * 256 + col] =
                    pack_h2(d[mt][nt][2], d[mt][nt][3]);
            } else {
                const float b0 = bf[col], b1 = bf[col + 1];
                *(unsigned*)&g_proc16[(size_t)row * 256 + col] =
                    pack_h2(d[mt][nt][0] + b0, d[mt][nt][1] + b1);
                *(unsigned*)&g_proc16[(size_t)(row + 8) * 256 + col] =
                    pack_h2(d[mt][nt][2] + b0, d[mt][nt][3] + b1);
            }
        }
    }
}

// ===========================================================================
// K2f: off_feat = relu(W1b@low + up2x(t) + b1) -> fp16 ; grid (1024, 2)
// Post-mainloop: accum staged @0 (f32, 67584B), t rows jy0/jy1 staged @67584
// (32KB fp16). Dyn smem = 100352 (2 CTA/SM).
// ===========================================================================
__global__ __launch_bounds__(256, 2)
void k2f(const float* __restrict__ b1)
{
    extern __shared__ char dsm[];
    const unsigned sb = smem_u32(dsm), sbB = sb + 32768;
    float (*stage)[132] = (float(*)[132])dsm;

    const int tid = threadIdx.x, lane = tid & 31, warp = tid >> 5;
    const int wm = warp & 1, wn = warp >> 1;
    const int m0 = blockIdx.x * 128;
    const int n0 = blockIdx.y * 128;
    const int bb = m0 >> 14, s0 = m0 & 16383;
    const int brow0 = 512 + n0;

    const __half* A16 = g_l16 + ((size_t)bb * HWHI + s0) * 256;

    unsigned aoff[4], boff[2];
#pragma unroll
    for (int mt = 0; mt < 4; ++mt)
        aoff[mt] = ((unsigned)(wm * 64 + mt * 16 + (lane & 15)) << 7) + (lane >> 4) * 16;
#pragma unroll
    for (int p = 0; p < 2; ++p)
        boff[p] = ((unsigned)(wn * 32 + p * 16 + (lane & 7) + ((lane >> 4) & 1) * 8) << 7)
                  + ((lane >> 3) & 1) * 16;

    float d[4][4][4];
#pragma unroll
    for (int i = 0; i < 4; ++i)
#pragma unroll
        for (int j = 0; j < 4; ++j)
#pragma unroll
            for (int e = 0; e < 4; ++e) d[i][j][e] = 0.f;

#pragma unroll
    for (int i = 0; i < 16; ++i) {
        const int idx = i * 256 + tid;
        const int n = idx >> 5, c = idx & 31;
        cpa16(sbB + (c >> 3) * 16384 + sw128(n * 128 + (c & 7) * 16),
              g_wh + (size_t)(brow0 + n) * 256 + c * 8);
    }
    load_A_chunk(sb, A16, 0, tid);
    CP_COMMIT();
    load_A_chunk(sb + 16384, A16, 1, tid);
    CP_COMMIT();

    for (int kt = 0; kt < 4; ++kt) {
        if (kt < 3) cp_wait<1>(); else cp_wait<0>();
        __syncthreads();
        const unsigned bufA = sb + (kt & 1) * 16384;
        const unsigned bufB = sbB + kt * 16384;
#pragma unroll
        for (int ks = 0; ks < 4; ++ks) {
            const unsigned ksb = ks * 32;
            unsigned a[4][4], b[4][2];
#pragma unroll
            for (int mt = 0; mt < 4; ++mt)
                LDSM_X4(a[mt][0], a[mt][1], a[mt][2], a[mt][3], bufA + sw128(aoff[mt] + ksb));
            LDSM_X4(b[0][0], b[0][1], b[1][0], b[1][1], bufB + sw128(boff[0] + ksb));
            LDSM_X4(b[2][0], b[2][1], b[3][0], b[3][1], bufB + sw128(boff[1] + ksb));
#pragma unroll
            for (int mt = 0; mt < 4; ++mt)
#pragma unroll
                for (int nt = 0; nt < 4; ++nt)
                    MMA_F16(d[mt][nt], a[mt], b[nt]);
        }
        __syncthreads();
        if (kt < 2) { load_A_chunk(sb + (kt & 1) * 16384, A16, kt + 2, tid); CP_COMMIT(); }
    }

    // ---- post-mainloop: all smem free. Stage accums + t rows, then epilogue.
    __syncthreads();
    const int yy = s0 >> 7;
    int jy0_, jy1_;
    float wy0, wy1;
    if (yy & 1) { jy0_ = yy >> 1; jy1_ = ((yy >> 1) + 1 > 63) ? 63 : (yy >> 1) + 1; wy0 = 0.75f; wy1 = 0.25f; }
    else        { jy0_ = ((yy >> 1) - 1 < 0) ? 0 : (yy >> 1) - 1; jy1_ = yy >> 1;   wy0 = 0.25f; wy1 = 0.75f; }

#pragma unroll
    for (int mt = 0; mt < 4; ++mt) {
        const int sr = wm * 64 + mt * 16 + (lane >> 2);
#pragma unroll
        for (int nt = 0; nt < 4; ++nt) {
            const int sc = wn * 32 + nt * 8 + (lane & 3) * 2;
            *(float2*)&stage[sr][sc]     = make_float2(d[mt][nt][0], d[mt][nt][1]);
            *(float2*)&stage[sr + 8][sc] = make_float2(d[mt][nt][2], d[mt][nt][3]);
        }
    }
    // cooperative stage of t rows jy0/jy1 (n-half): 2 x 64 px x 128 ch fp16
    {
        const __half* tb = g_t16 + (size_t)bb * HWLO * 256;
        uint4* tst = (uint4*)(dsm + 67584);
#pragma unroll
        for (int i = 0; i < 8; ++i) {
            const int idx = i * 256 + tid;           // 0..2047
            const int r = idx >> 10, rest = idx & 1023;
            const int j = rest >> 4, cc = rest & 15; // 16B chunk
            const int jy = r ? jy1_ : jy0_;
            tst[idx] = *(const uint4*)(tb + (size_t)(jy * 64 + j) * 256 + n0 + cc * 8);
        }
    }
    __syncthreads();

    const int p = tid >> 1, chh = tid & 1;
    const int m = m0 + p;
    const int xx = p;
    const int tw = xx >> 1;
    int jx0, jx1;
    float wx0, wx1;
    if (xx & 1) { jx0 = tw; jx1 = (tw + 1 > 63) ? 63 : tw + 1; wx0 = 0.75f; wx1 = 0.25f; }
    else        { jx0 = (tw - 1 < 0) ? 0 : tw - 1; jx1 = tw;   wx0 = 0.25f; wx1 = 0.75f; }
    const float wa = wy0 * wx0, wb_ = wy0 * wx1, wc = wy1 * wx0, wd = wy1 * wx1;
    const __half* tsh = (const __half*)(dsm + 67584);
    const __half* r0p = tsh;            // row jy0 block: [64 px][128 ch]
    const __half* r1p = tsh + 8192;     // row jy1 block
    __half* ob = g_off16 + (size_t)m * 256 + n0;

#pragma unroll
    for (int g = 0; g < 16; ++g) {
        const int c = chh * 64 + g * 4;
        float4 av  = *(const float4*)&stage[p][c];
        float4 bv  = *(const float4*)&b1[n0 + c];
        uint2 q00 = *(const uint2*)&r0p[jx0 * 128 + c];
        uint2 q01 = *(const uint2*)&r0p[jx1 * 128 + c];
        uint2 q10 = *(const uint2*)&r1p[jx0 * 128 + c];
        uint2 q11 = *(const uint2*)&r1p[jx1 * 128 + c];
        float2 a00 = h2f(q00.x), b00 = h2f(q00.y);
        float2 a01 = h2f(q01.x), b01 = h2f(q01.y);
        float2 a10 = h2f(q10.x), b10v = h2f(q10.y);
        float2 a11 = h2f(q11.x), b11v = h2f(q11.y);
        float o0 = fmaxf(av.x + bv.x + wa*a00.x + wb_*a01.x + wc*a10.x + wd*a11.x, 0.f);
        float o1 = fmaxf(av.y + bv.y + wa*a00.y + wb_*a01.y + wc*a10.y + wd*a11.y, 0.f);
        float o2 = fmaxf(av.z + bv.z + wa*b00.x + wb_*b01.x + wc*b10v.x + wd*b11v.x, 0.f);
        float o3 = fmaxf(av.w + bv.w + wa*b00.y + wb_*b01.y + wc*b10v.y + wd*b11v.y, 0.f);
        *(uint2*)&ob[c] = make_uint2(pack_h2(o0, o1), pack_h2(o2, o3));
    }
}

// ===========================================================================
// K5f: q = off_feat @ W2taps (N=72 pad 80)
// ===========================================================================
__global__ __launch_bounds__(256, 2)
void k5f()
{
    extern __shared__ char dsm[];
    const unsigned sb = smem_u32(dsm), sbB = sb + 32768;
    const int tid = threadIdx.x, lane = tid & 31, warp = tid >> 5;
    const int wm = warp >> 1, wn = warp & 1;
    const int m0 = blockIdx.x * 128;

    const __half* A16 = g_off16 + (size_t)m0 * 256;

    unsigned aoff[2], boffp[2], boffs;
#pragma unroll
    for (int mt = 0; mt < 2; ++mt)
        aoff[mt] = ((unsigned)(wm * 32 + mt * 16 + (lane & 15)) << 7) + (lane >> 4) * 16;
#pragma unroll
    for (int p = 0; p < 2; ++p)
        boffp[p] = ((unsigned)(wn * 40 + p * 16 + (lane & 7) + ((lane >> 4) & 1) * 8) << 7)
                   + ((lane >> 3) & 1) * 16;
    boffs = ((unsigned)(wn * 40 + 32 + (lane & 7)) << 7) + ((lane >> 3) & 1) * 16;

    float d[2][5][4];
#pragma unroll
    for (int i = 0; i < 2; ++i)
#pragma unroll
        for (int j = 0; j < 5; ++j)
#pragma unroll
            for (int e = 0; e < 4; ++e) d[i][j][e] = 0.f;

#pragma unroll
    for (int i = 0; i < 10; ++i) {
        const int idx = i * 256 + tid;
        const int n = idx >> 5, c = idx & 31;
        cpa16(sbB + (c >> 3) * 10240 + sw128(n * 128 + (c & 7) * 16),
              g_wh + (size_t)(768 + n) * 256 + c * 8);
    }
    load_A_chunk(sb, A16, 0, tid);
    CP_COMMIT();
    load_A_chunk(sb + 16384, A16, 1, tid);
    CP_COMMIT();

    for (int kt = 0; kt < 4; ++kt) {
        if (kt < 3) cp_wait<1>(); else cp_wait<0>();
        __syncthreads();
        const unsigned bufA = sb + (kt & 1) * 16384;
        const unsigned bufB = sbB + kt * 10240;
#pragma unroll
        for (int ks = 0; ks < 4; ++ks) {
            const unsigned ksb = ks * 32;
            unsigned a[2][4], b[5][2];
#pragma unroll
            for (int mt = 0; mt < 2; ++mt)
                LDSM_X4(a[mt][0], a[mt][1], a[mt][2], a[mt][3], bufA + sw128(aoff[mt] + ksb));
            LDSM_X4(b[0][0], b[0][1], b[1][0], b[1][1], bufB + sw128(boffp[0] + ksb));
            LDSM_X4(b[2][0], b[2][1], b[3][0], b[3][1], bufB + sw128(boffp[1] + ksb));
            LDSM_X2(b[4][0], b[4][1], bufB + sw128(boffs + ksb));
#pragma unroll
            for (int mt = 0; mt < 2; ++mt)
#pragma unroll
                for (int nt = 0; nt < 5; ++nt)
                    MMA_F16(d[mt][nt], a[mt], b[nt]);
        }
        __syncthreads();
        if (kt < 2) { load_A_chunk(sb + (kt & 1) * 16384, A16, kt + 2, tid); CP_COMMIT(); }
    }

#pragma unroll
    for (int mt = 0; mt < 2; ++mt) {
        const int row = m0 + wm * 32 + mt * 16 + (lane >> 2);
#pragma unroll
        for (int nt = 0; nt < 5; ++nt) {
            const int col = wn * 40 + nt * 8 + (lane & 3) * 2;
            if (col < 72) {
                *(float2*)&g_q[(size_t)row * 72 + col] = make_float2(d[mt][nt][0], d[mt][nt][1]);
                *(float2*)&g_q[(size_t)(row + 8) * 72 + col] = make_float2(d[mt][nt][2], d[mt][nt][3]);
            }
        }
    }
}

// ===========================================================================
// K6: offsets[p][o] = b2[o] + sum 9-tap shift of q
// ===========================================================================
__global__ __launch_bounds__(256)
void k6_stencil(const float* __restrict__ b2)
{
    const int p = blockIdx.x * 256 + threadIdx.x;
    const int bb = p >> 14, s = p & 16383, y = s >> 7, x = s & 127;
    float4 a0 = *(const float4*)&b2[0];
    float4 a1 = *(const float4*)&b2[4];
    const float* qb = g_q + (size_t)bb * HWHI * 72;
#pragma unroll
    for (int dy = 0; dy < 3; ++dy) {
        const int yy = y + dy - 1;
        if (yy < 0 || yy > 127) continue;
#pragma unroll
        for (int dx = 0; dx < 3; ++dx) {
            const int xx = x + dx - 1;
            if (xx < 0 || xx > 127) continue;
            const float* qq = qb + (size_t)(yy * 128 + xx) * 72 + (dy * 3 + dx) * 8;
            float4 v0 = *(const float4*)qq;
            float4 v1 = *(const float4*)(qq + 4);
            a0.x += v0.x; a0.y += v0.y; a0.z += v0.z; a0.w += v0.w;
            a1.x += v1.x; a1.y += v1.y; a1.z += v1.z; a1.w += v1.w;
        }
    }
    *(float4*)&g_offsets[(size_t)p * 8] = a0;
    *(float4*)&g_offsets[(size_t)p * 8 + 4] = a1;
}

// ===========================================================================
// K4: deformable 4-point bilinear sample. Warp = full 256 ch via uint4 taps.
// grid (4, 128, 8); block 256; warp handles 4 pixels of the 32-px x-tile.
// smem transpose padded 9-floats/group, 289-floats/row (conflict-free).
// ===========================================================================
__global__ __launch_bounds__(256)
void k4_sample(float* __restrict__ out)
{
    __shared__ int   sh_idx[32][16];
    __shared__ float sh_w[32][16];
    __shared__ float sh_t[32 * 289 + 8];

    const int tid = threadIdx.x;
    const int xt = blockIdx.x;
    const int y  = blockIdx.y;
    const int bb = blockIdx.z;
    const int x0 = xt * 32;

    if (tid < 128) {
        const int px = tid >> 2, p = tid & 3;
        const int x = x0 + px;
        const size_t pi = ((size_t)bb * HWHI + y * 128 + x) * 8;
        const float ox = g_offsets[pi + 2 * p]     * (1.0f / 64.0f);
        const float oy = g_offsets[pi + 2 * p + 1] * (1.0f / 64.0f);
        const float gx = fmaf((float)x, 2.0f / 127.0f, -1.0f) + ox;
        const float gy = fmaf((float)y, 2.0f / 127.0f, -1.0f) + oy;
        const float gxp = fminf(fmaxf(fmaf(gx, 32.0f, 31.5f), 0.0f), 63.0f);
        const float gyp = fminf(fmaxf(fmaf(gy, 32.0f, 31.5f), 0.0f), 63.0f);
        const float fx0 = floorf(gxp), fy0 = floorf(gyp);
        const int ix0 = (int)fx0, iy0 = (int)fy0;
        const float fx = gxp - fx0, fy = gyp - fy0;
        const int ix1 = (ix0 + 1 > 63) ? 63 : ix0 + 1;
        const int iy1 = (iy0 + 1 > 63) ? 63 : iy0 + 1;
        const int q = p * 4;
        // offsets in uint4 units (pixel stride = 256 ch * 2B = 32 uint4)
        sh_idx[px][q + 0] = (iy0 * 64 + ix0) * 32;
        sh_idx[px][q + 1] = (iy0 * 64 + ix1) * 32;
        sh_idx[px][q + 2] = (iy1 * 64 + ix0) * 32;
        sh_idx[px][q + 3] = (iy1 * 64 + ix1) * 32;
        sh_w[px][q + 0] = (1.f - fx) * (1.f - fy) * 0.25f;
        sh_w[px][q + 1] = fx * (1.f - fy) * 0.25f;
        sh_w[px][q + 2] = (1.f - fx) * fy * 0.25f;
        sh_w[px][q + 3] = fx * fy * 0.25f;
    }
    __syncthreads();

    const int lane = tid & 31, wrp = tid >> 5;
    const uint4* pb = (const uint4*)(g_proc16 + (size_t)bb * HWLO * 256) + lane;

#pragma unroll
    for (int r = 0; r < 4; ++r) {
        const int px = wrp * 4 + r;
        float acc[8];
#pragma unroll
        for (int j = 0; j < 8; ++j) acc[j] = 0.f;
#pragma unroll
        for (int t = 0; t < 16; ++t) {
            const float wt = sh_w[px][t];
            const uint4 u = pb[sh_idx[px][t]];
            float2 f0 = h2f(u.x), f1 = h2f(u.y), f2 = h2f(u.z), f3 = h2f(u.w);
            acc[0] = fmaf(wt, f0.x, acc[0]); acc[1] = fmaf(wt, f0.y, acc[1]);
            acc[2] = fmaf(wt, f1.x, acc[2]); acc[3] = fmaf(wt, f1.y, acc[3]);
            acc[4] = fmaf(wt, f2.x, acc[4]); acc[5] = fmaf(wt, f2.y, acc[5]);
            acc[6] = fmaf(wt, f3.x, acc[6]); acc[7] = fmaf(wt, f3.y, acc[7]);
        }
        float* dstp = &sh_t[px * 289 + lane * 9];
#pragma unroll
        for (int j = 0; j < 8; ++j) dstp[j] = acc[j];
    }
    __syncthreads();

    const int xl = tid & 31;
    const int c0 = tid >> 5;
#pragma unroll
    for (int i = 0; i < 32; ++i) {
        const int c = c0 * 32 + i;
        out[((size_t)bb * 256 + c) * HWHI + y * 128 + x0 + xl] =
            sh_t[xl * 289 + (c >> 3) * 9 + (c & 7)];
    }
}

// ===========================================================================
extern "C" void kernel_launch(void* const* d_in, const int* in_sizes, int n_in,
                              void* d_out, int out_size)
{
    const float* high = (const float*)d_in[0];
    const float* low  = (const float*)d_in[1];
    const float* W1   = (const float*)d_in[2];
    const float* b1   = (const float*)d_in[3];
    const float* W2   = (const float*)d_in[4];
    const float* b2   = (const float*)d_in[5];
    const float* Wf   = (const float*)d_in[6];
    const float* bf   = (const float*)d_in[7];
    float* out = (float*)d_out;

    const int SM_K1 = 98304;    // 2x16K A + 64K B
    const int SM_K2 = 100352;   // + t-row stage region
    const int SM_K5 = 73728;
    static int inited = 0;
    if (!inited) {
        cudaFuncSetAttribute(k1f, cudaFuncAttributeMaxDynamicSharedMemorySize, SM_K1);
        cudaFuncSetAttribute(k2f, cudaFuncAttributeMaxDynamicSharedMemorySize, SM_K2);
        cudaFuncSetAttribute(k5f, cudaFuncAttributeMaxDynamicSharedMemorySize, SM_K5);
        inited = 1;
    }

    k0t<<<dim3(64, 4, 8), 256>>>(high, 0, HWLO);
    k0t<<<dim3(256, 4, 8), 256>>>(low, 1, HWHI);
    k0w<<<848, 256>>>(W1, Wf, W2);
    k1f<<<dim3(256, 4), 256, SM_K1>>>(bf);
    k2f<<<dim3(1024, 2), 256, SM_K2>>>(b1);
    k5f<<<1024, 256, SM_K5>>>();
    k6_stencil<<<512, 256>>>(b2);
    k4_sample<<<dim3(4, 128, 8), 256>>>(out);
}

// round 11
// speedup vs baseline: 2.7646x; 1.0090x over previous
#include <cuda_runtime.h>
#include <cuda_fp16.h>

// ---------------------------------------------------------------------------
// AdaUp, fp16 mma.sync + cp.async pipelines + forked-stream overlap.
//   s2: k0t-low (DRAM-bound)  ||  s0: k0t-high -> k0w -> k1f (tensor-bound)
//   join -> k2f -> k5f -> k6 -> k4
// ---------------------------------------------------------------------------

#define NB    8
#define HWLO  4096
#define HWHI  16384

__device__ __half g_h16[(size_t)NB * HWLO * 256];
__device__ __half g_l16[(size_t)NB * HWHI * 256];
__device__ __half g_wh[1024 * 256];
__device__ __half g_t16[(size_t)NB * HWLO * 256];
__device__ __half g_proc16[(size_t)NB * HWLO * 256];
__device__ __half g_off16[(size_t)NB * HWHI * 256];
__device__ __half g_q16[(size_t)NB * HWHI * 72];
__device__ float  g_offsets[(size_t)NB * HWHI * 8];

__device__ __forceinline__ unsigned smem_u32(const void* p) {
    unsigned a;
    asm("{ .reg .u64 t; cvta.to.shared.u64 t, %1; cvt.u32.u64 %0, t; }" : "=r"(a) : "l"(p));
    return a;
}
__device__ __forceinline__ unsigned sw128(unsigned o) { return o ^ ((o >> 3) & 0x70); }
__device__ __forceinline__ unsigned pack_h2(float lo, float hi) {
    unsigned u;
    asm("cvt.rn.f16x2.f32 %0, %1, %2;" : "=r"(u) : "f"(hi), "f"(lo));
    return u;
}
__device__ __forceinline__ void cpa16(unsigned dst, const void* src) {
    asm volatile("cp.async.cg.shared.global [%0], [%1], 16;" :: "r"(dst), "l"(src));
}
#define CP_COMMIT() asm volatile("cp.async.commit_group;" ::: "memory")
template <int N> __device__ __forceinline__ void cp_wait() {
    asm volatile("cp.async.wait_group %0;" :: "n"(N) : "memory");
}

#define LDSM_X4(r0, r1, r2, r3, addr) \
    asm volatile("ldmatrix.sync.aligned.m8n8.x4.shared.b16 {%0,%1,%2,%3}, [%4];" \
                 : "=r"(r0), "=r"(r1), "=r"(r2), "=r"(r3) : "r"(addr))
#define LDSM_X2(r0, r1, addr) \
    asm volatile("ldmatrix.sync.aligned.m8n8.x2.shared.b16 {%0,%1}, [%2];" \
                 : "=r"(r0), "=r"(r1) : "r"(addr))
#define MMA_F16(d, a, b) \
    asm volatile("mma.sync.aligned.m16n8k16.row.col.f32.f16.f16.f32 " \
                 "{%0,%1,%2,%3}, {%4,%5,%6,%7}, {%8,%9}, {%0,%1,%2,%3};" \
                 : "+f"((d)[0]), "+f"((d)[1]), "+f"((d)[2]), "+f"((d)[3]) \
                 : "r"((a)[0]), "r"((a)[1]), "r"((a)[2]), "r"((a)[3]), \
                   "r"((b)[0]), "r"((b)[1]))

__device__ __forceinline__ float2 h2f(unsigned u) {
    return __half22float2(*(const __half2*)&u);
}

// ===========================================================================
// K0t: [b][k][s] f32 -> [b][s][k] fp16
// ===========================================================================
__global__ __launch_bounds__(256)
void k0t(const float* __restrict__ src, int which, int S)
{
    __shared__ float ts[64][65];
    __half* dst = which ? g_l16 : g_h16;
    const int tid = threadIdx.x;
    const int s0 = blockIdx.x * 64, k0 = blockIdx.y * 64, b = blockIdx.z;
    const float* in = src + (size_t)b * 256 * S + (size_t)k0 * S + s0;
#pragma unroll
    for (int i = 0; i < 16; ++i) {
        const int idx = i * 256 + tid;
        const int kk = idx >> 6, ss = idx & 63;
        ts[ss][kk] = in[(size_t)kk * S + ss];
    }
    __syncthreads();
    unsigned* ob = (unsigned*)(dst + ((size_t)b * S + s0) * 256 + k0);
#pragma unroll
    for (int i = 0; i < 8; ++i) {
        const int idx = i * 256 + tid;
        const int ss = idx >> 5, kp = (idx & 31) * 2;
        ob[(size_t)ss * 128 + (kp >> 1)] = pack_h2(ts[ss][kp], ts[ss][kp + 1]);
    }
}

// ===========================================================================
// K0w: pack weights fp16 [row][256]
// ===========================================================================
__global__ __launch_bounds__(256)
void k0w(const float* __restrict__ W1, const float* __restrict__ Wf,
         const float* __restrict__ W2)
{
    const int row = blockIdx.x, c = threadIdx.x;
    float v = 0.f;
    if (row < 256)      v = W1[(size_t)row * 512 + c];
    else if (row < 512) v = Wf[(size_t)(row - 256) * 256 + c];
    else if (row < 768) v = W1[(size_t)(row - 512) * 512 + 256 + c];
    else if (row < 840) {
        const int t = (row - 768) >> 3, o = (row - 768) & 7;
        v = W2[(size_t)o * 2304 + c * 9 + t];
    }
    g_wh[(size_t)row * 256 + c] = __float2half(v);
}

// ===========================================================================
// cp.async one 64-k A chunk (128 rows x 128 bytes)
// ===========================================================================
__device__ __forceinline__ void load_A_chunk(unsigned bufA, const __half* A16,
                                             int kt, int tid)
{
    const int row = tid >> 1, c4 = (tid & 1) * 4;
#pragma unroll
    for (int j = 0; j < 4; ++j) {
        const int c = c4 + j;
        cpa16(bufA + sw128(row * 128 + c * 16), A16 + (size_t)row * 256 + kt * 64 + c * 8);
    }
}

// ===========================================================================
// K1f: [t | proc] = [W1a | Wf] @ high ; grid (256, 4)
// ===========================================================================
__global__ __launch_bounds__(256, 2)
void k1f(const float* __restrict__ bf)
{
    extern __shared__ char dsm[];
    const unsigned sb = smem_u32(dsm), sbB = sb + 32768;
    const int tid = threadIdx.x, lane = tid & 31, warp = tid >> 5;
    const int wm = warp & 1, wn = warp >> 1;
    const int m0 = blockIdx.x * 128;
    const int ny = blockIdx.y >> 1, nhalf = blockIdx.y & 1;
    const int bb = m0 >> 12, s0 = m0 & 4095;
    const int brow0 = ny * 256 + nhalf * 128;

    const __half* A16 = g_h16 + ((size_t)bb * HWLO + s0) * 256;

    unsigned aoff[4], boff[2];
#pragma unroll
    for (int mt = 0; mt < 4; ++mt)
        aoff[mt] = ((unsigned)(wm * 64 + mt * 16 + (lane & 15)) << 7) + (lane >> 4) * 16;
#pragma unroll
    for (int p = 0; p < 2; ++p)
        boff[p] = ((unsigned)(wn * 32 + p * 16 + (lane & 7) + ((lane >> 4) & 1) * 8) << 7)
                  + ((lane >> 3) & 1) * 16;

    float d[4][4][4];
#pragma unroll
    for (int i = 0; i < 4; ++i)
#pragma unroll
        for (int j = 0; j < 4; ++j)
#pragma unroll
            for (int e = 0; e < 4; ++e) d[i][j][e] = 0.f;

#pragma unroll
    for (int i = 0; i < 16; ++i) {
        const int idx = i * 256 + tid;
        const int n = idx >> 5, c = idx & 31;
        cpa16(sbB + (c >> 3) * 16384 + sw128(n * 128 + (c & 7) * 16),
              g_wh + (size_t)(brow0 + n) * 256 + c * 8);
    }
    load_A_chunk(sb, A16, 0, tid);
    CP_COMMIT();
    load_A_chunk(sb + 16384, A16, 1, tid);
    CP_COMMIT();

    for (int kt = 0; kt < 4; ++kt) {
        if (kt < 3) cp_wait<1>(); else cp_wait<0>();
        __syncthreads();
        const unsigned bufA = sb + (kt & 1) * 16384;
        const unsigned bufB = sbB + kt * 16384;
#pragma unroll
        for (int ks = 0; ks < 4; ++ks) {
            const unsigned ksb = ks * 32;
            unsigned a[4][4], b[4][2];
#pragma unroll
            for (int mt = 0; mt < 4; ++mt)
                LDSM_X4(a[mt][0], a[mt][1], a[mt][2], a[mt][3], bufA + sw128(aoff[mt] + ksb));
            LDSM_X4(b[0][0], b[0][1], b[1][0], b[1][1], bufB + sw128(boff[0] + ksb));
            LDSM_X4(b[2][0], b[2][1], b[3][0], b[3][1], bufB + sw128(boff[1] + ksb));
#pragma unroll
            for (int mt = 0; mt < 4; ++mt)
#pragma unroll
                for (int nt = 0; nt < 4; ++nt)
                    MMA_F16(d[mt][nt], a[mt], b[nt]);
        }
        __syncthreads();
        if (kt < 2) { load_A_chunk(sb + (kt & 1) * 16384, A16, kt + 2, tid); CP_COMMIT(); }
    }

#pragma unroll
    for (int mt = 0; mt < 4; ++mt) {
        const int row = m0 + wm * 64 + mt * 16 + (lane >> 2);
#pragma unroll
        for (int nt = 0; nt < 4; ++nt) {
            const int col = nhalf * 128 + wn * 32 + nt * 8 + (lane & 3) * 2;
            if (ny == 0) {
                *(unsigned*)&g_t16[(size_t)row * 256 + col] =
                    pack_h2(d[mt][nt][0], d[mt][nt][1]);
                *(unsigned*)&g_t16[(size_t)(row + 8) * 256 + col] =
                    pack_h2(d[mt][nt][2], d[mt][nt][3]);
            } else {
                const float b0 = bf[col], b1 = bf[col + 1];
                *(unsigned*)&g_proc16[(size_t)row * 256 + col] =
                    pack_h2(d[mt][nt][0] + b0, d[mt][nt][1] + b1);
                *(unsigned*)&g_proc16[(size_t)(row + 8) * 256 + col] =
                    pack_h2(d[mt][nt][2] + b0, d[mt][nt][3] + b1);
            }
        }
    }
}

// ===========================================================================
// K2f: off_feat = relu(W1b@low + up2x(t) + b1) -> fp16 ; grid (1024, 2)
// ===========================================================================
__global__ __launch_bounds__(256, 2)
void k2f(const float* __restrict__ b1)
{
    extern __shared__ char dsm[];
    const unsigned sb = smem_u32(dsm), sbB = sb + 32768;
    float (*stage)[132] = (float(*)[132])dsm;

    const int tid = threadIdx.x, lane = tid & 31, warp = tid >> 5;
    const int wm = warp & 1, wn = warp >> 1;
    const int m0 = blockIdx.x * 128;
    const int n0 = blockIdx.y * 128;
    const int bb = m0 >> 14, s0 = m0 & 16383;
    const int brow0 = 512 + n0;

    const __half* A16 = g_l16 + ((size_t)bb * HWHI + s0) * 256;

    unsigned aoff[4], boff[2];
#pragma unroll
    for (int mt = 0; mt < 4; ++mt)
        aoff[mt] = ((unsigned)(wm * 64 + mt * 16 + (lane & 15)) << 7) + (lane >> 4) * 16;
#pragma unroll
    for (int p = 0; p < 2; ++p)
        boff[p] = ((unsigned)(wn * 32 + p * 16 + (lane & 7) + ((lane >> 4) & 1) * 8) << 7)
                  + ((lane >> 3) & 1) * 16;

    float d[4][4][4];
#pragma unroll
    for (int i = 0; i < 4; ++i)
#pragma unroll
        for (int j = 0; j < 4; ++j)
#pragma unroll
            for (int e = 0; e < 4; ++e) d[i][j][e] = 0.f;

#pragma unroll
    for (int i = 0; i < 16; ++i) {
        const int idx = i * 256 + tid;
        const int n = idx >> 5, c = idx & 31;
        cpa16(sbB + (c >> 3) * 16384 + sw128(n * 128 + (c & 7) * 16),
              g_wh + (size_t)(brow0 + n) * 256 + c * 8);
    }
    load_A_chunk(sb, A16, 0, tid);
    CP_COMMIT();
    load_A_chunk(sb + 16384, A16, 1, tid);
    CP_COMMIT();

    for (int kt = 0; kt < 4; ++kt) {
        if (kt < 3) cp_wait<1>(); else cp_wait<0>();
        __syncthreads();
        const unsigned bufA = sb + (kt & 1) * 16384;
        const unsigned bufB = sbB + kt * 16384;
#pragma unroll
        for (int ks = 0; ks < 4; ++ks) {
            const unsigned ksb = ks * 32;
            unsigned a[4][4], b[4][2];
#pragma unroll
            for (int mt = 0; mt < 4; ++mt)
                LDSM_X4(a[mt][0], a[mt][1], a[mt][2], a[mt][3], bufA + sw128(aoff[mt] + ksb));
            LDSM_X4(b[0][0], b[0][1], b[1][0], b[1][1], bufB + sw128(boff[0] + ksb));
            LDSM_X4(b[2][0], b[2][1], b[3][0], b[3][1], bufB + sw128(boff[1] + ksb));
#pragma unroll
            for (int mt = 0; mt < 4; ++mt)
#pragma unroll
                for (int nt = 0; nt < 4; ++nt)
                    MMA_F16(d[mt][nt], a[mt], b[nt]);
        }
        __syncthreads();
        if (kt < 2) { load_A_chunk(sb + (kt & 1) * 16384, A16, kt + 2, tid); CP_COMMIT(); }
    }

    // post-mainloop: stage accums + 2 t-rows in now-free smem
    __syncthreads();
    const int yy = s0 >> 7;
    int jy0_, jy1_;
    float wy0, wy1;
    if (yy & 1) { jy0_ = yy >> 1; jy1_ = ((yy >> 1) + 1 > 63) ? 63 : (yy >> 1) + 1; wy0 = 0.75f; wy1 = 0.25f; }
    else        { jy0_ = ((yy >> 1) - 1 < 0) ? 0 : (yy >> 1) - 1; jy1_ = yy >> 1;   wy0 = 0.25f; wy1 = 0.75f; }

#pragma unroll
    for (int mt = 0; mt < 4; ++mt) {
        const int sr = wm * 64 + mt * 16 + (lane >> 2);
#pragma unroll
        for (int nt = 0; nt < 4; ++nt) {
            const int sc = wn * 32 + nt * 8 + (lane & 3) * 2;
            *(float2*)&stage[sr][sc]     = make_float2(d[mt][nt][0], d[mt][nt][1]);
            *(float2*)&stage[sr + 8][sc] = make_float2(d[mt][nt][2], d[mt][nt][3]);
        }
    }
    {
        const __half* tb = g_t16 + (size_t)bb * HWLO * 256;
        uint4* tst = (uint4*)(dsm + 67584);
#pragma unroll
        for (int i = 0; i < 8; ++i) {
            const int idx = i * 256 + tid;
            const int r = idx >> 10, rest = idx & 1023;
            const int j = rest >> 4, cc = rest & 15;
            const int jy = r ? jy1_ : jy0_;
            tst[idx] = *(const uint4*)(tb + (size_t)(jy * 64 + j) * 256 + n0 + cc * 8);
        }
    }
    __syncthreads();

    const int p = tid >> 1, chh = tid & 1;
    const int m = m0 + p;
    const int xx = p;
    const int tw = xx >> 1;
    int jx0, jx1;
    float wx0, wx1;
    if (xx & 1) { jx0 = tw; jx1 = (tw + 1 > 63) ? 63 : tw + 1; wx0 = 0.75f; wx1 = 0.25f; }
    else        { jx0 = (tw - 1 < 0) ? 0 : tw - 1; jx1 = tw;   wx0 = 0.25f; wx1 = 0.75f; }
    const float wa = wy0 * wx0, wb_ = wy0 * wx1, wc = wy1 * wx0, wd = wy1 * wx1;
    const __half* tsh = (const __half*)(dsm + 67584);
    const __half* r0p = tsh;
    const __half* r1p = tsh + 8192;
    __half* ob = g_off16 + (size_t)m * 256 + n0;

#pragma unroll
    for (int g = 0; g < 16; ++g) {
        const int c = chh * 64 + g * 4;
        float4 av  = *(const float4*)&stage[p][c];
        float4 bv  = *(const float4*)&b1[n0 + c];
        uint2 q00 = *(const uint2*)&r0p[jx0 * 128 + c];
        uint2 q01 = *(const uint2*)&r0p[jx1 * 128 + c];
        uint2 q10 = *(const uint2*)&r1p[jx0 * 128 + c];
        uint2 q11 = *(const uint2*)&r1p[jx1 * 128 + c];
        float2 a00 = h2f(q00.x), b00 = h2f(q00.y);
        float2 a01 = h2f(q01.x), b01 = h2f(q01.y);
        float2 a10 = h2f(q10.x), b10v = h2f(q10.y);
        float2 a11 = h2f(q11.x), b11v = h2f(q11.y);
        float o0 = fmaxf(av.x + bv.x + wa*a00.x + wb_*a01.x + wc*a10.x + wd*a11.x, 0.f);
        float o1 = fmaxf(av.y + bv.y + wa*a00.y + wb_*a01.y + wc*a10.y + wd*a11.y, 0.f);
        float o2 = fmaxf(av.z + bv.z + wa*b00.x + wb_*b01.x + wc*b10v.x + wd*b11v.x, 0.f);
        float o3 = fmaxf(av.w + bv.w + wa*b00.y + wb_*b01.y + wc*b10v.y + wd*b11v.y, 0.f);
        *(uint2*)&ob[c] = make_uint2(pack_h2(o0, o1), pack_h2(o2, o3));
    }
}

// ===========================================================================
// K5f: q = off_feat @ W2taps (N=72 pad 80) ; q stored fp16
// ===========================================================================
__global__ __launch_bounds__(256, 2)
void k5f()
{
    extern __shared__ char dsm[];
    const unsigned sb = smem_u32(dsm), sbB = sb + 32768;
    const int tid = threadIdx.x, lane = tid & 31, warp = tid >> 5;
    const int wm = warp >> 1, wn = warp & 1;
    const int m0 = blockIdx.x * 128;

    const __half* A16 = g_off16 + (size_t)m0 * 256;

    unsigned aoff[2], boffp[2], boffs;
#pragma unroll
    for (int mt = 0; mt < 2; ++mt)
        aoff[mt] = ((unsigned)(wm * 32 + mt * 16 + (lane & 15)) << 7) + (lane >> 4) * 16;
#pragma unroll
    for (int p = 0; p < 2; ++p)
        boffp[p] = ((unsigned)(wn * 40 + p * 16 + (lane & 7) + ((lane >> 4) & 1) * 8) << 7)
                   + ((lane >> 3) & 1) * 16;
    boffs = ((unsigned)(wn * 40 + 32 + (lane & 7)) << 7) + ((lane >> 3) & 1) * 16;

    float d[2][5][4];
#pragma unroll
    for (int i = 0; i < 2; ++i)
#pragma unroll
        for (int j = 0; j < 5; ++j)
#pragma unroll
            for (int e = 0; e < 4; ++e) d[i][j][e] = 0.f;

#pragma unroll
    for (int i = 0; i < 10; ++i) {
        const int idx = i * 256 + tid;
        const int n = idx >> 5, c = idx & 31;
        cpa16(sbB + (c >> 3) * 10240 + sw128(n * 128 + (c & 7) * 16),
              g_wh + (size_t)(768 + n) * 256 + c * 8);
    }
    load_A_chunk(sb, A16, 0, tid);
    CP_COMMIT();
    load_A_chunk(sb + 16384, A16, 1, tid);
    CP_COMMIT();

    for (int kt = 0; kt < 4; ++kt) {
        if (kt < 3) cp_wait<1>(); else cp_wait<0>();
        __syncthreads();
        const unsigned bufA = sb + (kt & 1) * 16384;
        const unsigned bufB = sbB + kt * 10240;
#pragma unroll
        for (int ks = 0; ks < 4; ++ks) {
            const unsigned ksb = ks * 32;
            unsigned a[2][4], b[5][2];
#pragma unroll
            for (int mt = 0; mt < 2; ++mt)
                LDSM_X4(a[mt][0], a[mt][1], a[mt][2], a[mt][3], bufA + sw128(aoff[mt] + ksb));
            LDSM_X4(b[0][0], b[0][1], b[1][0], b[1][1], bufB + sw128(boffp[0] + ksb));
            LDSM_X4(b[2][0], b[2][1], b[3][0], b[3][1], bufB + sw128(boffp[1] + ksb));
            LDSM_X2(b[4][0], b[4][1], bufB + sw128(boffs + ksb));
#pragma unroll
            for (int mt = 0; mt < 2; ++mt)
#pragma unroll
                for (int nt = 0; nt < 5; ++nt)
                    MMA_F16(d[mt][nt], a[mt], b[nt]);
        }
        __syncthreads();
        if (kt < 2) { load_A_chunk(sb + (kt & 1) * 16384, A16, kt + 2, tid); CP_COMMIT(); }
    }

#pragma unroll
    for (int mt = 0; mt < 2; ++mt) {
        const int row = m0 + wm * 32 + mt * 16 + (lane >> 2);
#pragma unroll
        for (int nt = 0; nt < 5; ++nt) {
            const int col = wn * 40 + nt * 8 + (lane & 3) * 2;
            if (col < 72) {
                *(unsigned*)&g_q16[(size_t)row * 72 + col] =
                    pack_h2(d[mt][nt][0], d[mt][nt][1]);
                *(unsigned*)&g_q16[(size_t)(row + 8) * 72 + col] =
                    pack_h2(d[mt][nt][2], d[mt][nt][3]);
            }
        }
    }
}

// ===========================================================================
// K6: offsets[p][o] = b2[o] + sum 9-tap shift of q (fp16 taps, f32 accum)
// ===========================================================================
__global__ __launch_bounds__(256)
void k6_stencil(const float* __restrict__ b2)
{
    const int p = blockIdx.x * 256 + threadIdx.x;
    const int bb = p >> 14, s = p & 16383, y = s >> 7, x = s & 127;
    float a[8];
    {
        float4 b0 = *(const float4*)&b2[0];
        float4 b1v = *(const float4*)&b2[4];
        a[0] = b0.x; a[1] = b0.y; a[2] = b0.z; a[3] = b0.w;
        a[4] = b1v.x; a[5] = b1v.y; a[6] = b1v.z; a[7] = b1v.w;
    }
    const __half* qb = g_q16 + (size_t)bb * HWHI * 72;
#pragma unroll
    for (int dy = 0; dy < 3; ++dy) {
        const int yy = y + dy - 1;
        if (yy < 0 || yy > 127) continue;
#pragma unroll
        for (int dx = 0; dx < 3; ++dx) {
            const int xx = x + dx - 1;
            if (xx < 0 || xx > 127) continue;
            const uint4 u = *(const uint4*)(qb + (size_t)(yy * 128 + xx) * 72 + (dy * 3 + dx) * 8);
            float2 f0 = h2f(u.x), f1 = h2f(u.y), f2 = h2f(u.z), f3 = h2f(u.w);
            a[0] += f0.x; a[1] += f0.y; a[2] += f1.x; a[3] += f1.y;
            a[4] += f2.x; a[5] += f2.y; a[6] += f3.x; a[7] += f3.y;
        }
    }
    *(float4*)&g_offsets[(size_t)p * 8]     = make_float4(a[0], a[1], a[2], a[3]);
    *(float4*)&g_offsets[(size_t)p * 8 + 4] = make_float4(a[4], a[5], a[6], a[7]);
}

// ===========================================================================
// K4: deformable 4-point bilinear sample. Warp = full 256 ch via uint4 taps.
// ===========================================================================
__global__ __launch_bounds__(256)
void k4_sample(float* __restrict__ out)
{
    __shared__ int   sh_idx[32][16];
    __shared__ float sh_w[32][16];
    __shared__ float sh_t[32 * 289 + 8];

    const int tid = threadIdx.x;
    const int xt = blockIdx.x;
    const int y  = blockIdx.y;
    const int bb = blockIdx.z;
    const int x0 = xt * 32;

    if (tid < 128) {
        const int px = tid >> 2, p = tid & 3;
        const int x = x0 + px;
        const size_t pi = ((size_t)bb * HWHI + y * 128 + x) * 8;
        const float ox = g_offsets[pi + 2 * p]     * (1.0f / 64.0f);
        const float oy = g_offsets[pi + 2 * p + 1] * (1.0f / 64.0f);
        const float gx = fmaf((float)x, 2.0f / 127.0f, -1.0f) + ox;
        const float gy = fmaf((float)y, 2.0f / 127.0f, -1.0f) + oy;
        const float gxp = fminf(fmaxf(fmaf(gx, 32.0f, 31.5f), 0.0f), 63.0f);
        const float gyp = fminf(fmaxf(fmaf(gy, 32.0f, 31.5f), 0.0f), 63.0f);
        const float fx0 = floorf(gxp), fy0 = floorf(gyp);
        const int ix0 = (int)fx0, iy0 = (int)fy0;
        const float fx = gxp - fx0, fy = gyp - fy0;
        const int ix1 = (ix0 + 1 > 63) ? 63 : ix0 + 1;
        const int iy1 = (iy0 + 1 > 63) ? 63 : iy0 + 1;
        const int q = p * 4;
        sh_idx[px][q + 0] = (iy0 * 64 + ix0) * 32;
        sh_idx[px][q + 1] = (iy0 * 64 + ix1) * 32;
        sh_idx[px][q + 2] = (iy1 * 64 + ix0) * 32;
        sh_idx[px][q + 3] = (iy1 * 64 + ix1) * 32;
        sh_w[px][q + 0] = (1.f - fx) * (1.f - fy) * 0.25f;
        sh_w[px][q + 1] = fx * (1.f - fy) * 0.25f;
        sh_w[px][q + 2] = (1.f - fx) * fy * 0.25f;
        sh_w[px][q + 3] = fx * fy * 0.25f;
    }
    __syncthreads();

    const int lane = tid & 31, wrp = tid >> 5;
    const uint4* pb = (const uint4*)(g_proc16 + (size_t)bb * HWLO * 256) + lane;

#pragma unroll
    for (int r = 0; r < 4; ++r) {
        const int px = wrp * 4 + r;
        float acc[8];
#pragma unroll
        for (int j = 0; j < 8; ++j) acc[j] = 0.f;
#pragma unroll
        for (int t = 0; t < 16; ++t) {
            const float wt = sh_w[px][t];
            const uint4 u = pb[sh_idx[px][t]];
            float2 f0 = h2f(u.x), f1 = h2f(u.y), f2 = h2f(u.z), f3 = h2f(u.w);
            acc[0] = fmaf(wt, f0.x, acc[0]); acc[1] = fmaf(wt, f0.y, acc[1]);
            acc[2] = fmaf(wt, f1.x, acc[2]); acc[3] = fmaf(wt, f1.y, acc[3]);
            acc[4] = fmaf(wt, f2.x, acc[4]); acc[5] = fmaf(wt, f2.y, acc[5]);
            acc[6] = fmaf(wt, f3.x, acc[6]); acc[7] = fmaf(wt, f3.y, acc[7]);
        }
        float* dstp = &sh_t[px * 289 + lane * 9];
#pragma unroll
        for (int j = 0; j < 8; ++j) dstp[j] = acc[j];
    }
    __syncthreads();

    const int xl = tid & 31;
    const int c0 = tid >> 5;
#pragma unroll
    for (int i = 0; i < 32; ++i) {
        const int c = c0 * 32 + i;
        out[((size_t)bb * 256 + c) * HWHI + y * 128 + x0 + xl] =
            sh_t[xl * 289 + (c >> 3) * 9 + (c & 7)];
    }
}

// ===========================================================================
extern "C" void kernel_launch(void* const* d_in, const int* in_sizes, int n_in,
                              void* d_out, int out_size)
{
    const float* high = (const float*)d_in[0];
    const float* low  = (const float*)d_in[1];
    const float* W1   = (const float*)d_in[2];
    const float* b1   = (const float*)d_in[3];
    const float* W2   = (const float*)d_in[4];
    const float* b2   = (const float*)d_in[5];
    const float* Wf   = (const float*)d_in[6];
    const float* bf   = (const float*)d_in[7];
    float* out = (float*)d_out;

    const int SM_K1 = 98304;
    const int SM_K2 = 100352;
    const int SM_K5 = 73728;

    static cudaStream_t s2;
    static cudaEvent_t e_fork, e_join;
    static int inited = 0;
    if (!inited) {
        cudaFuncSetAttribute(k1f, cudaFuncAttributeMaxDynamicSharedMemorySize, SM_K1);
        cudaFuncSetAttribute(k2f, cudaFuncAttributeMaxDynamicSharedMemorySize, SM_K2);
        cudaFuncSetAttribute(k5f, cudaFuncAttributeMaxDynamicSharedMemorySize, SM_K5);
        cudaStreamCreateWithFlags(&s2, cudaStreamNonBlocking);
        cudaEventCreateWithFlags(&e_fork, cudaEventDisableTiming);
        cudaEventCreateWithFlags(&e_join, cudaEventDisableTiming);
        inited = 1;
    }

    // fork: k0t-low (DRAM-bound) runs on s2, parallel with the k1f chain on s0
    cudaEventRecord(e_fork, 0);
    cudaStreamWaitEvent(s2, e_fork, 0);
    k0t<<<dim3(256, 4, 8), 256, 0, s2>>>(low, 1, HWHI);
    cudaEventRecord(e_join, s2);

    k0t<<<dim3(64, 4, 8), 256>>>(high, 0, HWLO);
    k0w<<<848, 256>>>(W1, Wf, W2);
    k1f<<<dim3(256, 4), 256, SM_K1>>>(bf);

    // join: k2f needs both g_l16 (s2) and g_t16/g_wh (s0)
    cudaStreamWaitEvent(0, e_join, 0);
    k2f<<<dim3(1024, 2), 256, SM_K2>>>(b1);
    k5f<<<1024, 256, SM_K5>>>();
    k6_stencil<<<512, 256>>>(b2);
    k4_sample<<<dim3(4, 128, 8), 256>>>(out);
}

// round 12
// speedup vs baseline: 3.4072x; 1.2324x over previous
#include <cuda_runtime.h>
#include <cuda_fp16.h>

// ---------------------------------------------------------------------------
// AdaUp, fp16 mma.sync + cp.async. Fused pipeline (6 kernels):
//   s2: k0t-low || s0: k0t-high -> k0w -> k1f ; join -> k2f -> k4
//   K1f: t = W1a@high (fp16) ; proc = Wf@high + bf (fp16)
//   K2f: GEMM(W1b@low) -> fragment-direct epilogue (up2x(t)+b1, ReLU) ->
//        fp16 tile in smem -> in-CTA q-GEMM (W2 half-K) -> g_q16h[half]
//   K4 : phase A sums q halves (9-tap stencil + b2) -> 4-pt deformable sample
// ---------------------------------------------------------------------------

#define NB    8
#define HWLO  4096
#define HWHI  16384

__device__ __half g_h16[(size_t)NB * HWLO * 256];
__device__ __half g_l16[(size_t)NB * HWHI * 256];
__device__ __half g_wh[1024 * 256];
__device__ __half g_t16[(size_t)NB * HWLO * 256];
__device__ __half g_proc16[(size_t)NB * HWLO * 256];
__device__ __half g_q16h[2][(size_t)NB * HWHI * 72];

__device__ __forceinline__ unsigned smem_u32(const void* p) {
    unsigned a;
    asm("{ .reg .u64 t; cvta.to.shared.u64 t, %1; cvt.u32.u64 %0, t; }" : "=r"(a) : "l"(p));
    return a;
}
__device__ __forceinline__ unsigned sw128(unsigned o) { return o ^ ((o >> 3) & 0x70); }
__device__ __forceinline__ unsigned pack_h2(float lo, float hi) {
    unsigned u;
    asm("cvt.rn.f16x2.f32 %0, %1, %2;" : "=r"(u) : "f"(hi), "f"(lo));
    return u;
}
__device__ __forceinline__ void cpa16(unsigned dst, const void* src) {
    asm volatile("cp.async.cg.shared.global [%0], [%1], 16;" :: "r"(dst), "l"(src));
}
#define CP_COMMIT() asm volatile("cp.async.commit_group;" ::: "memory")
template <int N> __device__ __forceinline__ void cp_wait() {
    asm volatile("cp.async.wait_group %0;" :: "n"(N) : "memory");
}

#define LDSM_X4(r0, r1, r2, r3, addr) \
    asm volatile("ldmatrix.sync.aligned.m8n8.x4.shared.b16 {%0,%1,%2,%3}, [%4];" \
                 : "=r"(r0), "=r"(r1), "=r"(r2), "=r"(r3) : "r"(addr))
#define LDSM_X2(r0, r1, addr) \
    asm volatile("ldmatrix.sync.aligned.m8n8.x2.shared.b16 {%0,%1}, [%2];" \
                 : "=r"(r0), "=r"(r1) : "r"(addr))
#define MMA_F16(d, a, b) \
    asm volatile("mma.sync.aligned.m16n8k16.row.col.f32.f16.f16.f32 " \
                 "{%0,%1,%2,%3}, {%4,%5,%6,%7}, {%8,%9}, {%0,%1,%2,%3};" \
                 : "+f"((d)[0]), "+f"((d)[1]), "+f"((d)[2]), "+f"((d)[3]) \
                 : "r"((a)[0]), "r"((a)[1]), "r"((a)[2]), "r"((a)[3]), \
                   "r"((b)[0]), "r"((b)[1]))

__device__ __forceinline__ float2 h2f(unsigned u) {
    return __half22float2(*(const __half2*)&u);
}

// ===========================================================================
// K0t: [b][k][s] f32 -> [b][s][k] fp16
// ===========================================================================
__global__ __launch_bounds__(256)
void k0t(const float* __restrict__ src, int which, int S)
{
    __shared__ float ts[64][65];
    __half* dst = which ? g_l16 : g_h16;
    const int tid = threadIdx.x;
    const int s0 = blockIdx.x * 64, k0 = blockIdx.y * 64, b = blockIdx.z;
    const float* in = src + (size_t)b * 256 * S + (size_t)k0 * S + s0;
#pragma unroll
    for (int i = 0; i < 16; ++i) {
        const int idx = i * 256 + tid;
        const int kk = idx >> 6, ss = idx & 63;
        ts[ss][kk] = in[(size_t)kk * S + ss];
    }
    __syncthreads();
    unsigned* ob = (unsigned*)(dst + ((size_t)b * S + s0) * 256 + k0);
#pragma unroll
    for (int i = 0; i < 8; ++i) {
        const int idx = i * 256 + tid;
        const int ss = idx >> 5, kp = (idx & 31) * 2;
        ob[(size_t)ss * 128 + (kp >> 1)] = pack_h2(ts[ss][kp], ts[ss][kp + 1]);
    }
}

// ===========================================================================
// K0w: pack weights fp16 [row][256]
// rows: 0-255 W1a | 256-511 Wf | 512-767 W1b | 768-839 W2(tap*8+o) | 840-847 0
// ===========================================================================
__global__ __launch_bounds__(256)
void k0w(const float* __restrict__ W1, const float* __restrict__ Wf,
         const float* __restrict__ W2)
{
    const int row = blockIdx.x, c = threadIdx.x;
    float v = 0.f;
    if (row < 256)      v = W1[(size_t)row * 512 + c];
    else if (row < 512) v = Wf[(size_t)(row - 256) * 256 + c];
    else if (row < 768) v = W1[(size_t)(row - 512) * 512 + 256 + c];
    else if (row < 840) {
        const int t = (row - 768) >> 3, o = (row - 768) & 7;
        v = W2[(size_t)o * 2304 + c * 9 + t];
    }
    g_wh[(size_t)row * 256 + c] = __float2half(v);
}

// ===========================================================================
// cp.async one 64-k A chunk (128 rows x 128 bytes)
// ===========================================================================
__device__ __forceinline__ void load_A_chunk(unsigned bufA, const __half* A16,
                                             int kt, int tid)
{
    const int row = tid >> 1, c4 = (tid & 1) * 4;
#pragma unroll
    for (int j = 0; j < 4; ++j) {
        const int c = c4 + j;
        cpa16(bufA + sw128(row * 128 + c * 16), A16 + (size_t)row * 256 + kt * 64 + c * 8);
    }
}

// ===========================================================================
// K1f: [t | proc] = [W1a | Wf] @ high ; grid (256, 4)
// ===========================================================================
__global__ __launch_bounds__(256, 2)
void k1f(const float* __restrict__ bf)
{
    extern __shared__ char dsm[];
    const unsigned sb = smem_u32(dsm), sbB = sb + 32768;
    const int tid = threadIdx.x, lane = tid & 31, warp = tid >> 5;
    const int wm = warp & 1, wn = warp >> 1;
    const int m0 = blockIdx.x * 128;
    const int ny = blockIdx.y >> 1, nhalf = blockIdx.y & 1;
    const int bb = m0 >> 12, s0 = m0 & 4095;
    const int brow0 = ny * 256 + nhalf * 128;

    const __half* A16 = g_h16 + ((size_t)bb * HWLO + s0) * 256;

    unsigned aoff[4], boff[2];
#pragma unroll
    for (int mt = 0; mt < 4; ++mt)
        aoff[mt] = ((unsigned)(wm * 64 + mt * 16 + (lane & 15)) << 7) + (lane >> 4) * 16;
#pragma unroll
    for (int p = 0; p < 2; ++p)
        boff[p] = ((unsigned)(wn * 32 + p * 16 + (lane & 7) + ((lane >> 4) & 1) * 8) << 7)
                  + ((lane >> 3) & 1) * 16;

    float d[4][4][4];
#pragma unroll
    for (int i = 0; i < 4; ++i)
#pragma unroll
        for (int j = 0; j < 4; ++j)
#pragma unroll
            for (int e = 0; e < 4; ++e) d[i][j][e] = 0.f;

#pragma unroll
    for (int i = 0; i < 16; ++i) {
        const int idx = i * 256 + tid;
        const int n = idx >> 5, c = idx & 31;
        cpa16(sbB + (c >> 3) * 16384 + sw128(n * 128 + (c & 7) * 16),
              g_wh + (size_t)(brow0 + n) * 256 + c * 8);
    }
    load_A_chunk(sb, A16, 0, tid);
    CP_COMMIT();
    load_A_chunk(sb + 16384, A16, 1, tid);
    CP_COMMIT();

    for (int kt = 0; kt < 4; ++kt) {
        if (kt < 3) cp_wait<1>(); else cp_wait<0>();
        __syncthreads();
        const unsigned bufA = sb + (kt & 1) * 16384;
        const unsigned bufB = sbB + kt * 16384;
#pragma unroll
        for (int ks = 0; ks < 4; ++ks) {
            const unsigned ksb = ks * 32;
            unsigned a[4][4], b[4][2];
#pragma unroll
            for (int mt = 0; mt < 4; ++mt)
                LDSM_X4(a[mt][0], a[mt][1], a[mt][2], a[mt][3], bufA + sw128(aoff[mt] + ksb));
            LDSM_X4(b[0][0], b[0][1], b[1][0], b[1][1], bufB + sw128(boff[0] + ksb));
            LDSM_X4(b[2][0], b[2][1], b[3][0], b[3][1], bufB + sw128(boff[1] + ksb));
#pragma unroll
            for (int mt = 0; mt < 4; ++mt)
#pragma unroll
                for (int nt = 0; nt < 4; ++nt)
                    MMA_F16(d[mt][nt], a[mt], b[nt]);
        }
        __syncthreads();
        if (kt < 2) { load_A_chunk(sb + (kt & 1) * 16384, A16, kt + 2, tid); CP_COMMIT(); }
    }

#pragma unroll
    for (int mt = 0; mt < 4; ++mt) {
        const int row = m0 + wm * 64 + mt * 16 + (lane >> 2);
#pragma unroll
        for (int nt = 0; nt < 4; ++nt) {
            const int col = nhalf * 128 + wn * 32 + nt * 8 + (lane & 3) * 2;
            if (ny == 0) {
                *(unsigned*)&g_t16[(size_t)row * 256 + col] =
                    pack_h2(d[mt][nt][0], d[mt][nt][1]);
                *(unsigned*)&g_t16[(size_t)(row + 8) * 256 + col] =
                    pack_h2(d[mt][nt][2], d[mt][nt][3]);
            } else {
                const float b0 = bf[col], b1 = bf[col + 1];
                *(unsigned*)&g_proc16[(size_t)row * 256 + col] =
                    pack_h2(d[mt][nt][0] + b0, d[mt][nt][1] + b1);
                *(unsigned*)&g_proc16[(size_t)(row + 8) * 256 + col] =
                    pack_h2(d[mt][nt][2] + b0, d[mt][nt][3] + b1);
            }
        }
    }
}

// ===========================================================================
// K2f: GEMM W1b@low + fragment-direct epilogue -> fp16 off tile in smem ->
//      in-CTA q-GEMM (W2 half-K) -> g_q16h[blockIdx.y]
// grid (1024, 2). Dyn smem 98304, 2 CTA/SM.
// smem phases:
//   mainloop: A0 @0, A1 @16384, B @32768 (4x16K)
//   post:     t-rows @0 (32K) | qA tiles @32768 (2x16K) | W2 B @65536 (2x10240)
// ===========================================================================
__global__ __launch_bounds__(256, 2)
void k2f(const float* __restrict__ b1)
{
    extern __shared__ char dsm[];
    const unsigned sb = smem_u32(dsm), sbB = sb + 32768;
    const int tid = threadIdx.x, lane = tid & 31, warp = tid >> 5;
    const int wm = warp & 1, wn = warp >> 1;
    const int m0 = blockIdx.x * 128;
    const int n0 = blockIdx.y * 128;
    const int bb = m0 >> 14, s0 = m0 & 16383;
    const int brow0 = 512 + n0;

    const __half* A16 = g_l16 + ((size_t)bb * HWHI + s0) * 256;

    unsigned aoff[4], boff[2];
#pragma unroll
    for (int mt = 0; mt < 4; ++mt)
        aoff[mt] = ((unsigned)(wm * 64 + mt * 16 + (lane & 15)) << 7) + (lane >> 4) * 16;
#pragma unroll
    for (int p = 0; p < 2; ++p)
        boff[p] = ((unsigned)(wn * 32 + p * 16 + (lane & 7) + ((lane >> 4) & 1) * 8) << 7)
                  + ((lane >> 3) & 1) * 16;

    float d[4][4][4];
#pragma unroll
    for (int i = 0; i < 4; ++i)
#pragma unroll
        for (int j = 0; j < 4; ++j)
#pragma unroll
            for (int e = 0; e < 4; ++e) d[i][j][e] = 0.f;

#pragma unroll
    for (int i = 0; i < 16; ++i) {
        const int idx = i * 256 + tid;
        const int n = idx >> 5, c = idx & 31;
        cpa16(sbB + (c >> 3) * 16384 + sw128(n * 128 + (c & 7) * 16),
              g_wh + (size_t)(brow0 + n) * 256 + c * 8);
    }
    load_A_chunk(sb, A16, 0, tid);
    CP_COMMIT();
    load_A_chunk(sb + 16384, A16, 1, tid);
    CP_COMMIT();

    for (int kt = 0; kt < 4; ++kt) {
        if (kt < 3) cp_wait<1>(); else cp_wait<0>();
        __syncthreads();
        const unsigned bufA = sb + (kt & 1) * 16384;
        const unsigned bufB = sbB + kt * 16384;
#pragma unroll
        for (int ks = 0; ks < 4; ++ks) {
            const unsigned ksb = ks * 32;
            unsigned a[4][4], b[4][2];
#pragma unroll
            for (int mt = 0; mt < 4; ++mt)
                LDSM_X4(a[mt][0], a[mt][1], a[mt][2], a[mt][3], bufA + sw128(aoff[mt] + ksb));
            LDSM_X4(b[0][0], b[0][1], b[1][0], b[1][1], bufB + sw128(boff[0] + ksb));
            LDSM_X4(b[2][0], b[2][1], b[3][0], b[3][1], bufB + sw128(boff[1] + ksb));
#pragma unroll
            for (int mt = 0; mt < 4; ++mt)
#pragma unroll
                for (int nt = 0; nt < 4; ++nt)
                    MMA_F16(d[mt][nt], a[mt], b[nt]);
        }
        __syncthreads();
        if (kt < 2) { load_A_chunk(sb + (kt & 1) * 16384, A16, kt + 2, tid); CP_COMMIT(); }
    }

    // ---- post-mainloop: all buffers dead. Stage t-rows @0, cp.async W2 @65536.
    __syncthreads();
    const int yy = s0 >> 7;
    int jy0_, jy1_;
    float wy0, wy1;
    if (yy & 1) { jy0_ = yy >> 1; jy1_ = ((yy >> 1) + 1 > 63) ? 63 : (yy >> 1) + 1; wy0 = 0.75f; wy1 = 0.25f; }
    else        { jy0_ = ((yy >> 1) - 1 < 0) ? 0 : (yy >> 1) - 1; jy1_ = yy >> 1;   wy0 = 0.25f; wy1 = 0.75f; }

    {
        const __half* tb = g_t16 + (size_t)bb * HWLO * 256;
        uint4* tst = (uint4*)dsm;
#pragma unroll
        for (int i = 0; i < 8; ++i) {
            const int idx = i * 256 + tid;
            const int r = idx >> 10, rest = idx & 1023;
            const int j = rest >> 4, cc = rest & 15;
            const int jy = r ? jy1_ : jy0_;
            tst[idx] = *(const uint4*)(tb + (size_t)(jy * 64 + j) * 256 + n0 + cc * 8);
        }
    }
    // W2 half-K B tiles: 2 chunks x 80 rows x 128B
#pragma unroll
    for (int i = 0; i < 5; ++i) {
        const int idx = i * 256 + tid;          // 0..1279
        const int ck = idx >= 640;
        const int rest = idx - ck * 640;
        const int n = rest >> 3, c8 = rest & 7;
        cpa16(sb + 65536 + ck * 10240 + sw128(n * 128 + c8 * 16),
              g_wh + (size_t)(768 + n) * 256 + n0 + ck * 64 + c8 * 8);
    }
    CP_COMMIT();
    __syncthreads();   // t-rows visible; qA region free to write

    // ---- fragment-direct epilogue: relu(acc + b1 + up2x(t)) -> fp16 qA tiles
    const __half* r0p = (const __half*)dsm;
    const __half* r1p = (const __half*)dsm + 8192;
#pragma unroll
    for (int mt = 0; mt < 4; ++mt) {
#pragma unroll
        for (int h = 0; h < 2; ++h) {
            const int r = wm * 64 + mt * 16 + (lane >> 2) + h * 8;   // pixel x
            const int tw = r >> 1;
            int jx0, jx1;
            float wx0, wx1;
            if (r & 1) { jx0 = tw; jx1 = (tw + 1 > 63) ? 63 : tw + 1; wx0 = 0.75f; wx1 = 0.25f; }
            else       { jx0 = (tw - 1 < 0) ? 0 : tw - 1; jx1 = tw;   wx0 = 0.25f; wx1 = 0.75f; }
            const float wa = wy0 * wx0, wb_ = wy0 * wx1, wc = wy1 * wx0, wd = wy1 * wx1;
#pragma unroll
            for (int nt = 0; nt < 4; ++nt) {
                const int col = wn * 32 + nt * 8 + (lane & 3) * 2;
                float2 bv = *(const float2*)&b1[n0 + col];
                float2 f00 = h2f(*(const unsigned*)&r0p[jx0 * 128 + col]);
                float2 f01 = h2f(*(const unsigned*)&r0p[jx1 * 128 + col]);
                float2 f10 = h2f(*(const unsigned*)&r1p[jx0 * 128 + col]);
                float2 f11 = h2f(*(const unsigned*)&r1p[jx1 * 128 + col]);
                float o0 = fmaxf(d[mt][nt][h * 2 + 0] + bv.x +
                                 wa * f00.x + wb_ * f01.x + wc * f10.x + wd * f11.x, 0.f);
                float o1 = fmaxf(d[mt][nt][h * 2 + 1] + bv.y +
                                 wa * f00.y + wb_ * f01.y + wc * f10.y + wd * f11.y, 0.f);
                *(unsigned*)(dsm + 32768 + (col >> 6) * 16384 +
                             sw128((unsigned)r * 128 + (col & 63) * 2)) = pack_h2(o0, o1);
            }
        }
    }
    cp_wait<0>();
    __syncthreads();   // qA tiles + W2 tiles ready

    // ---- in-CTA q-GEMM: q_half[128 x 80] = offtile @ W2halfK, K=128
    const int wm2 = warp >> 1, wn2 = warp & 1;
    unsigned aoff2[2], boffp2[2], boffs2;
#pragma unroll
    for (int mt = 0; mt < 2; ++mt)
        aoff2[mt] = ((unsigned)(wm2 * 32 + mt * 16 + (lane & 15)) << 7) + (lane >> 4) * 16;
#pragma unroll
    for (int p = 0; p < 2; ++p)
        boffp2[p] = ((unsigned)(wn2 * 40 + p * 16 + (lane & 7) + ((lane >> 4) & 1) * 8) << 7)
                    + ((lane >> 3) & 1) * 16;
    boffs2 = ((unsigned)(wn2 * 40 + 32 + (lane & 7)) << 7) + ((lane >> 3) & 1) * 16;

    float dq[2][5][4];
#pragma unroll
    for (int i = 0; i < 2; ++i)
#pragma unroll
        for (int j = 0; j < 5; ++j)
#pragma unroll
            for (int e = 0; e < 4; ++e) dq[i][j][e] = 0.f;

#pragma unroll
    for (int ck = 0; ck < 2; ++ck) {
        const unsigned bufA = sb + 32768 + ck * 16384;
        const unsigned bufB = sb + 65536 + ck * 10240;
#pragma unroll
        for (int ks = 0; ks < 4; ++ks) {
            const unsigned ksb = ks * 32;
            unsigned a[2][4], b[5][2];
#pragma unroll
            for (int mt = 0; mt < 2; ++mt)
                LDSM_X4(a[mt][0], a[mt][1], a[mt][2], a[mt][3], bufA + sw128(aoff2[mt] + ksb));
            LDSM_X4(b[0][0], b[0][1], b[1][0], b[1][1], bufB + sw128(boffp2[0] + ksb));
            LDSM_X4(b[2][0], b[2][1], b[3][0], b[3][1], bufB + sw128(boffp2[1] + ksb));
            LDSM_X2(b[4][0], b[4][1], bufB + sw128(boffs2 + ksb));
#pragma unroll
            for (int mt = 0; mt < 2; ++mt)
#pragma unroll
                for (int nt = 0; nt < 5; ++nt)
                    MMA_F16(dq[mt][nt], a[mt], b[nt]);
        }
    }

    __half* gq = g_q16h[blockIdx.y];
#pragma unroll
    for (int mt = 0; mt < 2; ++mt) {
        const int row = m0 + wm2 * 32 + mt * 16 + (lane >> 2);
#pragma unroll
        for (int nt = 0; nt < 5; ++nt) {
            const int col = wn2 * 40 + nt * 8 + (lane & 3) * 2;
            if (col < 72) {
                *(unsigned*)&gq[(size_t)row * 72 + col] = pack_h2(dq[mt][nt][0], dq[mt][nt][1]);
                *(unsigned*)&gq[(size_t)(row + 8) * 72 + col] = pack_h2(dq[mt][nt][2], dq[mt][nt][3]);
            }
        }
    }
}

// ===========================================================================
// K4: phase A = fused offset stencil (b2 + 9-tap sum of q halves), then
//     4-point deformable bilinear sample of fp16 proc (uint4 taps).
// ===========================================================================
__global__ __launch_bounds__(256)
void k4_sample(const float* __restrict__ b2, float* __restrict__ out)
{
    __shared__ int   sh_idx[32][16];
    __shared__ float sh_w[32][16];
    __shared__ float sh_t[32 * 289 + 8];

    const int tid = threadIdx.x;
    const int xt = blockIdx.x;
    const int y  = blockIdx.y;
    const int bb = blockIdx.z;
    const int x0 = xt * 32;

    if (tid < 128) {
        const int px = tid >> 2, p = tid & 3;
        const int x = x0 + px;
        // fused k6: offsets = b2 + sum over 9 taps of (q_lo + q_hi)
        float ax = b2[2 * p], ay = b2[2 * p + 1];
#pragma unroll
        for (int dy = 0; dy < 3; ++dy) {
            const int yyt = y + dy - 1;
            if (yyt < 0 || yyt > 127) continue;
#pragma unroll
            for (int dx = 0; dx < 3; ++dx) {
                const int xxt = x + dx - 1;
                if (xxt < 0 || xxt > 127) continue;
                const size_t qi = ((size_t)bb * HWHI + yyt * 128 + xxt) * 72
                                  + (dy * 3 + dx) * 8 + 2 * p;
                float2 flo = h2f(*(const unsigned*)&g_q16h[0][qi]);
                float2 fhi = h2f(*(const unsigned*)&g_q16h[1][qi]);
                ax += flo.x + fhi.x;
                ay += flo.y + fhi.y;
            }
        }
        const float ox = ax * (1.0f / 64.0f);
        const float oy = ay * (1.0f / 64.0f);
        const float gx = fmaf((float)x, 2.0f / 127.0f, -1.0f) + ox;
        const float gy = fmaf((float)y, 2.0f / 127.0f, -1.0f) + oy;
        const float gxp = fminf(fmaxf(fmaf(gx, 32.0f, 31.5f), 0.0f), 63.0f);
        const float gyp = fminf(fmaxf(fmaf(gy, 32.0f, 31.5f), 0.0f), 63.0f);
        const float fx0 = floorf(gxp), fy0 = floorf(gyp);
        const int ix0 = (int)fx0, iy0 = (int)fy0;
        const float fx = gxp - fx0, fy = gyp - fy0;
        const int ix1 = (ix0 + 1 > 63) ? 63 : ix0 + 1;
        const int iy1 = (iy0 + 1 > 63) ? 63 : iy0 + 1;
        const int q = p * 4;
        sh_idx[px][q + 0] = (iy0 * 64 + ix0) * 32;
        sh_idx[px][q + 1] = (iy0 * 64 + ix1) * 32;
        sh_idx[px][q + 2] = (iy1 * 64 + ix0) * 32;
        sh_idx[px][q + 3] = (iy1 * 64 + ix1) * 32;
        sh_w[px][q + 0] = (1.f - fx) * (1.f - fy) * 0.25f;
        sh_w[px][q + 1] = fx * (1.f - fy) * 0.25f;
        sh_w[px][q + 2] = (1.f - fx) * fy * 0.25f;
        sh_w[px][q + 3] = fx * fy * 0.25f;
    }
    __syncthreads();

    const int lane = tid & 31, wrp = tid >> 5;
    const uint4* pb = (const uint4*)(g_proc16 + (size_t)bb * HWLO * 256) + lane;

#pragma unroll
    for (int r = 0; r < 4; ++r) {
        const int px = wrp * 4 + r;
        float acc[8];
#pragma unroll
        for (int j = 0; j < 8; ++j) acc[j] = 0.f;
#pragma unroll
        for (int t = 0; t < 16; ++t) {
            const float wt = sh_w[px][t];
            const uint4 u = pb[sh_idx[px][t]];
            float2 f0 = h2f(u.x), f1 = h2f(u.y), f2 = h2f(u.z), f3 = h2f(u.w);
            acc[0] = fmaf(wt, f0.x, acc[0]); acc[1] = fmaf(wt, f0.y, acc[1]);
            acc[2] = fmaf(wt, f1.x, acc[2]); acc[3] = fmaf(wt, f1.y, acc[3]);
            acc[4] = fmaf(wt, f2.x, acc[4]); acc[5] = fmaf(wt, f2.y, acc[5]);
            acc[6] = fmaf(wt, f3.x, acc[6]); acc[7] = fmaf(wt, f3.y, acc[7]);
        }
        float* dstp = &sh_t[px * 289 + lane * 9];
#pragma unroll
        for (int j = 0; j < 8; ++j) dstp[j] = acc[j];
    }
    __syncthreads();

    const int xl = tid & 31;
    const int c0 = tid >> 5;
#pragma unroll
    for (int i = 0; i < 32; ++i) {
        const int c = c0 * 32 + i;
        out[((size_t)bb * 256 + c) * HWHI + y * 128 + x0 + xl] =
            sh_t[xl * 289 + (c >> 3) * 9 + (c & 7)];
    }
}

// ===========================================================================
extern "C" void kernel_launch(void* const* d_in, const int* in_sizes, int n_in,
                              void* d_out, int out_size)
{
    const float* high = (const float*)d_in[0];
    const float* low  = (const float*)d_in[1];
    const float* W1   = (const float*)d_in[2];
    const float* b1   = (const float*)d_in[3];
    const float* W2   = (const float*)d_in[4];
    const float* b2   = (const float*)d_in[5];
    const float* Wf   = (const float*)d_in[6];
    const float* bf   = (const float*)d_in[7];
    float* out = (float*)d_out;

    const int SM_K1 = 98304;
    const int SM_K2 = 98304;

    static cudaStream_t s2;
    static cudaEvent_t e_fork, e_join;
    static int inited = 0;
    if (!inited) {
        cudaFuncSetAttribute(k1f, cudaFuncAttributeMaxDynamicSharedMemorySize, SM_K1);
        cudaFuncSetAttribute(k2f, cudaFuncAttributeMaxDynamicSharedMemorySize, SM_K2);
        cudaStreamCreateWithFlags(&s2, cudaStreamNonBlocking);
        cudaEventCreateWithFlags(&e_fork, cudaEventDisableTiming);
        cudaEventCreateWithFlags(&e_join, cudaEventDisableTiming);
        inited = 1;
    }

    // fork: k0t-low runs on s2, parallel with the k1f chain on s0
    cudaEventRecord(e_fork, 0);
    cudaStreamWaitEvent(s2, e_fork, 0);
    k0t<<<dim3(256, 4, 8), 256, 0, s2>>>(low, 1, HWHI);
    cudaEventRecord(e_join, s2);

    k0t<<<dim3(64, 4, 8), 256>>>(high, 0, HWLO);
    k0w<<<848, 256>>>(W1, Wf, W2);
    k1f<<<dim3(256, 4), 256, SM_K1>>>(bf);

    cudaStreamWaitEvent(0, e_join, 0);
    k2f<<<dim3(1024, 2), 256, SM_K2>>>(b1);
    k4_sample<<<dim3(4, 128, 8), 256>>>(b2, out);
}

// round 13
// speedup vs baseline: 3.4236x; 1.0048x over previous
#include <cuda_runtime.h>
#include <cuda_fp16.h>

// ---------------------------------------------------------------------------
// AdaUp, fp16 mma.sync + cp.async. Fused pipeline (6 kernels):
//   s2: k0t-low || s0: k0t-high -> k0w -> k1f ; join -> k2f -> k4
//   K1f: t = W1a@high (fp16) ; proc = Wf@high + bf (fp16)
//   K2f: GEMM(W1b@low) -> fragment-direct epilogue (up2x(t)+b1, ReLU) ->
//        fp16 tile in smem -> in-CTA q-GEMM (W2 half-K) -> g_q16h[half]
//   K4 : phase A sums q halves (9-tap stencil + b2) -> 4-pt deformable sample
// ---------------------------------------------------------------------------

#define NB    8
#define HWLO  4096
#define HWHI  16384

__device__ __half g_h16[(size_t)NB * HWLO * 256];
__device__ __half g_l16[(size_t)NB * HWHI * 256];
__device__ __half g_wh[1024 * 256];
__device__ __half g_t16[(size_t)NB * HWLO * 256];
__device__ __half g_proc16[(size_t)NB * HWLO * 256];
__device__ __half g_q16h[2][(size_t)NB * HWHI * 72];

__device__ __forceinline__ unsigned smem_u32(const void* p) {
    unsigned a;
    asm("{ .reg .u64 t; cvta.to.shared.u64 t, %1; cvt.u32.u64 %0, t; }" : "=r"(a) : "l"(p));
    return a;
}
__device__ __forceinline__ unsigned sw128(unsigned o) { return o ^ ((o >> 3) & 0x70); }
__device__ __forceinline__ unsigned pack_h2(float lo, float hi) {
    unsigned u;
    asm("cvt.rn.f16x2.f32 %0, %1, %2;" : "=r"(u) : "f"(hi), "f"(lo));
    return u;
}
__device__ __forceinline__ void cpa16(unsigned dst, const void* src) {
    asm volatile("cp.async.cg.shared.global [%0], [%1], 16;" :: "r"(dst), "l"(src));
}
#define CP_COMMIT() asm volatile("cp.async.commit_group;" ::: "memory")
template <int N> __device__ __forceinline__ void cp_wait() {
    asm volatile("cp.async.wait_group %0;" :: "n"(N) : "memory");
}

#define LDSM_X4(r0, r1, r2, r3, addr) \
    asm volatile("ldmatrix.sync.aligned.m8n8.x4.shared.b16 {%0,%1,%2,%3}, [%4];" \
                 : "=r"(r0), "=r"(r1), "=r"(r2), "=r"(r3) : "r"(addr))
#define LDSM_X2(r0, r1, addr) \
    asm volatile("ldmatrix.sync.aligned.m8n8.x2.shared.b16 {%0,%1}, [%2];" \
                 : "=r"(r0), "=r"(r1) : "r"(addr))
#define MMA_F16(d, a, b) \
    asm volatile("mma.sync.aligned.m16n8k16.row.col.f32.f16.f16.f32 " \
                 "{%0,%1,%2,%3}, {%4,%5,%6,%7}, {%8,%9}, {%0,%1,%2,%3};" \
                 : "+f"((d)[0]), "+f"((d)[1]), "+f"((d)[2]), "+f"((d)[3]) \
                 : "r"((a)[0]), "r"((a)[1]), "r"((a)[2]), "r"((a)[3]), \
                   "r"((b)[0]), "r"((b)[1]))

__device__ __forceinline__ float2 h2f(unsigned u) {
    return __half22float2(*(const __half2*)&u);
}

// ===========================================================================
// K0t: [b][k][s] f32 -> [b][s][k] fp16
// ===========================================================================
__global__ __launch_bounds__(256)
void k0t(const float* __restrict__ src, int which, int S)
{
    __shared__ float ts[64][65];
    __half* dst = which ? g_l16 : g_h16;
    const int tid = threadIdx.x;
    const int s0 = blockIdx.x * 64, k0 = blockIdx.y * 64, b = blockIdx.z;
    const float* in = src + (size_t)b * 256 * S + (size_t)k0 * S + s0;
#pragma unroll
    for (int i = 0; i < 16; ++i) {
        const int idx = i * 256 + tid;
        const int kk = idx >> 6, ss = idx & 63;
        ts[ss][kk] = in[(size_t)kk * S + ss];
    }
    __syncthreads();
    unsigned* ob = (unsigned*)(dst + ((size_t)b * S + s0) * 256 + k0);
#pragma unroll
    for (int i = 0; i < 8; ++i) {
        const int idx = i * 256 + tid;
        const int ss = idx >> 5, kp = (idx & 31) * 2;
        ob[(size_t)ss * 128 + (kp >> 1)] = pack_h2(ts[ss][kp], ts[ss][kp + 1]);
    }
}

// ===========================================================================
// K0w: pack weights fp16 [row][256]
// rows: 0-255 W1a | 256-511 Wf | 512-767 W1b | 768-839 W2(tap*8+o) | 840-847 0
// ===========================================================================
__global__ __launch_bounds__(256)
void k0w(const float* __restrict__ W1, const float* __restrict__ Wf,
         const float* __restrict__ W2)
{
    const int row = blockIdx.x, c = threadIdx.x;
    float v = 0.f;
    if (row < 256)      v = W1[(size_t)row * 512 + c];
    else if (row < 512) v = Wf[(size_t)(row - 256) * 256 + c];
    else if (row < 768) v = W1[(size_t)(row - 512) * 512 + 256 + c];
    else if (row < 840) {
        const int t = (row - 768) >> 3, o = (row - 768) & 7;
        v = W2[(size_t)o * 2304 + c * 9 + t];
    }
    g_wh[(size_t)row * 256 + c] = __float2half(v);
}

// ===========================================================================
// cp.async one 64-k A chunk (128 rows x 128 bytes)
// ===========================================================================
__device__ __forceinline__ void load_A_chunk(unsigned bufA, const __half* A16,
                                             int kt, int tid)
{
    const int row = tid >> 1, c4 = (tid & 1) * 4;
#pragma unroll
    for (int j = 0; j < 4; ++j) {
        const int c = c4 + j;
        cpa16(bufA + sw128(row * 128 + c * 16), A16 + (size_t)row * 256 + kt * 64 + c * 8);
    }
}

// ===========================================================================
// K1f: [t | proc] = [W1a | Wf] @ high ; grid (256, 4)
// ===========================================================================
__global__ __launch_bounds__(256, 2)
void k1f(const float* __restrict__ bf)
{
    extern __shared__ char dsm[];
    const unsigned sb = smem_u32(dsm), sbB = sb + 32768;
    const int tid = threadIdx.x, lane = tid & 31, warp = tid >> 5;
    const int wm = warp & 1, wn = warp >> 1;
    const int m0 = blockIdx.x * 128;
    const int ny = blockIdx.y >> 1, nhalf = blockIdx.y & 1;
    const int bb = m0 >> 12, s0 = m0 & 4095;
    const int brow0 = ny * 256 + nhalf * 128;

    const __half* A16 = g_h16 + ((size_t)bb * HWLO + s0) * 256;

    unsigned aoff[4], boff[2];
#pragma unroll
    for (int mt = 0; mt < 4; ++mt)
        aoff[mt] = ((unsigned)(wm * 64 + mt * 16 + (lane & 15)) << 7) + (lane >> 4) * 16;
#pragma unroll
    for (int p = 0; p < 2; ++p)
        boff[p] = ((unsigned)(wn * 32 + p * 16 + (lane & 7) + ((lane >> 4) & 1) * 8) << 7)
                  + ((lane >> 3) & 1) * 16;

    float d[4][4][4];
#pragma unroll
    for (int i = 0; i < 4; ++i)
#pragma unroll
        for (int j = 0; j < 4; ++j)
#pragma unroll
            for (int e = 0; e < 4; ++e) d[i][j][e] = 0.f;

#pragma unroll
    for (int i = 0; i < 16; ++i) {
        const int idx = i * 256 + tid;
        const int n = idx >> 5, c = idx & 31;
        cpa16(sbB + (c >> 3) * 16384 + sw128(n * 128 + (c & 7) * 16),
              g_wh + (size_t)(brow0 + n) * 256 + c * 8);
    }
    load_A_chunk(sb, A16, 0, tid);
    CP_COMMIT();
    load_A_chunk(sb + 16384, A16, 1, tid);
    CP_COMMIT();

    for (int kt = 0; kt < 4; ++kt) {
        if (kt < 3) cp_wait<1>(); else cp_wait<0>();
        __syncthreads();
        const unsigned bufA = sb + (kt & 1) * 16384;
        const unsigned bufB = sbB + kt * 16384;
#pragma unroll
        for (int ks = 0; ks < 4; ++ks) {
            const unsigned ksb = ks * 32;
            unsigned a[4][4], b[4][2];
#pragma unroll
            for (int mt = 0; mt < 4; ++mt)
                LDSM_X4(a[mt][0], a[mt][1], a[mt][2], a[mt][3], bufA + sw128(aoff[mt] + ksb));
            LDSM_X4(b[0][0], b[0][1], b[1][0], b[1][1], bufB + sw128(boff[0] + ksb));
            LDSM_X4(b[2][0], b[2][1], b[3][0], b[3][1], bufB + sw128(boff[1] + ksb));
#pragma unroll
            for (int mt = 0; mt < 4; ++mt)
#pragma unroll
                for (int nt = 0; nt < 4; ++nt)
                    MMA_F16(d[mt][nt], a[mt], b[nt]);
        }
        __syncthreads();
        if (kt < 2) { load_A_chunk(sb + (kt & 1) * 16384, A16, kt + 2, tid); CP_COMMIT(); }
    }

#pragma unroll
    for (int mt = 0; mt < 4; ++mt) {
        const int row = m0 + wm * 64 + mt * 16 + (lane >> 2);
#pragma unroll
        for (int nt = 0; nt < 4; ++nt) {
            const int col = nhalf * 128 + wn * 32 + nt * 8 + (lane & 3) * 2;
            if (ny == 0) {
                *(unsigned*)&g_t16[(size_t)row * 256 + col] =
                    pack_h2(d[mt][nt][0], d[mt][nt][1]);
                *(unsigned*)&g_t16[(size_t)(row + 8) * 256 + col] =
                    pack_h2(d[mt][nt][2], d[mt][nt][3]);
            } else {
                const float b0 = bf[col], b1 = bf[col + 1];
                *(unsigned*)&g_proc16[(size_t)row * 256 + col] =
                    pack_h2(d[mt][nt][0] + b0, d[mt][nt][1] + b1);
                *(unsigned*)&g_proc16[(size_t)(row + 8) * 256 + col] =
                    pack_h2(d[mt][nt][2] + b0, d[mt][nt][3] + b1);
            }
        }
    }
}

// ===========================================================================
// K2f: GEMM W1b@low + fragment-direct epilogue -> fp16 off tile in smem ->
//      in-CTA q-GEMM (W2 half-K) -> g_q16h[blockIdx.y]
// grid (1024, 2). Dyn smem 98304, 2 CTA/SM.
// smem phases:
//   mainloop: A0 @0, A1 @16384, B @32768 (4x16K)
//   post:     t-rows @0 (32K) | qA tiles @32768 (2x16K) | W2 B @65536 (2x10240)
// ===========================================================================
__global__ __launch_bounds__(256, 2)
void k2f(const float* __restrict__ b1)
{
    extern __shared__ char dsm[];
    const unsigned sb = smem_u32(dsm), sbB = sb + 32768;
    const int tid = threadIdx.x, lane = tid & 31, warp = tid >> 5;
    const int wm = warp & 1, wn = warp >> 1;
    const int m0 = blockIdx.x * 128;
    const int n0 = blockIdx.y * 128;
    const int bb = m0 >> 14, s0 = m0 & 16383;
    const int brow0 = 512 + n0;

    const __half* A16 = g_l16 + ((size_t)bb * HWHI + s0) * 256;

    unsigned aoff[4], boff[2];
#pragma unroll
    for (int mt = 0; mt < 4; ++mt)
        aoff[mt] = ((unsigned)(wm * 64 + mt * 16 + (lane & 15)) << 7) + (lane >> 4) * 16;
#pragma unroll
    for (int p = 0; p < 2; ++p)
        boff[p] = ((unsigned)(wn * 32 + p * 16 + (lane & 7) + ((lane >> 4) & 1) * 8) << 7)
                  + ((lane >> 3) & 1) * 16;

    float d[4][4][4];
#pragma unroll
    for (int i = 0; i < 4; ++i)
#pragma unroll
        for (int j = 0; j < 4; ++j)
#pragma unroll
            for (int e = 0; e < 4; ++e) d[i][j][e] = 0.f;

#pragma unroll
    for (int i = 0; i < 16; ++i) {
        const int idx = i * 256 + tid;
        const int n = idx >> 5, c = idx & 31;
        cpa16(sbB + (c >> 3) * 16384 + sw128(n * 128 + (c & 7) * 16),
              g_wh + (size_t)(brow0 + n) * 256 + c * 8);
    }
    load_A_chunk(sb, A16, 0, tid);
    CP_COMMIT();
    load_A_chunk(sb + 16384, A16, 1, tid);
    CP_COMMIT();

    for (int kt = 0; kt < 4; ++kt) {
        if (kt < 3) cp_wait<1>(); else cp_wait<0>();
        __syncthreads();
        const unsigned bufA = sb + (kt & 1) * 16384;
        const unsigned bufB = sbB + kt * 16384;
#pragma unroll
        for (int ks = 0; ks < 4; ++ks) {
            const unsigned ksb = ks * 32;
            unsigned a[4][4], b[4][2];
#pragma unroll
            for (int mt = 0; mt < 4; ++mt)
                LDSM_X4(a[mt][0], a[mt][1], a[mt][2], a[mt][3], bufA + sw128(aoff[mt] + ksb));
            LDSM_X4(b[0][0], b[0][1], b[1][0], b[1][1], bufB + sw128(boff[0] + ksb));
            LDSM_X4(b[2][0], b[2][1], b[3][0], b[3][1], bufB + sw128(boff[1] + ksb));
#pragma unroll
            for (int mt = 0; mt < 4; ++mt)
#pragma unroll
                for (int nt = 0; nt < 4; ++nt)
                    MMA_F16(d[mt][nt], a[mt], b[nt]);
        }
        __syncthreads();
        if (kt < 2) { load_A_chunk(sb + (kt & 1) * 16384, A16, kt + 2, tid); CP_COMMIT(); }
    }

    // ---- post-mainloop: all buffers dead. Stage t-rows @0, cp.async W2 @65536.
    __syncthreads();
    const int yy = s0 >> 7;
    int jy0_, jy1_;
    float wy0, wy1;
    if (yy & 1) { jy0_ = yy >> 1; jy1_ = ((yy >> 1) + 1 > 63) ? 63 : (yy >> 1) + 1; wy0 = 0.75f; wy1 = 0.25f; }
    else        { jy0_ = ((yy >> 1) - 1 < 0) ? 0 : (yy >> 1) - 1; jy1_ = yy >> 1;   wy0 = 0.25f; wy1 = 0.75f; }

    {
        const __half* tb = g_t16 + (size_t)bb * HWLO * 256;
        uint4* tst = (uint4*)dsm;
#pragma unroll
        for (int i = 0; i < 8; ++i) {
            const int idx = i * 256 + tid;
            const int r = idx >> 10, rest = idx & 1023;
            const int j = rest >> 4, cc = rest & 15;
            const int jy = r ? jy1_ : jy0_;
            tst[idx] = *(const uint4*)(tb + (size_t)(jy * 64 + j) * 256 + n0 + cc * 8);
        }
    }
    // W2 half-K B tiles: 2 chunks x 80 rows x 128B
#pragma unroll
    for (int i = 0; i < 5; ++i) {
        const int idx = i * 256 + tid;          // 0..1279
        const int ck = idx >= 640;
        const int rest = idx - ck * 640;
        const int n = rest >> 3, c8 = rest & 7;
        cpa16(sb + 65536 + ck * 10240 + sw128(n * 128 + c8 * 16),
              g_wh + (size_t)(768 + n) * 256 + n0 + ck * 64 + c8 * 8);
    }
    CP_COMMIT();
    __syncthreads();   // t-rows visible; qA region free to write

    // ---- fragment-direct epilogue: relu(acc + b1 + up2x(t)) -> fp16 qA tiles
    const __half* r0p = (const __half*)dsm;
    const __half* r1p = (const __half*)dsm + 8192;
#pragma unroll
    for (int mt = 0; mt < 4; ++mt) {
#pragma unroll
        for (int h = 0; h < 2; ++h) {
            const int r = wm * 64 + mt * 16 + (lane >> 2) + h * 8;   // pixel x
            const int tw = r >> 1;
            int jx0, jx1;
            float wx0, wx1;
            if (r & 1) { jx0 = tw; jx1 = (tw + 1 > 63) ? 63 : tw + 1; wx0 = 0.75f; wx1 = 0.25f; }
            else       { jx0 = (tw - 1 < 0) ? 0 : tw - 1; jx1 = tw;   wx0 = 0.25f; wx1 = 0.75f; }
            const float wa = wy0 * wx0, wb_ = wy0 * wx1, wc = wy1 * wx0, wd = wy1 * wx1;
#pragma unroll
            for (int nt = 0; nt < 4; ++nt) {
                const int col = wn * 32 + nt * 8 + (lane & 3) * 2;
                float2 bv = *(const float2*)&b1[n0 + col];
                float2 f00 = h2f(*(const unsigned*)&r0p[jx0 * 128 + col]);
                float2 f01 = h2f(*(const unsigned*)&r0p[jx1 * 128 + col]);
                float2 f10 = h2f(*(const unsigned*)&r1p[jx0 * 128 + col]);
                float2 f11 = h2f(*(const unsigned*)&r1p[jx1 * 128 + col]);
                float o0 = fmaxf(d[mt][nt][h * 2 + 0] + bv.x +
                                 wa * f00.x + wb_ * f01.x + wc * f10.x + wd * f11.x, 0.f);
                float o1 = fmaxf(d[mt][nt][h * 2 + 1] + bv.y +
                                 wa * f00.y + wb_ * f01.y + wc * f10.y + wd * f11.y, 0.f);
                *(unsigned*)(dsm + 32768 + (col >> 6) * 16384 +
                             sw128((unsigned)r * 128 + (col & 63) * 2)) = pack_h2(o0, o1);
            }
        }
    }
    cp_wait<0>();
    __syncthreads();   // qA tiles + W2 tiles ready

    // ---- in-CTA q-GEMM: q_half[128 x 80] = offtile @ W2halfK, K=128
    const int wm2 = warp >> 1, wn2 = warp & 1;
    unsigned aoff2[2], boffp2[2], boffs2;
#pragma unroll
    for (int mt = 0; mt < 2; ++mt)
        aoff2[mt] = ((unsigned)(wm2 * 32 + mt * 16 + (lane & 15)) << 7) + (lane >> 4) * 16;
#pragma unroll
    for (int p = 0; p < 2; ++p)
        boffp2[p] = ((unsigned)(wn2 * 40 + p * 16 + (lane & 7) + ((lane >> 4) & 1) * 8) << 7)
                    + ((lane >> 3) & 1) * 16;
    boffs2 = ((unsigned)(wn2 * 40 + 32 + (lane & 7)) << 7) + ((lane >> 3) & 1) * 16;

    float dq[2][5][4];
#pragma unroll
    for (int i = 0; i < 2; ++i)
#pragma unroll
        for (int j = 0; j < 5; ++j)
#pragma unroll
            for (int e = 0; e < 4; ++e) dq[i][j][e] = 0.f;

#pragma unroll
    for (int ck = 0; ck < 2; ++ck) {
        const unsigned bufA = sb + 32768 + ck * 16384;
        const unsigned bufB = sb + 65536 + ck * 10240;
#pragma unroll
        for (int ks = 0; ks < 4; ++ks) {
            const unsigned ksb = ks * 32;
            unsigned a[2][4], b[5][2];
#pragma unroll
            for (int mt = 0; mt < 2; ++mt)
                LDSM_X4(a[mt][0], a[mt][1], a[mt][2], a[mt][3], bufA + sw128(aoff2[mt] + ksb));
            LDSM_X4(b[0][0], b[0][1], b[1][0], b[1][1], bufB + sw128(boffp2[0] + ksb));
            LDSM_X4(b[2][0], b[2][1], b[3][0], b[3][1], bufB + sw128(boffp2[1] + ksb));
            LDSM_X2(b[4][0], b[4][1], bufB + sw128(boffs2 + ksb));
#pragma unroll
            for (int mt = 0; mt < 2; ++mt)
#pragma unroll
                for (int nt = 0; nt < 5; ++nt)
                    MMA_F16(dq[mt][nt], a[mt], b[nt]);
        }
    }

    __half* gq = g_q16h[blockIdx.y];
#pragma unroll
    for (int mt = 0; mt < 2; ++mt) {
        const int row = m0 + wm2 * 32 + mt * 16 + (lane >> 2);
#pragma unroll
        for (int nt = 0; nt < 5; ++nt) {
            const int col = wn2 * 40 + nt * 8 + (lane & 3) * 2;
            if (col < 72) {
                *(unsigned*)&gq[(size_t)row * 72 + col] = pack_h2(dq[mt][nt][0], dq[mt][nt][1]);
                *(unsigned*)&gq[(size_t)(row + 8) * 72 + col] = pack_h2(dq[mt][nt][2], dq[mt][nt][3]);
            }
        }
    }
}

// ===========================================================================
// K4: phase A = fused offset stencil (b2 + 9-tap sum of q halves), then
//     4-point deformable bilinear sample of fp16 proc (uint4 taps).
// ===========================================================================
__global__ __launch_bounds__(256)
void k4_sample(const float* __restrict__ b2, float* __restrict__ out)
{
    __shared__ int   sh_idx[32][16];
    __shared__ float sh_w[32][16];
    __shared__ float sh_t[32 * 289 + 8];

    const int tid = threadIdx.x;
    const int xt = blockIdx.x;
    const int y  = blockIdx.y;
    const int bb = blockIdx.z;
    const int x0 = xt * 32;

    if (tid < 128) {
        const int px = tid >> 2, p = tid & 3;
        const int x = x0 + px;
        // fused k6: offsets = b2 + sum over 9 taps of (q_lo + q_hi)
        float ax = b2[2 * p], ay = b2[2 * p + 1];
#pragma unroll
        for (int dy = 0; dy < 3; ++dy) {
            const int yyt = y + dy - 1;
            if (yyt < 0 || yyt > 127) continue;
#pragma unroll
            for (int dx = 0; dx < 3; ++dx) {
                const int xxt = x + dx - 1;
                if (xxt < 0 || xxt > 127) continue;
                const size_t qi = ((size_t)bb * HWHI + yyt * 128 + xxt) * 72
                                  + (dy * 3 + dx) * 8 + 2 * p;
                float2 flo = h2f(*(const unsigned*)&g_q16h[0][qi]);
                float2 fhi = h2f(*(const unsigned*)&g_q16h[1][qi]);
                ax += flo.x + fhi.x;
                ay += flo.y + fhi.y;
            }
        }
        const float ox = ax * (1.0f / 64.0f);
        const float oy = ay * (1.0f / 64.0f);
        const float gx = fmaf((float)x, 2.0f / 127.0f, -1.0f) + ox;
        const float gy = fmaf((float)y, 2.0f / 127.0f, -1.0f) + oy;
        const float gxp = fminf(fmaxf(fmaf(gx, 32.0f, 31.5f), 0.0f), 63.0f);
        const float gyp = fminf(fmaxf(fmaf(gy, 32.0f, 31.5f), 0.0f), 63.0f);
        const float fx0 = floorf(gxp), fy0 = floorf(gyp);
        const int ix0 = (int)fx0, iy0 = (int)fy0;
        const float fx = gxp - fx0, fy = gyp - fy0;
        const int ix1 = (ix0 + 1 > 63) ? 63 : ix0 + 1;
        const int iy1 = (iy0 + 1 > 63) ? 63 : iy0 + 1;
        const int q = p * 4;
        sh_idx[px][q + 0] = (iy0 * 64 + ix0) * 32;
        sh_idx[px][q + 1] = (iy0 * 64 + ix1) * 32;
        sh_idx[px][q + 2] = (iy1 * 64 + ix0) * 32;
        sh_idx[px][q + 3] = (iy1 * 64 + ix1) * 32;
        sh_w[px][q + 0] = (1.f - fx) * (1.f - fy) * 0.25f;
        sh_w[px][q + 1] = fx * (1.f - fy) * 0.25f;
        sh_w[px][q + 2] = (1.f - fx) * fy * 0.25f;
        sh_w[px][q + 3] = fx * fy * 0.25f;
    }
    __syncthreads();

    const int lane = tid & 31, wrp = tid >> 5;
    const uint4* pb = (const uint4*)(g_proc16 + (size_t)bb * HWLO * 256) + lane;

#pragma unroll
    for (int r = 0; r < 4; ++r) {
        const int px = wrp * 4 + r;
        float acc[8];
#pragma unroll
        for (int j = 0; j < 8; ++j) acc[j] = 0.f;
#pragma unroll
        for (int t = 0; t < 16; ++t) {
            const float wt = sh_w[px][t];
            const uint4 u = pb[sh_idx[px][t]];
            float2 f0 = h2f(u.x), f1 = h2f(u.y), f2 = h2f(u.z), f3 = h2f(u.w);
            acc[0] = fmaf(wt, f0.x, acc[0]); acc[1] = fmaf(wt, f0.y, acc[1]);
            acc[2] = fmaf(wt, f1.x, acc[2]); acc[3] = fmaf(wt, f1.y, acc[3]);
            acc[4] = fmaf(wt, f2.x, acc[4]); acc[5] = fmaf(wt, f2.y, acc[5]);
            acc[6] = fmaf(wt, f3.x, acc[6]); acc[7] = fmaf(wt, f3.y, acc[7]);
        }
        float* dstp = &sh_t[px * 289 + lane * 9];
#pragma unroll
        for (int j = 0; j < 8; ++j) dstp[j] = acc[j];
    }
    __syncthreads();

    const int xl = tid & 31;
    const int c0 = tid >> 5;
#pragma unroll
    for (int i = 0; i < 32; ++i) {
        const int c = c0 * 32 + i;
        out[((size_t)bb * 256 + c) * HWHI + y * 128 + x0 + xl] =
            sh_t[xl * 289 + (c >> 3) * 9 + (c & 7)];
    }
}

// ===========================================================================
extern "C" void kernel_launch(void* const* d_in, const int* in_sizes, int n_in,
                              void* d_out, int out_size)
{
    const float* high = (const float*)d_in[0];
    const float* low  = (const float*)d_in[1];
    const float* W1   = (const float*)d_in[2];
    const float* b1   = (const float*)d_in[3];
    const float* W2   = (const float*)d_in[4];
    const float* b2   = (const float*)d_in[5];
    const float* Wf   = (const float*)d_in[6];
    const float* bf   = (const float*)d_in[7];
    float* out = (float*)d_out;

    const int SM_K1 = 98304;
    const int SM_K2 = 98304;

    static cudaStream_t s2;
    static cudaEvent_t e_fork, e_join;
    static int inited = 0;
    if (!inited) {
        cudaFuncSetAttribute(k1f, cudaFuncAttributeMaxDynamicSharedMemorySize, SM_K1);
        cudaFuncSetAttribute(k2f, cudaFuncAttributeMaxDynamicSharedMemorySize, SM_K2);
        cudaStreamCreateWithFlags(&s2, cudaStreamNonBlocking);
        cudaEventCreateWithFlags(&e_fork, cudaEventDisableTiming);
        cudaEventCreateWithFlags(&e_join, cudaEventDisableTiming);
        inited = 1;
    }

    // fork: k0t-low runs on s2, parallel with the k1f chain on s0
    cudaEventRecord(e_fork, 0);
    cudaStreamWaitEvent(s2, e_fork, 0);
    k0t<<<dim3(256, 4, 8), 256, 0, s2>>>(low, 1, HWHI);
    cudaEventRecord(e_join, s2);

    k0t<<<dim3(64, 4, 8), 256>>>(high, 0, HWLO);
    k0w<<<848, 256>>>(W1, Wf, W2);
    k1f<<<dim3(256, 4), 256, SM_K1>>>(bf);

    cudaStreamWaitEvent(0, e_join, 0);
    k2f<<<dim3(1024, 2), 256, SM_K2>>>(b1);
    k4_sample<<<dim3(4, 128, 8), 256>>>(b2, out);
}

// round 15
// speedup vs baseline: 3.4767x; 1.0155x over previous
#include <cuda_runtime.h>
#include <cuda_fp16.h>

// ---------------------------------------------------------------------------
// AdaUp, fp16 mma.sync + cp.async. Fused pipeline:
//   s2: k0w -> k0t-low  ||  s0: k0t-high -> (wait k0w) k1f ; join -> k2f -> k4
//   K2f: GEMM + overlapped t/W2 staging at kt=3 + fragment epilogue + q-GEMM
//   K4 : 256-thread fused offset stencil -> 4-pt deformable sample
// ---------------------------------------------------------------------------

#define NB    8
#define HWLO  4096
#define HWHI  16384

__device__ __half g_h16[(size_t)NB * HWLO * 256];
__device__ __half g_l16[(size_t)NB * HWHI * 256];
__device__ __half g_wh[1024 * 256];
__device__ __half g_t16[(size_t)NB * HWLO * 256];
__device__ __half g_proc16[(size_t)NB * HWLO * 256];
__device__ __half g_q16h[2][(size_t)NB * HWHI * 72];

__device__ __forceinline__ unsigned smem_u32(const void* p) {
    unsigned a;
    asm("{ .reg .u64 t; cvta.to.shared.u64 t, %1; cvt.u32.u64 %0, t; }" : "=r"(a) : "l"(p));
    return a;
}
__device__ __forceinline__ unsigned sw128(unsigned o) { return o ^ ((o >> 3) & 0x70); }
__device__ __forceinline__ unsigned pack_h2(float lo, float hi) {
    unsigned u;
    asm("cvt.rn.f16x2.f32 %0, %1, %2;" : "=r"(u) : "f"(hi), "f"(lo));
    return u;
}
__device__ __forceinline__ void cpa16(unsigned dst, const void* src) {
    asm volatile("cp.async.cg.shared.global [%0], [%1], 16;" :: "r"(dst), "l"(src));
}
#define CP_COMMIT() asm volatile("cp.async.commit_group;" ::: "memory")
template <int N> __device__ __forceinline__ void cp_wait() {
    asm volatile("cp.async.wait_group %0;" :: "n"(N) : "memory");
}

#define LDSM_X4(r0, r1, r2, r3, addr) \
    asm volatile("ldmatrix.sync.aligned.m8n8.x4.shared.b16 {%0,%1,%2,%3}, [%4];" \
                 : "=r"(r0), "=r"(r1), "=r"(r2), "=r"(r3) : "r"(addr))
#define LDSM_X2(r0, r1, addr) \
    asm volatile("ldmatrix.sync.aligned.m8n8.x2.shared.b16 {%0,%1}, [%2];" \
                 : "=r"(r0), "=r"(r1) : "r"(addr))
#define MMA_F16(d, a, b) \
    asm volatile("mma.sync.aligned.m16n8k16.row.col.f32.f16.f16.f32 " \
                 "{%0,%1,%2,%3}, {%4,%5,%6,%7}, {%8,%9}, {%0,%1,%2,%3};" \
                 : "+f"((d)[0]), "+f"((d)[1]), "+f"((d)[2]), "+f"((d)[3]) \
                 : "r"((a)[0]), "r"((a)[1]), "r"((a)[2]), "r"((a)[3]), \
                   "r"((b)[0]), "r"((b)[1]))

__device__ __forceinline__ float2 h2f(unsigned u) {
    return __half22float2(*(const __half2*)&u);
}

// ===========================================================================
// K0t: [b][k][s] f32 -> [b][s][k] fp16
// ===========================================================================
__global__ __launch_bounds__(256)
void k0t(const float* __restrict__ src, int which, int S)
{
    __shared__ float ts[64][65];
    __half* dst = which ? g_l16 : g_h16;
    const int tid = threadIdx.x;
    const int s0 = blockIdx.x * 64, k0 = blockIdx.y * 64, b = blockIdx.z;
    const float* in = src + (size_t)b * 256 * S + (size_t)k0 * S + s0;
#pragma unroll
    for (int i = 0; i < 16; ++i) {
        const int idx = i * 256 + tid;
        const int kk = idx >> 6, ss = idx & 63;
        ts[ss][kk] = in[(size_t)kk * S + ss];
    }
    __syncthreads();
    unsigned* ob = (unsigned*)(dst + ((size_t)b * S + s0) * 256 + k0);
#pragma unroll
    for (int i = 0; i < 8; ++i) {
        const int idx = i * 256 + tid;
        const int ss = idx >> 5, kp = (idx & 31) * 2;
        ob[(size_t)ss * 128 + (kp >> 1)] = pack_h2(ts[ss][kp], ts[ss][kp + 1]);
    }
}

// ===========================================================================
// K0w: pack weights fp16 [row][256]
// ===========================================================================
__global__ __launch_bounds__(256)
void k0w(const float* __restrict__ W1, const float* __restrict__ Wf,
         const float* __restrict__ W2)
{
    const int row = blockIdx.x, c = threadIdx.x;
    float v = 0.f;
    if (row < 256)      v = W1[(size_t)row * 512 + c];
    else if (row < 512) v = Wf[(size_t)(row - 256) * 256 + c];
    else if (row < 768) v = W1[(size_t)(row - 512) * 512 + 256 + c];
    else if (row < 840) {
        const int t = (row - 768) >> 3, o = (row - 768) & 7;
        v = W2[(size_t)o * 2304 + c * 9 + t];
    }
    g_wh[(size_t)row * 256 + c] = __float2half(v);
}

// ===========================================================================
// cp.async one 64-k A chunk (128 rows x 128 bytes)
// ===========================================================================
__device__ __forceinline__ void load_A_chunk(unsigned bufA, const __half* A16,
                                             int kt, int tid)
{
    const int row = tid >> 1, c4 = (tid & 1) * 4;
#pragma unroll
    for (int j = 0; j < 4; ++j) {
        const int c = c4 + j;
        cpa16(bufA + sw128(row * 128 + c * 16), A16 + (size_t)row * 256 + kt * 64 + c * 8);
    }
}

// ===========================================================================
// K1f: [t | proc] = [W1a | Wf] @ high ; grid (256, 4)
// ===========================================================================
__global__ __launch_bounds__(256, 2)
void k1f(const float* __restrict__ bf)
{
    extern __shared__ char dsm[];
    const unsigned sb = smem_u32(dsm), sbB = sb + 32768;
    const int tid = threadIdx.x, lane = tid & 31, warp = tid >> 5;
    const int wm = warp & 1, wn = warp >> 1;
    const int m0 = blockIdx.x * 128;
    const int ny = blockIdx.y >> 1, nhalf = blockIdx.y & 1;
    const int bb = m0 >> 12, s0 = m0 & 4095;
    const int brow0 = ny * 256 + nhalf * 128;

    const __half* A16 = g_h16 + ((size_t)bb * HWLO + s0) * 256;

    unsigned aoff[4], boff[2];
#pragma unroll
    for (int mt = 0; mt < 4; ++mt)
        aoff[mt] = ((unsigned)(wm * 64 + mt * 16 + (lane & 15)) << 7) + (lane >> 4) * 16;
#pragma unroll
    for (int p = 0; p < 2; ++p)
        boff[p] = ((unsigned)(wn * 32 + p * 16 + (lane & 7) + ((lane >> 4) & 1) * 8) << 7)
                  + ((lane >> 3) & 1) * 16;

    float d[4][4][4];
#pragma unroll
    for (int i = 0; i < 4; ++i)
#pragma unroll
        for (int j = 0; j < 4; ++j)
#pragma unroll
            for (int e = 0; e < 4; ++e) d[i][j][e] = 0.f;

#pragma unroll
    for (int i = 0; i < 16; ++i) {
        const int idx = i * 256 + tid;
        const int n = idx >> 5, c = idx & 31;
        cpa16(sbB + (c >> 3) * 16384 + sw128(n * 128 + (c & 7) * 16),
              g_wh + (size_t)(brow0 + n) * 256 + c * 8);
    }
    load_A_chunk(sb, A16, 0, tid);
    CP_COMMIT();
    load_A_chunk(sb + 16384, A16, 1, tid);
    CP_COMMIT();

    for (int kt = 0; kt < 4; ++kt) {
        if (kt < 3) cp_wait<1>(); else cp_wait<0>();
        __syncthreads();
        const unsigned bufA = sb + (kt & 1) * 16384;
        const unsigned bufB = sbB + kt * 16384;
#pragma unroll
        for (int ks = 0; ks < 4; ++ks) {
            const unsigned ksb = ks * 32;
            unsigned a[4][4], b[4][2];
#pragma unroll
            for (int mt = 0; mt < 4; ++mt)
                LDSM_X4(a[mt][0], a[mt][1], a[mt][2], a[mt][3], bufA + sw128(aoff[mt] + ksb));
            LDSM_X4(b[0][0], b[0][1], b[1][0], b[1][1], bufB + sw128(boff[0] + ksb));
            LDSM_X4(b[2][0], b[2][1], b[3][0], b[3][1], bufB + sw128(boff[1] + ksb));
#pragma unroll
            for (int mt = 0; mt < 4; ++mt)
#pragma unroll
                for (int nt = 0; nt < 4; ++nt)
                    MMA_F16(d[mt][nt], a[mt], b[nt]);
        }
        __syncthreads();
        if (kt < 2) { load_A_chunk(sb + (kt & 1) * 16384, A16, kt + 2, tid); CP_COMMIT(); }
    }

#pragma unroll
    for (int mt = 0; mt < 4; ++mt) {
        const int row = m0 + wm * 64 + mt * 16 + (lane >> 2);
#pragma unroll
        for (int nt = 0; nt < 4; ++nt) {
            const int col = nhalf * 128 + wn * 32 + nt * 8 + (lane & 3) * 2;
            if (ny == 0) {
                *(unsigned*)&g_t16[(size_t)row * 256 + col] =
                    pack_h2(d[mt][nt][0], d[mt][nt][1]);
                *(unsigned*)&g_t16[(size_t)(row + 8) * 256 + col] =
                    pack_h2(d[mt][nt][2], d[mt][nt][3]);
            } else {
                const float b0 = bf[col], b1 = bf[col + 1];
                *(unsigned*)&g_proc16[(size_t)row * 256 + col] =
                    pack_h2(d[mt][nt][0] + b0, d[mt][nt][1] + b1);
                *(unsigned*)&g_proc16[(size_t)(row + 8) * 256 + col] =
                    pack_h2(d[mt][nt][2] + b0, d[mt][nt][3] + b1);
            }
        }
    }
}

// ===========================================================================
// K2f: GEMM W1b@low -> fragment-direct epilogue -> in-CTA q-GEMM.
// smem (98304, 2 CTA/SM):
//   mainloop: A0 @0, A1 @16384, B chunks @32768+kt*16384
//   at kt=3 (A0, B0-2 dead): t-row jy0 @0, jy1 @49152, W2ck0 @65536 (cp.async)
//   post: W2ck1 @81920 ; epilogue writes qA tile0 @32768, tile1 @16384
// ===========================================================================
__global__ __launch_bounds__(256, 2)
void k2f(const float* __restrict__ b1)
{
    extern __shared__ char dsm[];
    const unsigned sb = smem_u32(dsm), sbB = sb + 32768;
    const int tid = threadIdx.x, lane = tid & 31, warp = tid >> 5;
    const int wm = warp & 1, wn = warp >> 1;
    const int m0 = blockIdx.x * 128;
    const int n0 = blockIdx.y * 128;
    const int bb = m0 >> 14, s0 = m0 & 16383;
    const int brow0 = 512 + n0;

    const __half* A16 = g_l16 + ((size_t)bb * HWHI + s0) * 256;

    // upsample y-taps (depend only on s0)
    const int yy = s0 >> 7;
    int jy0_, jy1_;
    float wy0, wy1;
    if (yy & 1) { jy0_ = yy >> 1; jy1_ = ((yy >> 1) + 1 > 63) ? 63 : (yy >> 1) + 1; wy0 = 0.75f; wy1 = 0.25f; }
    else        { jy0_ = ((yy >> 1) - 1 < 0) ? 0 : (yy >> 1) - 1; jy1_ = yy >> 1;   wy0 = 0.25f; wy1 = 0.75f; }

    unsigned aoff[4], boff[2];
#pragma unroll
    for (int mt = 0; mt < 4; ++mt)
        aoff[mt] = ((unsigned)(wm * 64 + mt * 16 + (lane & 15)) << 7) + (lane >> 4) * 16;
#pragma unroll
    for (int p = 0; p < 2; ++p)
        boff[p] = ((unsigned)(wn * 32 + p * 16 + (lane & 7) + ((lane >> 4) & 1) * 8) << 7)
                  + ((lane >> 3) & 1) * 16;

    float d[4][4][4];
#pragma unroll
    for (int i = 0; i < 4; ++i)
#pragma unroll
        for (int j = 0; j < 4; ++j)
#pragma unroll
            for (int e = 0; e < 4; ++e) d[i][j][e] = 0.f;

#pragma unroll
    for (int i = 0; i < 16; ++i) {
        const int idx = i * 256 + tid;
        const int n = idx >> 5, c = idx & 31;
        cpa16(sbB + (c >> 3) * 16384 + sw128(n * 128 + (c & 7) * 16),
              g_wh + (size_t)(brow0 + n) * 256 + c * 8);
    }
    load_A_chunk(sb, A16, 0, tid);
    CP_COMMIT();
    load_A_chunk(sb + 16384, A16, 1, tid);
    CP_COMMIT();

    for (int kt = 0; kt < 4; ++kt) {
        if (kt < 3) cp_wait<1>(); else cp_wait<0>();
        __syncthreads();
        if (kt == 3) {
            // prefetch t-rows + W2ck0 into dead buffers, overlapped with compute
            const __half* tb = g_t16 + (size_t)bb * HWLO * 256;
#pragma unroll
            for (int r = 0; r < 2; ++r) {
                const int jy = r ? jy1_ : jy0_;
                const unsigned dstb = r ? 49152u : 0u;
#pragma unroll
                for (int i = 0; i < 4; ++i) {
                    const int idx = i * 256 + tid;     // 0..1023 uint4
                    const int j = idx >> 4, cc = idx & 15;
                    cpa16(sb + dstb + idx * 16,
                          tb + (size_t)(jy * 64 + j) * 256 + n0 + cc * 8);
                }
            }
#pragma unroll
            for (int i = 0; i < 3; ++i) {
                const int idx = i * 256 + tid;
                if (idx < 640) {
                    const int n = idx >> 3, c8 = idx & 7;
                    cpa16(sb + 65536 + sw128(n * 128 + c8 * 16),
                          g_wh + (size_t)(768 + n) * 256 + n0 + c8 * 8);
                }
            }
            CP_COMMIT();
        }
        const unsigned bufA = sb + (kt & 1) * 16384;
        const unsigned bufB = sbB + kt * 16384;
#pragma unroll
        for (int ks = 0; ks < 4; ++ks) {
            const unsigned ksb = ks * 32;
            unsigned a[4][4], b[4][2];
#pragma unroll
            for (int mt = 0; mt < 4; ++mt)
                LDSM_X4(a[mt][0], a[mt][1], a[mt][2], a[mt][3], bufA + sw128(aoff[mt] + ksb));
            LDSM_X4(b[0][0], b[0][1], b[1][0], b[1][1], bufB + sw128(boff[0] + ksb));
            LDSM_X4(b[2][0], b[2][1], b[3][0], b[3][1], bufB + sw128(boff[1] + ksb));
#pragma unroll
            for (int mt = 0; mt < 4; ++mt)
#pragma unroll
                for (int nt = 0; nt < 4; ++nt)
                    MMA_F16(d[mt][nt], a[mt], b[nt]);
        }
        __syncthreads();
        if (kt < 2) { load_A_chunk(sb + (kt & 1) * 16384, A16, kt + 2, tid); CP_COMMIT(); }
    }

    // issue W2ck1 into B chunk 3 (now dead), overlapped with epilogue
#pragma unroll
    for (int i = 0; i < 3; ++i) {
        const int idx = i * 256 + tid;
        if (idx < 640) {
            const int n = idx >> 3, c8 = idx & 7;
            cpa16(sb + 81920 + sw128(n * 128 + c8 * 16),
                  g_wh + (size_t)(768 + n) * 256 + n0 + 64 + c8 * 8);
        }
    }
    CP_COMMIT();
    cp_wait<1>();      // t-rows + W2ck0 arrived; W2ck1 may still fly
    __syncthreads();

    // ---- fragment-direct epilogue -> fp16 qA tiles (@32768 col<64, @16384 col>=64)
    const __half* r0p = (const __half*)dsm;
    const __half* r1p = (const __half*)(dsm + 49152);
#pragma unroll
    for (int mt = 0; mt < 4; ++mt) {
#pragma unroll
        for (int h = 0; h < 2; ++h) {
            const int r = wm * 64 + mt * 16 + (lane >> 2) + h * 8;   // pixel x
            const int tw = r >> 1;
            int jx0, jx1;
            float wx0, wx1;
            if (r & 1) { jx0 = tw; jx1 = (tw + 1 > 63) ? 63 : tw + 1; wx0 = 0.75f; wx1 = 0.25f; }
            else       { jx0 = (tw - 1 < 0) ? 0 : tw - 1; jx1 = tw;   wx0 = 0.25f; wx1 = 0.75f; }
            const float wa = wy0 * wx0, wb_ = wy0 * wx1, wc = wy1 * wx0, wd = wy1 * wx1;
#pragma unroll
            for (int nt = 0; nt < 4; ++nt) {
                const int col = wn * 32 + nt * 8 + (lane & 3) * 2;
                float2 bv = *(const float2*)&b1[n0 + col];
                float2 f00 = h2f(*(const unsigned*)&r0p[jx0 * 128 + col]);
                float2 f01 = h2f(*(const unsigned*)&r0p[jx1 * 128 + col]);
                float2 f10 = h2f(*(const unsigned*)&r1p[jx0 * 128 + col]);
                float2 f11 = h2f(*(const unsigned*)&r1p[jx1 * 128 + col]);
                float o0 = fmaxf(d[mt][nt][h * 2 + 0] + bv.x +
                                 wa * f00.x + wb_ * f01.x + wc * f10.x + wd * f11.x, 0.f);
                float o1 = fmaxf(d[mt][nt][h * 2 + 1] + bv.y +
                                 wa * f00.y + wb_ * f01.y + wc * f10.y + wd * f11.y, 0.f);
                *(unsigned*)(dsm + (col < 64 ? 32768u : 16384u) +
                             sw128((unsigned)r * 128 + (col & 63) * 2)) = pack_h2(o0, o1);
            }
        }
    }
    cp_wait<0>();
    __syncthreads();   // qA tiles + both W2 tiles ready

    // ---- in-CTA q-GEMM: q_half[128 x 80] = offtile @ W2halfK, K=128
    const int wm2 = warp >> 1, wn2 = warp & 1;
    unsigned aoff2[2], boffp2[2], boffs2;
#pragma unroll
    for (int mt = 0; mt < 2; ++mt)
        aoff2[mt] = ((unsigned)(wm2 * 32 + mt * 16 + (lane & 15)) << 7) + (lane >> 4) * 16;
#pragma unroll
    for (int p = 0; p < 2; ++p)
        boffp2[p] = ((unsigned)(wn2 * 40 + p * 16 + (lane & 7) + ((lane >> 4) & 1) * 8) << 7)
                    + ((lane >> 3) & 1) * 16;
    boffs2 = ((unsigned)(wn2 * 40 + 32 + (lane & 7)) << 7) + ((lane >> 3) & 1) * 16;

    float dq[2][5][4];
#pragma unroll
    for (int i = 0; i < 2; ++i)
#pragma unroll
        for (int j = 0; j < 5; ++j)
#pragma unroll
            for (int e = 0; e < 4; ++e) dq[i][j][e] = 0.f;

    const unsigned qa_base[2] = {32768u, 16384u};
    const unsigned qb_base[2] = {65536u, 81920u};
#pragma unroll
    for (int ck = 0; ck < 2; ++ck) {
        const unsigned bufA = sb + qa_base[ck];
        const unsigned bufB = sb + qb_base[ck];
#pragma unroll
        for (int ks = 0; ks < 4; ++ks) {
            const unsigned ksb = ks * 32;
            unsigned a[2][4], b[5][2];
#pragma unroll
            for (int mt = 0; mt < 2; ++mt)
                LDSM_X4(a[mt][0], a[mt][1], a[mt][2], a[mt][3], bufA + sw128(aoff2[mt] + ksb));
            LDSM_X4(b[0][0], b[0][1], b[1][0], b[1][1], bufB + sw128(boffp2[0] + ksb));
            LDSM_X4(b[2][0], b[2][1], b[3][0], b[3][1], bufB + sw128(boffp2[1] + ksb));
            LDSM_X2(b[4][0], b[4][1], bufB + sw128(boffs2 + ksb));
#pragma unroll
            for (int mt = 0; mt < 2; ++mt)
#pragma unroll
                for (int nt = 0; nt < 5; ++nt)
                    MMA_F16(dq[mt][nt], a[mt], b[nt]);
        }
    }

    __half* gq = g_q16h[blockIdx.y];
#pragma unroll
    for (int mt = 0; mt < 2; ++mt) {
        const int row = m0 + wm2 * 32 + mt * 16 + (lane >> 2);
#pragma unroll
        for (int nt = 0; nt < 5; ++nt) {
            const int col = wn2 * 40 + nt * 8 + (lane & 3) * 2;
            if (col < 72) {
                *(unsigned*)&gq[(size_t)row * 72 + col] = pack_h2(dq[mt][nt][0], dq[mt][nt][1]);
                *(unsigned*)&gq[(size_t)(row + 8) * 72 + col] = pack_h2(dq[mt][nt][2], dq[mt][nt][3]);
            }
        }
    }
}

// ===========================================================================
// K4: phase A = fused offset stencil on all 256 threads (one q-half each),
//     combine via smem, then 4-pt deformable bilinear sample (uint4 taps).
// ===========================================================================
__global__ __launch_bounds__(256)
void k4_sample(const float* __restrict__ b2, float* __restrict__ out)
{
    __shared__ int   sh_idx[32][16];
    __shared__ float sh_w[32][16];
    __shared__ float sh_part[256][2];
    __shared__ float sh_t[32 * 289 + 8];

    const int tid = threadIdx.x;
    const int xt = blockIdx.x;
    const int y  = blockIdx.y;
    const int bb = blockIdx.z;
    const int x0 = xt * 32;

    // phase A1: each thread sums 9 taps of one q-half for one (pixel, point)
    {
        const int hf = tid >> 7, r = tid & 127;
        const int px = r >> 2, p = r & 3;
        const int x = x0 + px;
        float ax = 0.f, ay = 0.f;
        const __half* qb = g_q16h[hf] + (size_t)bb * HWHI * 72;
#pragma unroll
        for (int dy = 0; dy < 3; ++dy) {
            const int yyt = y + dy - 1;
            if (yyt < 0 || yyt > 127) continue;
#pragma unroll
            for (int dx = 0; dx < 3; ++dx) {
                const int xxt = x + dx - 1;
                if (xxt < 0 || xxt > 127) continue;
                float2 f = h2f(*(const unsigned*)&qb[(size_t)(yyt * 128 + xxt) * 72
                                                     + (dy * 3 + dx) * 8 + 2 * p]);
                ax += f.x;
                ay += f.y;
            }
        }
        sh_part[tid][0] = ax;
        sh_part[tid][1] = ay;
    }
    __syncthreads();

    if (tid < 128) {
        const int px = tid >> 2, p = tid & 3;
        const int x = x0 + px;
        const float ax = sh_part[tid][0] + sh_part[tid + 128][0] + b2[2 * p];
        const float ay = sh_part[tid][1] + sh_part[tid + 128][1] + b2[2 * p + 1];
        const float ox = ax * (1.0f / 64.0f);
        const float oy = ay * (1.0f / 64.0f);
        const float gx = fmaf((float)x, 2.0f / 127.0f, -1.0f) + ox;
        const float gy = fmaf((float)y, 2.0f / 127.0f, -1.0f) + oy;
        const float gxp = fminf(fmaxf(fmaf(gx, 32.0f, 31.5f), 0.0f), 63.0f);
        const float gyp = fminf(fmaxf(fmaf(gy, 32.0f, 31.5f), 0.0f), 63.0f);
        const float fx0 = floorf(gxp), fy0 = floorf(gyp);
        const int ix0 = (int)fx0, iy0 = (int)fy0;
        const float fx = gxp - fx0, fy = gyp - fy0;
        const int ix1 = (ix0 + 1 > 63) ? 63 : ix0 + 1;
        const int iy1 = (iy0 + 1 > 63) ? 63 : iy0 + 1;
        const int q = p * 4;
        sh_idx[px][q + 0] = (iy0 * 64 + ix0) * 32;
        sh_idx[px][q + 1] = (iy0 * 64 + ix1) * 32;
        sh_idx[px][q + 2] = (iy1 * 64 + ix0) * 32;
        sh_idx[px][q + 3] = (iy1 * 64 + ix1) * 32;
        sh_w[px][q + 0] = (1.f - fx) * (1.f - fy) * 0.25f;
        sh_w[px][q + 1] = fx * (1.f - fy) * 0.25f;
        sh_w[px][q + 2] = (1.f - fx) * fy * 0.25f;
        sh_w[px][q + 3] = fx * fy * 0.25f;
    }
    __syncthreads();

    const int lane = tid & 31, wrp = tid >> 5;
    const uint4* pb = (const uint4*)(g_proc16 + (size_t)bb * HWLO * 256) + lane;

#pragma unroll
    for (int r = 0; r < 4; ++r) {
        const int px = wrp * 4 + r;
        float acc[8];
#pragma unroll
        for (int j = 0; j < 8; ++j) acc[j] = 0.f;
#pragma unroll
        for (int t = 0; t < 16; ++t) {
            const float wt = sh_w[px][t];
            const uint4 u = pb[sh_idx[px][t]];
            float2 f0 = h2f(u.x), f1 = h2f(u.y), f2 = h2f(u.z), f3 = h2f(u.w);
            acc[0] = fmaf(wt, f0.x, acc[0]); acc[1] = fmaf(wt, f0.y, acc[1]);
            acc[2] = fmaf(wt, f1.x, acc[2]); acc[3] = fmaf(wt, f1.y, acc[3]);
            acc[4] = fmaf(wt, f2.x, acc[4]); acc[5] = fmaf(wt, f2.y, acc[5]);
            acc[6] = fmaf(wt, f3.x, acc[6]); acc[7] = fmaf(wt, f3.y, acc[7]);
        }
        float* dstp = &sh_t[px * 289 + lane * 9];
#pragma unroll
        for (int j = 0; j < 8; ++j) dstp[j] = acc[j];
    }
    __syncthreads();

    const int xl = tid & 31;
    const int c0 = tid >> 5;
#pragma unroll
    for (int i = 0; i < 32; ++i) {
        const int c = c0 * 32 + i;
        out[((size_t)bb * 256 + c) * HWHI + y * 128 + x0 + xl] =
            sh_t[xl * 289 + (c >> 3) * 9 + (c & 7)];
    }
}

// ===========================================================================
extern "C" void kernel_launch(void* const* d_in, const int* in_sizes, int n_in,
                              void* d_out, int out_size)
{
    const float* high = (const float*)d_in[0];
    const float* low  = (const float*)d_in[1];
    const float* W1   = (const float*)d_in[2];
    const float* b1   = (const float*)d_in[3];
    const float* W2   = (const float*)d_in[4];
    const float* b2   = (const float*)d_in[5];
    const float* Wf   = (const float*)d_in[6];
    const float* bf   = (const float*)d_in[7];
    float* out = (float*)d_out;

    const int SM_K1 = 98304;
    const int SM_K2 = 98304;

    static cudaStream_t s2;
    static cudaEvent_t e_fork, e_w, e_join;
    static int inited = 0;
    if (!inited) {
        cudaFuncSetAttribute(k1f, cudaFuncAttributeMaxDynamicSharedMemorySize, SM_K1);
        cudaFuncSetAttribute(k2f, cudaFuncAttributeMaxDynamicSharedMemorySize, SM_K2);
        cudaStreamCreateWithFlags(&s2, cudaStreamNonBlocking);
        cudaEventCreateWithFlags(&e_fork, cudaEventDisableTiming);
        cudaEventCreateWithFlags(&e_w, cudaEventDisableTiming);
        cudaEventCreateWithFlags(&e_join, cudaEventDisableTiming);
        inited = 1;
    }

    // fork: k0w + k0t-low on s2, parallel with k0t-high + k1f on s0
    cudaEventRecord(e_fork, 0);
    cudaStreamWaitEvent(s2, e_fork, 0);
    k0w<<<848, 256, 0, s2>>>(W1, Wf, W2);
    cudaEventRecord(e_w, s2);
    k0t<<<dim3(256, 4, 8), 256, 0, s2>>>(low, 1, HWHI);
    cudaEventRecord(e_join, s2);

    k0t<<<dim3(64, 4, 8), 256>>>(high, 0, HWLO);
    cudaStreamWaitEvent(0, e_w, 0);
    k1f<<<dim3(256, 4), 256, SM_K1>>>(bf);

    cudaStreamWaitEvent(0, e_join, 0);
    k2f<<<dim3(1024, 2), 256, SM_K2>>>(b1);
    k4_sample<<<dim3(4, 128, 8), 256>>>(b2, out);
}